// round 9
// baseline (speedup 1.0000x reference)
#include <cuda_runtime.h>
#include <cuda_bf16.h>
#include <math.h>

#define BATCH 2
#define SEQ   4096
#define DM    512
#define ROWS  (BATCH*SEQ)   // 8192

typedef unsigned short u16;
typedef unsigned int   u32;

// ---------------------------------------------------------------------------
// Device scratch (allocation-free rule: __device__ globals)
// ---------------------------------------------------------------------------
__device__ u16 g_Qh[(size_t)ROWS*DM], g_Ql[(size_t)ROWS*DM];
__device__ u16 g_Kh[(size_t)ROWS*DM], g_Kl[(size_t)ROWS*DM];
__device__ u16 g_Vh[(size_t)ROWS*DM], g_Vl[(size_t)ROWS*DM];
__device__ u16 g_Wqh[DM*DM], g_Wql[DM*DM];
__device__ u16 g_Wkh[DM*DM], g_Wkl[DM*DM];
__device__ u16 g_Wvh[DM*DM], g_Wvl[DM*DM];
__device__ u16 g_qh[(size_t)ROWS*DM], g_ql[(size_t)ROWS*DM];
__device__ u16 g_kh[(size_t)ROWS*DM], g_kl[(size_t)ROWS*DM];
__device__ u16 g_vth[(size_t)BATCH*DM*SEQ], g_vtl[(size_t)BATCH*DM*SEQ];
__device__ float g_s[(size_t)BATCH*SEQ*SEQ];
__device__ u16 g_ah[(size_t)BATCH*SEQ*SEQ], g_al[(size_t)BATCH*SEQ*SEQ];

// ---------------------------------------------------------------------------
// bf16 helpers
// ---------------------------------------------------------------------------
__device__ __forceinline__ u16 f2bf(float x) {
    __nv_bfloat16 h = __float2bfloat16(x);
    return *reinterpret_cast<u16*>(&h);
}
__device__ __forceinline__ float bf2f(u16 u) {
    __nv_bfloat16 h = *reinterpret_cast<__nv_bfloat16*>(&u);
    return __bfloat162float(h);
}
__device__ __forceinline__ void split_bf16(float x, u16& hi, u16& lo) {
    hi = f2bf(x);
    lo = f2bf(x - bf2f(hi));
}
__device__ __forceinline__ unsigned pack2(u16 a, u16 b) {
    return (unsigned)a | ((unsigned)b << 16);
}

__device__ __forceinline__ void mma16816(float c[4],
                                         u32 a0, u32 a1, u32 a2, u32 a3,
                                         u32 b0, u32 b1)
{
    asm volatile(
        "mma.sync.aligned.m16n8k16.row.col.f32.bf16.bf16.f32 "
        "{%0,%1,%2,%3}, {%4,%5,%6,%7}, {%8,%9}, {%0,%1,%2,%3};\n"
        : "+f"(c[0]), "+f"(c[1]), "+f"(c[2]), "+f"(c[3])
        : "r"(a0), "r"(a1), "r"(a2), "r"(a3), "r"(b0), "r"(b1));
}

__device__ __forceinline__ void cp16(void* smem_dst, const void* gsrc) {
    u32 u = (u32)__cvta_generic_to_shared(smem_dst);
    asm volatile("cp.async.cg.shared.global [%0], [%1], 16;\n" :: "r"(u), "l"(gsrc));
}

__device__ __forceinline__ void ldsm4(u32& r0, u32& r1, u32& r2, u32& r3, u32 addr) {
    asm volatile("ldmatrix.sync.aligned.m8n8.x4.shared.b16 {%0,%1,%2,%3}, [%4];"
                 : "=r"(r0), "=r"(r1), "=r"(r2), "=r"(r3) : "r"(addr));
}

// ---------------------------------------------------------------------------
// Fused fp32 -> split bf16 for 3 equal-size arrays
// ---------------------------------------------------------------------------
__global__ __launch_bounds__(256)
void split3_kernel(const float* __restrict__ x0, const float* __restrict__ x1,
                   const float* __restrict__ x2,
                   u16* __restrict__ h0a, u16* __restrict__ l0a,
                   u16* __restrict__ h1a, u16* __restrict__ l1a,
                   u16* __restrict__ h2a, u16* __restrict__ l2a, int n)
{
    const float* x;
    u16 *hp, *lp;
    if (blockIdx.y == 0)      { x = x0; hp = h0a; lp = l0a; }
    else if (blockIdx.y == 1) { x = x1; hp = h1a; lp = l1a; }
    else                      { x = x2; hp = h2a; lp = l2a; }

    int i = (blockIdx.x * blockDim.x + threadIdx.x) * 4;
    if (i >= n) return;
    float4 f = *reinterpret_cast<const float4*>(x + i);
    u16 h0,l0,h1,l1,h2,l2,h3,l3;
    split_bf16(f.x, h0, l0);
    split_bf16(f.y, h1, l1);
    split_bf16(f.z, h2, l2);
    split_bf16(f.w, h3, l3);
    *reinterpret_cast<uint2*>(hp + i) = make_uint2(pack2(h0,h1), pack2(h2,h3));
    *reinterpret_cast<uint2*>(lp + i) = make_uint2(pack2(l0,l1), pack2(l2,l3));
}

// ---------------------------------------------------------------------------
// Shared GEMM constants
// ---------------------------------------------------------------------------
#define SMP   40                   // padded row stride (bf16): 80B, LDSM-conflict-free
#define ROWB  (SMP*2)              // 80 bytes

// ===== BN=128 variant (scores) =====
#define ARR_BYTES   (128*ROWB)     // 10240
#define STAGE_BYTES (4*ARR_BYTES)  // 40960
#define NSTAGE 2
#define DYNSMEM (NSTAGE*STAGE_BYTES)   // 81920 -> 2 CTAs/SM

__device__ __forceinline__ void issue_stage128(char* base,
    const u16* __restrict__ Agh, const u16* __restrict__ Agl,
    const u16* __restrict__ Bgh, const u16* __restrict__ Bgl,
    int row0, int col0, int K, int k0, int tid)
{
#pragma unroll
    for (int e = 0; e < 2; e++) {
        int idx = tid + (e << 8);
        int r = idx >> 2;
        int c = (idx & 3) << 3;
        size_t offA = (size_t)(row0 + r) * K + k0 + c;
        size_t offB = (size_t)(col0 + r) * K + k0 + c;
        int sm = r * ROWB + c * 2;
        cp16(base + sm,                 Agh + offA);
        cp16(base + ARR_BYTES   + sm,   Agl + offA);
        cp16(base + 2*ARR_BYTES + sm,   Bgh + offB);
        cp16(base + 3*ARR_BYTES + sm,   Bgl + offB);
    }
}

// Scores GEMM: C = alpha * A @ B^T, fp32 out, per-batch
__global__ __launch_bounds__(256, 2)
void gemm_scores(const u16* __restrict__ Agh, const u16* __restrict__ Agl,
                 const u16* __restrict__ Bgh, const u16* __restrict__ Bgl,
                 float* __restrict__ Cf,
                 int M, int N, int K,
                 long sA, long sB, long sC, float alpha)
{
    extern __shared__ char smem[];

    const int bz = blockIdx.z;
    Agh += (size_t)bz * sA;  Agl += (size_t)bz * sA;
    Bgh += (size_t)bz * sB;  Bgl += (size_t)bz * sB;

    const int tid  = threadIdx.x;
    const int lane = tid & 31;
    const int wid  = tid >> 5;
    const int g    = lane >> 2;
    const int tg   = lane & 3;
    const int wm0  = (wid & 3) * 32;
    const int wn0  = (wid >> 2) * 64;
    const int row0 = blockIdx.y * 128;
    const int col0 = blockIdx.x * 128;

    const u32 aLane = (u32)((wm0 + (lane & 15)) * ROWB + ((lane >> 4) << 4));
    const u32 bLane = (u32)((wn0 + ((lane >> 4) << 3) + (lane & 7)) * ROWB
                            + ((lane & 8) << 1));
    const u32 smem_base = (u32)__cvta_generic_to_shared(smem);

    float acc[2][8][4];
#pragma unroll
    for (int i = 0; i < 2; i++)
#pragma unroll
        for (int j = 0; j < 8; j++)
#pragma unroll
            for (int t = 0; t < 4; t++) acc[i][j][t] = 0.0f;

    const int NIT = K >> 5;

#pragma unroll
    for (int s = 0; s < NSTAGE; s++) {
        issue_stage128(smem + s * STAGE_BYTES, Agh, Agl, Bgh, Bgl,
                       row0, col0, K, s << 5, tid);
        asm volatile("cp.async.commit_group;\n" ::: "memory");
    }

    for (int it = 0; it < NIT; it++) {
        asm volatile("cp.async.wait_group 1;\n" ::: "memory");
        __syncthreads();

        const u32 stg = smem_base + (u32)((it & 1) * STAGE_BYTES);

#pragma unroll
        for (int ks = 0; ks < 2; ks++) {
            const u32 ko = ks << 5;
            u32 ah[2][4], al[2][4];
#pragma unroll
            for (int i = 0; i < 2; i++) {
                u32 aoff = stg + aLane + (u32)(i * 16 * ROWB) + ko;
                ldsm4(ah[i][0], ah[i][1], ah[i][2], ah[i][3], aoff);
                ldsm4(al[i][0], al[i][1], al[i][2], al[i][3], aoff + ARR_BYTES);
            }
#pragma unroll
            for (int half = 0; half < 2; half++) {
                u32 bh[4][2], bl[4][2];
#pragma unroll
                for (int p = 0; p < 2; p++) {
                    u32 boff = stg + 2*ARR_BYTES + bLane
                             + (u32)((half * 2 + p) * 16 * ROWB) + ko;
                    ldsm4(bh[2*p][0], bh[2*p][1], bh[2*p+1][0], bh[2*p+1][1], boff);
                    ldsm4(bl[2*p][0], bl[2*p][1], bl[2*p+1][0], bl[2*p+1][1],
                          boff + ARR_BYTES);
                }
#pragma unroll
                for (int i = 0; i < 2; i++)
#pragma unroll
                    for (int j = 0; j < 4; j++)
                        mma16816(acc[i][half*4 + j],
                                 ah[i][0], ah[i][1], ah[i][2], ah[i][3],
                                 bh[j][0], bh[j][1]);
#pragma unroll
                for (int i = 0; i < 2; i++)
#pragma unroll
                    for (int j = 0; j < 4; j++)
                        mma16816(acc[i][half*4 + j],
                                 ah[i][0], ah[i][1], ah[i][2], ah[i][3],
                                 bl[j][0], bl[j][1]);
#pragma unroll
                for (int i = 0; i < 2; i++)
#pragma unroll
                    for (int j = 0; j < 4; j++)
                        mma16816(acc[i][half*4 + j],
                                 al[i][0], al[i][1], al[i][2], al[i][3],
                                 bh[j][0], bh[j][1]);
            }
        }
        __syncthreads();

        if (it + NSTAGE < NIT)
            issue_stage128(smem + (it & 1) * STAGE_BYTES, Agh, Agl, Bgh, Bgl,
                           row0, col0, K, (it + NSTAGE) << 5, tid);
        asm volatile("cp.async.commit_group;\n" ::: "memory");
    }

#pragma unroll
    for (int i = 0; i < 2; i++) {
        int r1 = row0 + wm0 + 16 * i + g;
        int r2 = r1 + 8;
#pragma unroll
        for (int j = 0; j < 8; j++) {
            int n = col0 + wn0 + 8 * j + 2 * tg;
            float* Cb = Cf + (size_t)bz * sC;
            *reinterpret_cast<float2*>(Cb + (size_t)r1 * N + n) =
                make_float2(acc[i][j][0] * alpha, acc[i][j][1] * alpha);
            *reinterpret_cast<float2*>(Cb + (size_t)r2 * N + n) =
                make_float2(acc[i][j][2] * alpha, acc[i][j][3] * alpha);
        }
    }
}

// ===== BN=64 variant =====
#define AA_BYTES    (128*ROWB)                 // 10240 (A arrays)
#define BB_BYTES    (64*ROWB)                  // 5120  (B arrays)
#define STAGE64     (2*AA_BYTES + 2*BB_BYTES)  // 30720
#define DYNSMEM64   (2*STAGE64)                // 61440 -> 2 CTAs/SM

__device__ __forceinline__ void issue_stage64(char* base,
    const u16* __restrict__ Agh, const u16* __restrict__ Agl,
    const u16* __restrict__ Bgh, const u16* __restrict__ Bgl,
    int row0, int col0, int K, int k0, int tid)
{
#pragma unroll
    for (int e = 0; e < 2; e++) {
        int idx = tid + (e << 8);
        int r = idx >> 2;
        int c = (idx & 3) << 3;
        size_t offA = (size_t)(row0 + r) * K + k0 + c;
        int sm = r * ROWB + c * 2;
        cp16(base + sm,            Agh + offA);
        cp16(base + AA_BYTES + sm, Agl + offA);
    }
    {
        int r = tid >> 2;                 // 0..63
        int c = (tid & 3) << 3;
        size_t offB = (size_t)(col0 + r) * K + k0 + c;
        int sm = r * ROWB + c * 2;
        cp16(base + 2*AA_BYTES + sm,            Bgh + offB);
        cp16(base + 2*AA_BYTES + BB_BYTES + sm, Bgl + offB);
    }
}

// Core BN=64 mainloop: leaves results in acc[2][4][4]
__device__ __forceinline__ void gemm64_main(char* smem, float acc[2][4][4],
    const u16* Agh, const u16* Agl, const u16* Bgh, const u16* Bgl,
    int row0, int col0, int K, int tid)
{
    const int lane = tid & 31;
    const int wid  = tid >> 5;
    const int wm0  = (wid & 3) * 32;
    const int wn0  = (wid >> 2) * 32;

    const u32 aLane = (u32)((wm0 + (lane & 15)) * ROWB + ((lane >> 4) << 4));
    const u32 bLane = (u32)((wn0 + ((lane >> 4) << 3) + (lane & 7)) * ROWB
                            + ((lane & 8) << 1));
    const u32 smem_base = (u32)__cvta_generic_to_shared(smem);

#pragma unroll
    for (int i = 0; i < 2; i++)
#pragma unroll
        for (int j = 0; j < 4; j++)
#pragma unroll
            for (int t = 0; t < 4; t++) acc[i][j][t] = 0.0f;

    const int NIT = K >> 5;

#pragma unroll
    for (int s = 0; s < 2; s++) {
        issue_stage64(smem + s * STAGE64, Agh, Agl, Bgh, Bgl,
                      row0, col0, K, s << 5, tid);
        asm volatile("cp.async.commit_group;\n" ::: "memory");
    }

    for (int it = 0; it < NIT; it++) {
        asm volatile("cp.async.wait_group 1;\n" ::: "memory");
        __syncthreads();

        const u32 stg = smem_base + (u32)((it & 1) * STAGE64);

#pragma unroll
        for (int ks = 0; ks < 2; ks++) {
            const u32 ko = ks << 5;
            u32 ah[2][4], al[2][4];
#pragma unroll
            for (int i = 0; i < 2; i++) {
                u32 aoff = stg + aLane + (u32)(i * 16 * ROWB) + ko;
                ldsm4(ah[i][0], ah[i][1], ah[i][2], ah[i][3], aoff);
                ldsm4(al[i][0], al[i][1], al[i][2], al[i][3], aoff + AA_BYTES);
            }
            u32 bh[4][2], bl[4][2];
#pragma unroll
            for (int p = 0; p < 2; p++) {
                u32 boff = stg + 2*AA_BYTES + bLane + (u32)(p * 16 * ROWB) + ko;
                ldsm4(bh[2*p][0], bh[2*p][1], bh[2*p+1][0], bh[2*p+1][1], boff);
                ldsm4(bl[2*p][0], bl[2*p][1], bl[2*p+1][0], bl[2*p+1][1],
                      boff + BB_BYTES);
            }
#pragma unroll
            for (int i = 0; i < 2; i++)
#pragma unroll
                for (int j = 0; j < 4; j++)
                    mma16816(acc[i][j], ah[i][0], ah[i][1], ah[i][2], ah[i][3],
                             bh[j][0], bh[j][1]);
#pragma unroll
            for (int i = 0; i < 2; i++)
#pragma unroll
                for (int j = 0; j < 4; j++)
                    mma16816(acc[i][j], ah[i][0], ah[i][1], ah[i][2], ah[i][3],
                             bl[j][0], bl[j][1]);
#pragma unroll
            for (int i = 0; i < 2; i++)
#pragma unroll
                for (int j = 0; j < 4; j++)
                    mma16816(acc[i][j], al[i][0], al[i][1], al[i][2], al[i][3],
                             bh[j][0], bh[j][1]);
        }
        __syncthreads();

        if (it + 2 < NIT)
            issue_stage64(smem + (it & 1) * STAGE64, Agh, Agl, Bgh, Bgl,
                          row0, col0, K, (it + 2) << 5, tid);
        asm volatile("cp.async.commit_group;\n" ::: "memory");
    }
}

// Fused projections: grid (N/64, M/128, 3); z selects Q/K/V
struct ProjArgs {
    const u16* Ah[3]; const u16* Al[3];
    const u16* Bh[3]; const u16* Bl[3];
    const float* bias[3];
    u16* Ch[3]; u16* Cl[3];
};

__global__ __launch_bounds__(256, 2)
void proj_fused(ProjArgs pa)
{
    extern __shared__ char smem[];
    const int z = blockIdx.z;

    const int tid  = threadIdx.x;
    const int lane = tid & 31;
    const int wid  = tid >> 5;
    const int g    = lane >> 2;
    const int tg   = lane & 3;
    const int wm0  = (wid & 3) * 32;
    const int wn0  = (wid >> 2) * 32;
    const int row0 = blockIdx.y * 128;
    const int col0 = blockIdx.x * 64;

    float acc[2][4][4];
    gemm64_main(smem, acc, pa.Ah[z], pa.Al[z], pa.Bh[z], pa.Bl[z],
                row0, col0, DM, tid);

    const float* bias = pa.bias[z];
    u16* Ch = pa.Ch[z];
    u16* Cl = pa.Cl[z];
    const int N = DM;

#pragma unroll
    for (int i = 0; i < 2; i++) {
        int r1 = row0 + wm0 + 16 * i + g;
        int r2 = r1 + 8;
#pragma unroll
        for (int j = 0; j < 4; j++) {
            int n = col0 + wn0 + 8 * j + 2 * tg;
            float b0 = bias[n], b1 = bias[n + 1];
            float v00 = acc[i][j][0] + b0;
            float v01 = acc[i][j][1] + b1;
            float v10 = acc[i][j][2] + b0;
            float v11 = acc[i][j][3] + b1;

            if (z != 2) {
                u16 h0,l0,h1,l1;
                split_bf16(v00, h0, l0); split_bf16(v01, h1, l1);
                *reinterpret_cast<u32*>(Ch + (size_t)r1 * N + n) = pack2(h0, h1);
                *reinterpret_cast<u32*>(Cl + (size_t)r1 * N + n) = pack2(l0, l1);
                split_bf16(v10, h0, l0); split_bf16(v11, h1, l1);
                *reinterpret_cast<u32*>(Ch + (size_t)r2 * N + n) = pack2(h0, h1);
                *reinterpret_cast<u32*>(Cl + (size_t)r2 * N + n) = pack2(l0, l1);
            } else {
                int   rr[2] = { r1, r2 };
                float vv[2][2] = { { v00, v01 }, { v10, v11 } };
#pragma unroll
                for (int t = 0; t < 2; t++) {
                    int m  = rr[t];
                    int b  = m >> 12;
                    int mm = m & (SEQ - 1);
#pragma unroll
                    for (int u = 0; u < 2; u++) {
                        u16 h, l;
                        split_bf16(vv[t][u], h, l);
                        size_t idx = ((size_t)(b * DM + n + u)) * SEQ + mm;
                        Ch[idx] = h;
                        Cl[idx] = l;
                    }
                }
            }
        }
    }
}

// attn @ V via vT: BN=64, fp32 out, z = batch
__global__ __launch_bounds__(256, 2)
void gemm_av(const u16* __restrict__ Agh, const u16* __restrict__ Agl,
             const u16* __restrict__ Bgh, const u16* __restrict__ Bgl,
             float* __restrict__ Cf,
             int M, int N, int K, long sA, long sB, long sC)
{
    extern __shared__ char smem[];
    const int bz = blockIdx.z;
    Agh += (size_t)bz * sA;  Agl += (size_t)bz * sA;
    Bgh += (size_t)bz * sB;  Bgl += (size_t)bz * sB;

    const int tid  = threadIdx.x;
    const int lane = tid & 31;
    const int wid  = tid >> 5;
    const int g    = lane >> 2;
    const int tg   = lane & 3;
    const int wm0  = (wid & 3) * 32;
    const int wn0  = (wid >> 2) * 32;
    const int row0 = blockIdx.y * 128;
    const int col0 = blockIdx.x * 64;

    float acc[2][4][4];
    gemm64_main(smem, acc, Agh, Agl, Bgh, Bgl, row0, col0, K, tid);

    float* Cb = Cf + (size_t)bz * sC;
#pragma unroll
    for (int i = 0; i < 2; i++) {
        int r1 = row0 + wm0 + 16 * i + g;
        int r2 = r1 + 8;
#pragma unroll
        for (int j = 0; j < 4; j++) {
            int n = col0 + wn0 + 8 * j + 2 * tg;
            *reinterpret_cast<float2*>(Cb + (size_t)r1 * N + n) =
                make_float2(acc[i][j][0], acc[i][j][1]);
            *reinterpret_cast<float2*>(Cb + (size_t)r2 * N + n) =
                make_float2(acc[i][j][2], acc[i][j][3]);
        }
    }
}

// ---------------------------------------------------------------------------
// Row softmax: fp32 scores row -> split bf16 attention row
// ---------------------------------------------------------------------------
__global__ __launch_bounds__(256)
void softmax_split(const float* __restrict__ scores,
                   u16* __restrict__ ah, u16* __restrict__ al)
{
    const int S = SEQ;
    const size_t roff = (size_t)blockIdx.x * S;
    const float* p = scores + roff;
    const int tid = threadIdx.x;

    float v[16];
#pragma unroll
    for (int i = 0; i < 16; i++) v[i] = p[i * 256 + tid];

    float m = v[0];
#pragma unroll
    for (int i = 1; i < 16; i++) m = fmaxf(m, v[i]);

    __shared__ float red[32];
#pragma unroll
    for (int o = 16; o > 0; o >>= 1)
        m = fmaxf(m, __shfl_xor_sync(0xffffffffu, m, o));
    if ((tid & 31) == 0) red[tid >> 5] = m;
    __syncthreads();
    if (tid < 32) {
        float t = (tid < 8) ? red[tid] : -INFINITY;
#pragma unroll
        for (int o = 4; o > 0; o >>= 1)
            t = fmaxf(t, __shfl_xor_sync(0xffffffffu, t, o));
        if (tid == 0) red[0] = t;
    }
    __syncthreads();
    m = red[0];
    __syncthreads();

    float s = 0.0f;
#pragma unroll
    for (int i = 0; i < 16; i++) {
        v[i] = __expf(v[i] - m);
        s += v[i];
    }
#pragma unroll
    for (int o = 16; o > 0; o >>= 1)
        s += __shfl_xor_sync(0xffffffffu, s, o);
    if ((tid & 31) == 0) red[tid >> 5] = s;
    __syncthreads();
    if (tid < 32) {
        float t = (tid < 8) ? red[tid] : 0.0f;
#pragma unroll
        for (int o = 4; o > 0; o >>= 1)
            t += __shfl_xor_sync(0xffffffffu, t, o);
        if (tid == 0) red[0] = t;
    }
    __syncthreads();
    float inv = 1.0f / red[0];

#pragma unroll
    for (int i = 0; i < 16; i++) {
        float a = v[i] * inv;
        u16 h, l;
        split_bf16(a, h, l);
        ah[roff + i * 256 + tid] = h;
        al[roff + i * 256 + tid] = l;
    }
}

// ---------------------------------------------------------------------------
extern "C" void kernel_launch(void* const* d_in, const int* in_sizes, int n_in,
                              void* d_out, int out_size)
{
    const float* Q   = (const float*)d_in[0];
    const float* K   = (const float*)d_in[1];
    const float* V   = (const float*)d_in[2];
    const float* W_q = (const float*)d_in[3];
    const float* b_q = (const float*)d_in[4];
    const float* W_k = (const float*)d_in[5];
    const float* b_k = (const float*)d_in[6];
    const float* W_v = (const float*)d_in[7];
    const float* b_v = (const float*)d_in[8];
    float* out = (float*)d_out;

    u16 *Qh,*Ql,*Kh,*Kl,*Vh,*Vl, *Wqh,*Wql,*Wkh,*Wkl,*Wvh,*Wvl;
    u16 *qh,*ql,*kh,*kl,*vth,*vtl,*ah,*al;
    float* s;
    cudaGetSymbolAddress((void**)&Qh, g_Qh);   cudaGetSymbolAddress((void**)&Ql, g_Ql);
    cudaGetSymbolAddress((void**)&Kh, g_Kh);   cudaGetSymbolAddress((void**)&Kl, g_Kl);
    cudaGetSymbolAddress((void**)&Vh, g_Vh);   cudaGetSymbolAddress((void**)&Vl, g_Vl);
    cudaGetSymbolAddress((void**)&Wqh, g_Wqh); cudaGetSymbolAddress((void**)&Wql, g_Wql);
    cudaGetSymbolAddress((void**)&Wkh, g_Wkh); cudaGetSymbolAddress((void**)&Wkl, g_Wkl);
    cudaGetSymbolAddress((void**)&Wvh, g_Wvh); cudaGetSymbolAddress((void**)&Wvl, g_Wvl);
    cudaGetSymbolAddress((void**)&qh, g_qh);   cudaGetSymbolAddress((void**)&ql, g_ql);
    cudaGetSymbolAddress((void**)&kh, g_kh);   cudaGetSymbolAddress((void**)&kl, g_kl);
    cudaGetSymbolAddress((void**)&vth, g_vth); cudaGetSymbolAddress((void**)&vtl, g_vtl);
    cudaGetSymbolAddress((void**)&ah, g_ah);   cudaGetSymbolAddress((void**)&al, g_al);
    cudaGetSymbolAddress((void**)&s, g_s);

    cudaFuncSetAttribute(gemm_scores, cudaFuncAttributeMaxDynamicSharedMemorySize, DYNSMEM);
    cudaFuncSetAttribute(proj_fused,  cudaFuncAttributeMaxDynamicSharedMemorySize, DYNSMEM64);
    cudaFuncSetAttribute(gemm_av,     cudaFuncAttributeMaxDynamicSharedMemorySize, DYNSMEM64);

    const float scale = 1.0f / sqrtf((float)DM);
    dim3 blk(256);

    const int n1 = ROWS * DM;
    const int n2 = DM * DM;
    split3_kernel<<<dim3(n1/1024, 3), blk>>>(Q, K, V,
        Qh, Ql, Kh, Kl, Vh, Vl, n1);
    split3_kernel<<<dim3(n2/1024, 3), blk>>>(W_q, W_k, W_v,
        Wqh, Wql, Wkh, Wkl, Wvh, Wvl, n2);

    // Fused projections (BN=64): grid (8, 64, 3) = 1536 CTAs
    {
        ProjArgs pa;
        pa.Ah[0]=Qh; pa.Al[0]=Ql; pa.Bh[0]=Wqh; pa.Bl[0]=Wql; pa.bias[0]=b_q;
        pa.Ch[0]=qh; pa.Cl[0]=ql;
        pa.Ah[1]=Kh; pa.Al[1]=Kl; pa.Bh[1]=Wkh; pa.Bl[1]=Wkl; pa.bias[1]=b_k;
        pa.Ch[1]=kh; pa.Cl[1]=kl;
        pa.Ah[2]=Vh; pa.Al[2]=Vl; pa.Bh[2]=Wvh; pa.Bl[2]=Wvl; pa.bias[2]=b_v;
        pa.Ch[2]=vth; pa.Cl[2]=vtl;
        dim3 gp(DM/64, ROWS/128, 3);
        proj_fused<<<gp, blk, DYNSMEM64>>>(pa);
    }

    // Scores (NT, per batch): s = scale * q @ k^T  (BN=128)
    {
        dim3 gs(SEQ/128, SEQ/128, BATCH);
        gemm_scores<<<gs, blk, DYNSMEM>>>(qh, ql, kh, kl,
            s, SEQ, SEQ, DM,
            (long)SEQ*DM, (long)SEQ*DM, (long)SEQ*SEQ, scale);
    }

    // Softmax -> split bf16 attention
    softmax_split<<<ROWS, blk>>>(s, ah, al);

    // Output: out = attn @ v via vT  (BN=64): grid (8, 32, 2) = 512 CTAs
    {
        dim3 go(DM/64, SEQ/128, BATCH);
        gemm_av<<<go, blk, DYNSMEM64>>>(ah, al, vth, vtl,
            out, SEQ, DM, SEQ,
            (long)SEQ*SEQ, (long)DM*SEQ, (long)SEQ*DM);
    }
}

// round 10
// speedup vs baseline: 1.0963x; 1.0963x over previous
#include <cuda_runtime.h>
#include <cuda_bf16.h>
#include <math.h>

#define BATCH 2
#define SEQ   4096
#define DM    512
#define ROWS  (BATCH*SEQ)   // 8192
#define SPLITK 4

typedef unsigned short u16;
typedef unsigned int   u32;

// ---------------------------------------------------------------------------
// Device scratch (allocation-free rule: __device__ globals)
// ---------------------------------------------------------------------------
__device__ u16 g_Qh[(size_t)ROWS*DM], g_Ql[(size_t)ROWS*DM];
__device__ u16 g_Kh[(size_t)ROWS*DM], g_Kl[(size_t)ROWS*DM];
__device__ u16 g_Vh[(size_t)ROWS*DM], g_Vl[(size_t)ROWS*DM];
__device__ u16 g_Wqh[DM*DM], g_Wql[DM*DM];
__device__ u16 g_Wkh[DM*DM], g_Wkl[DM*DM];
__device__ u16 g_Wvh[DM*DM], g_Wvl[DM*DM];
__device__ u16 g_qh[(size_t)ROWS*DM], g_ql[(size_t)ROWS*DM];
__device__ u16 g_kh[(size_t)ROWS*DM], g_kl[(size_t)ROWS*DM];
__device__ u16 g_vth[(size_t)BATCH*DM*SEQ], g_vtl[(size_t)BATCH*DM*SEQ];
__device__ float g_s[(size_t)BATCH*SEQ*SEQ];
__device__ u16 g_ah[(size_t)BATCH*SEQ*SEQ], g_al[(size_t)BATCH*SEQ*SEQ];
__device__ float g_part[(size_t)BATCH*SPLITK*SEQ*DM];   // attnV split-K partials

// ---------------------------------------------------------------------------
// bf16 helpers
// ---------------------------------------------------------------------------
__device__ __forceinline__ u16 f2bf(float x) {
    __nv_bfloat16 h = __float2bfloat16(x);
    return *reinterpret_cast<u16*>(&h);
}
__device__ __forceinline__ float bf2f(u16 u) {
    __nv_bfloat16 h = *reinterpret_cast<__nv_bfloat16*>(&u);
    return __bfloat162float(h);
}
__device__ __forceinline__ void split_bf16(float x, u16& hi, u16& lo) {
    hi = f2bf(x);
    lo = f2bf(x - bf2f(hi));
}
__device__ __forceinline__ unsigned pack2(u16 a, u16 b) {
    return (unsigned)a | ((unsigned)b << 16);
}

__device__ __forceinline__ void mma16816(float c[4],
                                         u32 a0, u32 a1, u32 a2, u32 a3,
                                         u32 b0, u32 b1)
{
    asm volatile(
        "mma.sync.aligned.m16n8k16.row.col.f32.bf16.bf16.f32 "
        "{%0,%1,%2,%3}, {%4,%5,%6,%7}, {%8,%9}, {%0,%1,%2,%3};\n"
        : "+f"(c[0]), "+f"(c[1]), "+f"(c[2]), "+f"(c[3])
        : "r"(a0), "r"(a1), "r"(a2), "r"(a3), "r"(b0), "r"(b1));
}

__device__ __forceinline__ void cp16(void* smem_dst, const void* gsrc) {
    u32 u = (u32)__cvta_generic_to_shared(smem_dst);
    asm volatile("cp.async.cg.shared.global [%0], [%1], 16;\n" :: "r"(u), "l"(gsrc));
}

__device__ __forceinline__ void ldsm4(u32& r0, u32& r1, u32& r2, u32& r3, u32 addr) {
    asm volatile("ldmatrix.sync.aligned.m8n8.x4.shared.b16 {%0,%1,%2,%3}, [%4];"
                 : "=r"(r0), "=r"(r1), "=r"(r2), "=r"(r3) : "r"(addr));
}

// ---------------------------------------------------------------------------
// Fused fp32 -> split bf16 for 3 equal-size arrays
// ---------------------------------------------------------------------------
__global__ __launch_bounds__(256)
void split3_kernel(const float* __restrict__ x0, const float* __restrict__ x1,
                   const float* __restrict__ x2,
                   u16* __restrict__ h0a, u16* __restrict__ l0a,
                   u16* __restrict__ h1a, u16* __restrict__ l1a,
                   u16* __restrict__ h2a, u16* __restrict__ l2a, int n)
{
    const float* x;
    u16 *hp, *lp;
    if (blockIdx.y == 0)      { x = x0; hp = h0a; lp = l0a; }
    else if (blockIdx.y == 1) { x = x1; hp = h1a; lp = l1a; }
    else                      { x = x2; hp = h2a; lp = l2a; }

    int i = (blockIdx.x * blockDim.x + threadIdx.x) * 4;
    if (i >= n) return;
    float4 f = *reinterpret_cast<const float4*>(x + i);
    u16 h0,l0,h1,l1,h2,l2,h3,l3;
    split_bf16(f.x, h0, l0);
    split_bf16(f.y, h1, l1);
    split_bf16(f.z, h2, l2);
    split_bf16(f.w, h3, l3);
    *reinterpret_cast<uint2*>(hp + i) = make_uint2(pack2(h0,h1), pack2(h2,h3));
    *reinterpret_cast<uint2*>(lp + i) = make_uint2(pack2(l0,l1), pack2(l2,l3));
}

// ---------------------------------------------------------------------------
// Pipelined bf16 NT GEMM, 3-term hi/lo split, LDSM fragment loads:
//   C[m,n] = alpha * sum_{k in split} A[m,k]*B[n,k]  (+ bias[n])
// Block 128x128x32(bf16), 256 thr = 8 warps (4M x 2N), warp tile 32x64.
// 2-stage cp.async ring (80KB smem) -> 2 CTAs/SM. Term-major MMA order.
// splitk: blockIdx.z = batch*splitk + ks; CTA covers K-range [ks*K/splitk, ...).
// EPI0 writes to Cf + blockIdx.z * sC (partials when splitk>1).
// EPI: 0 = fp32 C (alpha)  1 = split bf16 C (+bias)
//      2 = split bf16 C transposed per-batch [b][n][m] (+bias)
// ---------------------------------------------------------------------------
#define SMP   40                   // padded row stride (bf16): 80B, LDSM-conflict-free
#define ROWB  (SMP*2)              // 80 bytes
#define ARR_BYTES   (128*ROWB)     // 10240
#define STAGE_BYTES (4*ARR_BYTES)  // 40960
#define NSTAGE 2
#define DYNSMEM (NSTAGE*STAGE_BYTES)   // 81920 -> 2 CTAs/SM

__device__ __forceinline__ void issue_stage(char* base,
    const u16* __restrict__ Agh, const u16* __restrict__ Agl,
    const u16* __restrict__ Bgh, const u16* __restrict__ Bgl,
    int row0, int col0, int Kstride, int k0, int tid)
{
#pragma unroll
    for (int e = 0; e < 2; e++) {
        int idx = tid + (e << 8);        // 0..511
        int r = idx >> 2;                // 0..127
        int c = (idx & 3) << 3;          // 0,8,16,24 (bf16 elems)
        size_t offA = (size_t)(row0 + r) * Kstride + k0 + c;
        size_t offB = (size_t)(col0 + r) * Kstride + k0 + c;
        int sm = r * ROWB + c * 2;
        cp16(base + sm,                 Agh + offA);
        cp16(base + ARR_BYTES   + sm,   Agl + offA);
        cp16(base + 2*ARR_BYTES + sm,   Bgh + offB);
        cp16(base + 3*ARR_BYTES + sm,   Bgl + offB);
    }
}

template <int EPI>
__global__ __launch_bounds__(256, 2)
void gemm_bf16(const u16* __restrict__ Agh, const u16* __restrict__ Agl,
               const u16* __restrict__ Bgh, const u16* __restrict__ Bgl,
               const float* __restrict__ bias,
               float* __restrict__ Cf,
               u16* __restrict__ Ch, u16* __restrict__ Cl,
               int M, int N, int K, int splitk,
               long sA, long sB, long sC, float alpha)
{
    extern __shared__ char smem[];

    const int bzAll = blockIdx.z;
    const int bat   = bzAll / splitk;
    const int ksp   = bzAll - bat * splitk;
    const int Kpart = K / splitk;
    const int kbeg  = ksp * Kpart;

    Agh += (size_t)bat * sA;  Agl += (size_t)bat * sA;
    Bgh += (size_t)bat * sB;  Bgl += (size_t)bat * sB;

    const int tid  = threadIdx.x;
    const int lane = tid & 31;
    const int wid  = tid >> 5;          // 0..7
    const int g    = lane >> 2;
    const int tg   = lane & 3;
    const int wm0  = (wid & 3) * 32;    // 4 warps along M
    const int wn0  = (wid >> 2) * 64;   // 2 warps along N
    const int row0 = blockIdx.y * 128;
    const int col0 = blockIdx.x * 128;

    const u32 aLane = (u32)((wm0 + (lane & 15)) * ROWB + ((lane >> 4) << 4));
    const u32 bLane = (u32)((wn0 + ((lane >> 4) << 3) + (lane & 7)) * ROWB
                            + ((lane & 8) << 1));
    const u32 smem_base = (u32)__cvta_generic_to_shared(smem);

    float acc[2][8][4];
#pragma unroll
    for (int i = 0; i < 2; i++)
#pragma unroll
        for (int j = 0; j < 8; j++)
#pragma unroll
            for (int t = 0; t < 4; t++) acc[i][j][t] = 0.0f;

    const int NIT = Kpart >> 5;

#pragma unroll
    for (int s = 0; s < NSTAGE; s++) {
        issue_stage(smem + s * STAGE_BYTES, Agh, Agl, Bgh, Bgl,
                    row0, col0, K, kbeg + (s << 5), tid);
        asm volatile("cp.async.commit_group;\n" ::: "memory");
    }

    for (int it = 0; it < NIT; it++) {
        asm volatile("cp.async.wait_group 1;\n" ::: "memory");
        __syncthreads();

        const u32 stg = smem_base + (u32)((it & 1) * STAGE_BYTES);

#pragma unroll
        for (int ks = 0; ks < 2; ks++) {
            const u32 ko = ks << 5;   // 16 bf16 = 32 bytes
            u32 ah[2][4], al[2][4];
#pragma unroll
            for (int i = 0; i < 2; i++) {
                u32 aoff = stg + aLane + (u32)(i * 16 * ROWB) + ko;
                ldsm4(ah[i][0], ah[i][1], ah[i][2], ah[i][3], aoff);
                ldsm4(al[i][0], al[i][1], al[i][2], al[i][3], aoff + ARR_BYTES);
            }
#pragma unroll
            for (int half = 0; half < 2; half++) {
                u32 bh[4][2], bl[4][2];
#pragma unroll
                for (int p = 0; p < 2; p++) {
                    u32 boff = stg + 2*ARR_BYTES + bLane
                             + (u32)((half * 2 + p) * 16 * ROWB) + ko;
                    ldsm4(bh[2*p][0], bh[2*p][1], bh[2*p+1][0], bh[2*p+1][1], boff);
                    ldsm4(bl[2*p][0], bl[2*p][1], bl[2*p+1][0], bl[2*p+1][1],
                          boff + ARR_BYTES);
                }
                // term-major: consecutive MMAs to same acc are 8 apart
#pragma unroll
                for (int i = 0; i < 2; i++)
#pragma unroll
                    for (int j = 0; j < 4; j++)
                        mma16816(acc[i][half*4 + j],
                                 ah[i][0], ah[i][1], ah[i][2], ah[i][3],
                                 bh[j][0], bh[j][1]);
#pragma unroll
                for (int i = 0; i < 2; i++)
#pragma unroll
                    for (int j = 0; j < 4; j++)
                        mma16816(acc[i][half*4 + j],
                                 ah[i][0], ah[i][1], ah[i][2], ah[i][3],
                                 bl[j][0], bl[j][1]);
#pragma unroll
                for (int i = 0; i < 2; i++)
#pragma unroll
                    for (int j = 0; j < 4; j++)
                        mma16816(acc[i][half*4 + j],
                                 al[i][0], al[i][1], al[i][2], al[i][3],
                                 bh[j][0], bh[j][1]);
            }
        }
        __syncthreads();

        if (it + NSTAGE < NIT)
            issue_stage(smem + (it & 1) * STAGE_BYTES, Agh, Agl, Bgh, Bgl,
                        row0, col0, K, kbeg + ((it + NSTAGE) << 5), tid);
        asm volatile("cp.async.commit_group;\n" ::: "memory");
    }

    // ---- Epilogue ----
#pragma unroll
    for (int i = 0; i < 2; i++) {
        int r1 = row0 + wm0 + 16 * i + g;
        int r2 = r1 + 8;
#pragma unroll
        for (int j = 0; j < 8; j++) {
            int n = col0 + wn0 + 8 * j + 2 * tg;
            float b0 = 0.0f, b1 = 0.0f;
            if (bias != nullptr) { b0 = bias[n]; b1 = bias[n + 1]; }
            float v00 = acc[i][j][0] * alpha + b0;
            float v01 = acc[i][j][1] * alpha + b1;
            float v10 = acc[i][j][2] * alpha + b0;
            float v11 = acc[i][j][3] * alpha + b1;

            if (EPI == 0) {
                float* Cb = Cf + (size_t)bzAll * sC;
                *reinterpret_cast<float2*>(Cb + (size_t)r1 * N + n) = make_float2(v00, v01);
                *reinterpret_cast<float2*>(Cb + (size_t)r2 * N + n) = make_float2(v10, v11);
            } else if (EPI == 1) {
                u16 h0,l0,h1,l1;
                split_bf16(v00, h0, l0); split_bf16(v01, h1, l1);
                *reinterpret_cast<u32*>(Ch + (size_t)r1 * N + n) = pack2(h0, h1);
                *reinterpret_cast<u32*>(Cl + (size_t)r1 * N + n) = pack2(l0, l1);
                split_bf16(v10, h0, l0); split_bf16(v11, h1, l1);
                *reinterpret_cast<u32*>(Ch + (size_t)r2 * N + n) = pack2(h0, h1);
                *reinterpret_cast<u32*>(Cl + (size_t)r2 * N + n) = pack2(l0, l1);
            } else {
                int   rr[2] = { r1, r2 };
                float vv[2][2] = { { v00, v01 }, { v10, v11 } };
#pragma unroll
                for (int t = 0; t < 2; t++) {
                    int m  = rr[t];
                    int b  = m >> 12;          // /SEQ
                    int mm = m & (SEQ - 1);
#pragma unroll
                    for (int u = 0; u < 2; u++) {
                        u16 h, l;
                        split_bf16(vv[t][u], h, l);
                        size_t idx = ((size_t)(b * DM + n + u)) * SEQ + mm;
                        Ch[idx] = h;
                        Cl[idx] = l;
                    }
                }
            }
        }
    }
}

// ---------------------------------------------------------------------------
// Reduce SPLITK partials: out[b][r] = sum_ks part[b*SPLITK+ks][r]
// ---------------------------------------------------------------------------
__global__ __launch_bounds__(256)
void reduce_splitk(const float* __restrict__ part, float* __restrict__ out)
{
    const size_t SD = (size_t)SEQ * DM;
    size_t idx = ((size_t)blockIdx.x * 256 + threadIdx.x) * 4;
    int b = (int)(idx / SD);
    size_t r = idx - (size_t)b * SD;
    const float* pb = part + (size_t)b * SPLITK * SD + r;
    float4 s0 = *reinterpret_cast<const float4*>(pb);
    float4 s1 = *reinterpret_cast<const float4*>(pb + SD);
    float4 s2 = *reinterpret_cast<const float4*>(pb + 2*SD);
    float4 s3 = *reinterpret_cast<const float4*>(pb + 3*SD);
    float4 o;
    o.x = (s0.x + s1.x) + (s2.x + s3.x);
    o.y = (s0.y + s1.y) + (s2.y + s3.y);
    o.z = (s0.z + s1.z) + (s2.z + s3.z);
    o.w = (s0.w + s1.w) + (s2.w + s3.w);
    *reinterpret_cast<float4*>(out + idx) = o;
}

// ---------------------------------------------------------------------------
// Row softmax (vectorized): fp32 scores row -> split bf16 attention row
// ---------------------------------------------------------------------------
__global__ __launch_bounds__(256)
void softmax_split(const float* __restrict__ scores,
                   u16* __restrict__ ah, u16* __restrict__ al)
{
    const size_t roff = (size_t)blockIdx.x * SEQ;
    const float* p = scores + roff;
    const int tid = threadIdx.x;

    float v[16];
#pragma unroll
    for (int i = 0; i < 4; i++) {
        float4 f = *reinterpret_cast<const float4*>(p + i * 1024 + tid * 4);
        v[i*4+0] = f.x; v[i*4+1] = f.y; v[i*4+2] = f.z; v[i*4+3] = f.w;
    }

    float m = v[0];
#pragma unroll
    for (int i = 1; i < 16; i++) m = fmaxf(m, v[i]);

    __shared__ float red[32];
#pragma unroll
    for (int o = 16; o > 0; o >>= 1)
        m = fmaxf(m, __shfl_xor_sync(0xffffffffu, m, o));
    if ((tid & 31) == 0) red[tid >> 5] = m;
    __syncthreads();
    if (tid < 32) {
        float t = (tid < 8) ? red[tid] : -INFINITY;
#pragma unroll
        for (int o = 4; o > 0; o >>= 1)
            t = fmaxf(t, __shfl_xor_sync(0xffffffffu, t, o));
        if (tid == 0) red[0] = t;
    }
    __syncthreads();
    m = red[0];
    __syncthreads();

    float s = 0.0f;
#pragma unroll
    for (int i = 0; i < 16; i++) {
        v[i] = __expf(v[i] - m);
        s += v[i];
    }
#pragma unroll
    for (int o = 16; o > 0; o >>= 1)
        s += __shfl_xor_sync(0xffffffffu, s, o);
    if ((tid & 31) == 0) red[tid >> 5] = s;
    __syncthreads();
    if (tid < 32) {
        float t = (tid < 8) ? red[tid] : 0.0f;
#pragma unroll
        for (int o = 4; o > 0; o >>= 1)
            t += __shfl_xor_sync(0xffffffffu, t, o);
        if (tid == 0) red[0] = t;
    }
    __syncthreads();
    float inv = 1.0f / red[0];

#pragma unroll
    for (int i = 0; i < 4; i++) {
        u16 h[4], l[4];
#pragma unroll
        for (int j = 0; j < 4; j++)
            split_bf16(v[i*4+j] * inv, h[j], l[j]);
        *reinterpret_cast<uint2*>(ah + roff + i * 1024 + tid * 4) =
            make_uint2(pack2(h[0], h[1]), pack2(h[2], h[3]));
        *reinterpret_cast<uint2*>(al + roff + i * 1024 + tid * 4) =
            make_uint2(pack2(l[0], l[1]), pack2(l[2], l[3]));
    }
}

// ---------------------------------------------------------------------------
extern "C" void kernel_launch(void* const* d_in, const int* in_sizes, int n_in,
                              void* d_out, int out_size)
{
    const float* Q   = (const float*)d_in[0];
    const float* K   = (const float*)d_in[1];
    const float* V   = (const float*)d_in[2];
    const float* W_q = (const float*)d_in[3];
    const float* b_q = (const float*)d_in[4];
    const float* W_k = (const float*)d_in[5];
    const float* b_k = (const float*)d_in[6];
    const float* W_v = (const float*)d_in[7];
    const float* b_v = (const float*)d_in[8];
    float* out = (float*)d_out;

    u16 *Qh,*Ql,*Kh,*Kl,*Vh,*Vl, *Wqh,*Wql,*Wkh,*Wkl,*Wvh,*Wvl;
    u16 *qh,*ql,*kh,*kl,*vth,*vtl,*ah,*al;
    float *s, *part;
    cudaGetSymbolAddress((void**)&Qh, g_Qh);   cudaGetSymbolAddress((void**)&Ql, g_Ql);
    cudaGetSymbolAddress((void**)&Kh, g_Kh);   cudaGetSymbolAddress((void**)&Kl, g_Kl);
    cudaGetSymbolAddress((void**)&Vh, g_Vh);   cudaGetSymbolAddress((void**)&Vl, g_Vl);
    cudaGetSymbolAddress((void**)&Wqh, g_Wqh); cudaGetSymbolAddress((void**)&Wql, g_Wql);
    cudaGetSymbolAddress((void**)&Wkh, g_Wkh); cudaGetSymbolAddress((void**)&Wkl, g_Wkl);
    cudaGetSymbolAddress((void**)&Wvh, g_Wvh); cudaGetSymbolAddress((void**)&Wvl, g_Wvl);
    cudaGetSymbolAddress((void**)&qh, g_qh);   cudaGetSymbolAddress((void**)&ql, g_ql);
    cudaGetSymbolAddress((void**)&kh, g_kh);   cudaGetSymbolAddress((void**)&kl, g_kl);
    cudaGetSymbolAddress((void**)&vth, g_vth); cudaGetSymbolAddress((void**)&vtl, g_vtl);
    cudaGetSymbolAddress((void**)&ah, g_ah);   cudaGetSymbolAddress((void**)&al, g_al);
    cudaGetSymbolAddress((void**)&s, g_s);     cudaGetSymbolAddress((void**)&part, g_part);

    cudaFuncSetAttribute(gemm_bf16<0>, cudaFuncAttributeMaxDynamicSharedMemorySize, DYNSMEM);
    cudaFuncSetAttribute(gemm_bf16<1>, cudaFuncAttributeMaxDynamicSharedMemorySize, DYNSMEM);
    cudaFuncSetAttribute(gemm_bf16<2>, cudaFuncAttributeMaxDynamicSharedMemorySize, DYNSMEM);

    const float scale = 1.0f / sqrtf((float)DM);
    dim3 blk(256);

    const int n1 = ROWS * DM;
    const int n2 = DM * DM;
    split3_kernel<<<dim3(n1/1024, 3), blk>>>(Q, K, V,
        Qh, Ql, Kh, Kl, Vh, Vl, n1);
    split3_kernel<<<dim3(n2/1024, 3), blk>>>(W_q, W_k, W_v,
        Wqh, Wql, Wkh, Wkl, Wvh, Wvl, n2);

    // Projections (NT): [8192,512] = X @ W^T + b ; q,k -> split ; v -> split+T
    {
        dim3 gp(DM/128, ROWS/128, 1);
        gemm_bf16<1><<<gp, blk, DYNSMEM>>>(Qh, Ql, Wqh, Wql, b_q,
            nullptr, qh, ql, ROWS, DM, DM, 1, 0, 0, 0, 1.0f);
        gemm_bf16<1><<<gp, blk, DYNSMEM>>>(Kh, Kl, Wkh, Wkl, b_k,
            nullptr, kh, kl, ROWS, DM, DM, 1, 0, 0, 0, 1.0f);
        gemm_bf16<2><<<gp, blk, DYNSMEM>>>(Vh, Vl, Wvh, Wvl, b_v,
            nullptr, vth, vtl, ROWS, DM, DM, 1, 0, 0, 0, 1.0f);
    }

    // Scores (NT, per batch): s = scale * q @ k^T, M=N=4096, K=512  [launch #6]
    {
        dim3 gs(SEQ/128, SEQ/128, BATCH);
        gemm_bf16<0><<<gs, blk, DYNSMEM>>>(qh, ql, kh, kl, nullptr,
            s, nullptr, nullptr, SEQ, SEQ, DM, 1,
            (long)SEQ*DM, (long)SEQ*DM, (long)SEQ*SEQ, scale);
    }

    // Softmax -> split bf16 attention
    softmax_split<<<ROWS, blk>>>(s, ah, al);

    // Output: out = attn @ v via vT, split-K=4 partials then reduce
    {
        dim3 go(DM/128, SEQ/128, BATCH * SPLITK);   // 1024 CTAs, K=1024 each
        gemm_bf16<0><<<go, blk, DYNSMEM>>>(ah, al, vth, vtl, nullptr,
            part, nullptr, nullptr, SEQ, DM, SEQ, SPLITK,
            (long)SEQ*SEQ, (long)DM*SEQ, (long)SEQ*DM, 1.0f);
        reduce_splitk<<<(ROWS*DM)/1024, blk>>>(part, out);
    }
}

// round 11
// speedup vs baseline: 1.1013x; 1.0046x over previous
#include <cuda_runtime.h>
#include <cuda_bf16.h>
#include <math.h>

#define BATCH 2
#define SEQ   4096
#define DM    512
#define ROWS  (BATCH*SEQ)   // 8192
#define SPLITK 4

typedef unsigned short u16;
typedef unsigned int   u32;

// ---------------------------------------------------------------------------
// Device scratch (allocation-free rule: __device__ globals)
// ---------------------------------------------------------------------------
__device__ u16 g_Qh[(size_t)ROWS*DM], g_Ql[(size_t)ROWS*DM];
__device__ u16 g_Kh[(size_t)ROWS*DM], g_Kl[(size_t)ROWS*DM];
__device__ u16 g_Vh[(size_t)ROWS*DM], g_Vl[(size_t)ROWS*DM];
__device__ u16 g_Wqh[DM*DM], g_Wql[DM*DM];
__device__ u16 g_Wkh[DM*DM], g_Wkl[DM*DM];
__device__ u16 g_Wvh[DM*DM], g_Wvl[DM*DM];
__device__ u16 g_qh[(size_t)ROWS*DM], g_ql[(size_t)ROWS*DM];
__device__ u16 g_kh[(size_t)ROWS*DM], g_kl[(size_t)ROWS*DM];
__device__ u16 g_vth[(size_t)BATCH*DM*SEQ], g_vtl[(size_t)BATCH*DM*SEQ];
__device__ float g_s[(size_t)BATCH*SEQ*SEQ];
__device__ u16 g_ah[(size_t)BATCH*SEQ*SEQ], g_al[(size_t)BATCH*SEQ*SEQ];
__device__ float g_part[(size_t)BATCH*SPLITK*SEQ*DM];   // attnV split-K partials

// ---------------------------------------------------------------------------
// bf16 helpers
// ---------------------------------------------------------------------------
__device__ __forceinline__ u16 f2bf(float x) {
    __nv_bfloat16 h = __float2bfloat16(x);
    return *reinterpret_cast<u16*>(&h);
}
__device__ __forceinline__ float bf2f(u16 u) {
    __nv_bfloat16 h = *reinterpret_cast<__nv_bfloat16*>(&u);
    return __bfloat162float(h);
}
__device__ __forceinline__ void split_bf16(float x, u16& hi, u16& lo) {
    hi = f2bf(x);
    lo = f2bf(x - bf2f(hi));
}
__device__ __forceinline__ unsigned pack2(u16 a, u16 b) {
    return (unsigned)a | ((unsigned)b << 16);
}

__device__ __forceinline__ void mma16816(float c[4],
                                         u32 a0, u32 a1, u32 a2, u32 a3,
                                         u32 b0, u32 b1)
{
    asm volatile(
        "mma.sync.aligned.m16n8k16.row.col.f32.bf16.bf16.f32 "
        "{%0,%1,%2,%3}, {%4,%5,%6,%7}, {%8,%9}, {%0,%1,%2,%3};\n"
        : "+f"(c[0]), "+f"(c[1]), "+f"(c[2]), "+f"(c[3])
        : "r"(a0), "r"(a1), "r"(a2), "r"(a3), "r"(b0), "r"(b1));
}

__device__ __forceinline__ void cp16(void* smem_dst, const void* gsrc) {
    u32 u = (u32)__cvta_generic_to_shared(smem_dst);
    asm volatile("cp.async.cg.shared.global [%0], [%1], 16;\n" :: "r"(u), "l"(gsrc));
}

__device__ __forceinline__ void ldsm4(u32& r0, u32& r1, u32& r2, u32& r3, u32 addr) {
    asm volatile("ldmatrix.sync.aligned.m8n8.x4.shared.b16 {%0,%1,%2,%3}, [%4];"
                 : "=r"(r0), "=r"(r1), "=r"(r2), "=r"(r3) : "r"(addr));
}

// ---------------------------------------------------------------------------
// Fused fp32 -> split bf16 for 3 equal-size arrays
// ---------------------------------------------------------------------------
__global__ __launch_bounds__(256)
void split3_kernel(const float* __restrict__ x0, const float* __restrict__ x1,
                   const float* __restrict__ x2,
                   u16* __restrict__ h0a, u16* __restrict__ l0a,
                   u16* __restrict__ h1a, u16* __restrict__ l1a,
                   u16* __restrict__ h2a, u16* __restrict__ l2a, int n)
{
    const float* x;
    u16 *hp, *lp;
    if (blockIdx.y == 0)      { x = x0; hp = h0a; lp = l0a; }
    else if (blockIdx.y == 1) { x = x1; hp = h1a; lp = l1a; }
    else                      { x = x2; hp = h2a; lp = l2a; }

    int i = (blockIdx.x * blockDim.x + threadIdx.x) * 4;
    if (i >= n) return;
    float4 f = *reinterpret_cast<const float4*>(x + i);
    u16 h0,l0,h1,l1,h2,l2,h3,l3;
    split_bf16(f.x, h0, l0);
    split_bf16(f.y, h1, l1);
    split_bf16(f.z, h2, l2);
    split_bf16(f.w, h3, l3);
    *reinterpret_cast<uint2*>(hp + i) = make_uint2(pack2(h0,h1), pack2(h2,h3));
    *reinterpret_cast<uint2*>(lp + i) = make_uint2(pack2(l0,l1), pack2(l2,l3));
}

// ---------------------------------------------------------------------------
// Shared mainloop: pipelined bf16 NT GEMM, 3-term hi/lo split, LDSM loads.
// Block 128x128x32(bf16), 256 thr = 8 warps (4M x 2N), warp tile 32x64.
// 2-stage cp.async ring (80KB smem) -> 2 CTAs/SM. Term-major MMA order.
// ---------------------------------------------------------------------------
#define SMP   40                   // padded row stride (bf16): 80B, LDSM-conflict-free
#define ROWB  (SMP*2)              // 80 bytes
#define ARR_BYTES   (128*ROWB)     // 10240
#define STAGE_BYTES (4*ARR_BYTES)  // 40960
#define NSTAGE 2
#define DYNSMEM (NSTAGE*STAGE_BYTES)   // 81920 -> 2 CTAs/SM

__device__ __forceinline__ void issue_stage(char* base,
    const u16* __restrict__ Agh, const u16* __restrict__ Agl,
    const u16* __restrict__ Bgh, const u16* __restrict__ Bgl,
    int row0, int col0, int Kstride, int k0, int tid)
{
#pragma unroll
    for (int e = 0; e < 2; e++) {
        int idx = tid + (e << 8);        // 0..511
        int r = idx >> 2;                // 0..127
        int c = (idx & 3) << 3;          // 0,8,16,24 (bf16 elems)
        size_t offA = (size_t)(row0 + r) * Kstride + k0 + c;
        size_t offB = (size_t)(col0 + r) * Kstride + k0 + c;
        int sm = r * ROWB + c * 2;
        cp16(base + sm,                 Agh + offA);
        cp16(base + ARR_BYTES   + sm,   Agl + offA);
        cp16(base + 2*ARR_BYTES + sm,   Bgh + offB);
        cp16(base + 3*ARR_BYTES + sm,   Bgl + offB);
    }
}

__device__ __forceinline__ void gemm_main(char* smem, float acc[2][8][4],
    const u16* __restrict__ Agh, const u16* __restrict__ Agl,
    const u16* __restrict__ Bgh, const u16* __restrict__ Bgl,
    int row0, int col0, int Kstride, int kbeg, int Kpart, int tid)
{
    const int lane = tid & 31;
    const int wid  = tid >> 5;          // 0..7
    const int wm0  = (wid & 3) * 32;    // 4 warps along M
    const int wn0  = (wid >> 2) * 64;   // 2 warps along N

    const u32 aLane = (u32)((wm0 + (lane & 15)) * ROWB + ((lane >> 4) << 4));
    const u32 bLane = (u32)((wn0 + ((lane >> 4) << 3) + (lane & 7)) * ROWB
                            + ((lane & 8) << 1));
    const u32 smem_base = (u32)__cvta_generic_to_shared(smem);

#pragma unroll
    for (int i = 0; i < 2; i++)
#pragma unroll
        for (int j = 0; j < 8; j++)
#pragma unroll
            for (int t = 0; t < 4; t++) acc[i][j][t] = 0.0f;

    const int NIT = Kpart >> 5;

#pragma unroll
    for (int s = 0; s < NSTAGE; s++) {
        issue_stage(smem + s * STAGE_BYTES, Agh, Agl, Bgh, Bgl,
                    row0, col0, Kstride, kbeg + (s << 5), tid);
        asm volatile("cp.async.commit_group;\n" ::: "memory");
    }

    for (int it = 0; it < NIT; it++) {
        asm volatile("cp.async.wait_group 1;\n" ::: "memory");
        __syncthreads();

        const u32 stg = smem_base + (u32)((it & 1) * STAGE_BYTES);

#pragma unroll
        for (int ks = 0; ks < 2; ks++) {
            const u32 ko = ks << 5;   // 16 bf16 = 32 bytes
            u32 ah[2][4], al[2][4];
#pragma unroll
            for (int i = 0; i < 2; i++) {
                u32 aoff = stg + aLane + (u32)(i * 16 * ROWB) + ko;
                ldsm4(ah[i][0], ah[i][1], ah[i][2], ah[i][3], aoff);
                ldsm4(al[i][0], al[i][1], al[i][2], al[i][3], aoff + ARR_BYTES);
            }
#pragma unroll
            for (int half = 0; half < 2; half++) {
                u32 bh[4][2], bl[4][2];
#pragma unroll
                for (int p = 0; p < 2; p++) {
                    u32 boff = stg + 2*ARR_BYTES + bLane
                             + (u32)((half * 2 + p) * 16 * ROWB) + ko;
                    ldsm4(bh[2*p][0], bh[2*p][1], bh[2*p+1][0], bh[2*p+1][1], boff);
                    ldsm4(bl[2*p][0], bl[2*p][1], bl[2*p+1][0], bl[2*p+1][1],
                          boff + ARR_BYTES);
                }
                // term-major: consecutive MMAs to same acc are 8 apart
#pragma unroll
                for (int i = 0; i < 2; i++)
#pragma unroll
                    for (int j = 0; j < 4; j++)
                        mma16816(acc[i][half*4 + j],
                                 ah[i][0], ah[i][1], ah[i][2], ah[i][3],
                                 bh[j][0], bh[j][1]);
#pragma unroll
                for (int i = 0; i < 2; i++)
#pragma unroll
                    for (int j = 0; j < 4; j++)
                        mma16816(acc[i][half*4 + j],
                                 ah[i][0], ah[i][1], ah[i][2], ah[i][3],
                                 bl[j][0], bl[j][1]);
#pragma unroll
                for (int i = 0; i < 2; i++)
#pragma unroll
                    for (int j = 0; j < 4; j++)
                        mma16816(acc[i][half*4 + j],
                                 al[i][0], al[i][1], al[i][2], al[i][3],
                                 bh[j][0], bh[j][1]);
            }
        }
        __syncthreads();

        if (it + NSTAGE < NIT)
            issue_stage(smem + (it & 1) * STAGE_BYTES, Agh, Agl, Bgh, Bgl,
                        row0, col0, Kstride, kbeg + ((it + NSTAGE) << 5), tid);
        asm volatile("cp.async.commit_group;\n" ::: "memory");
    }
}

// ---------------------------------------------------------------------------
// fp32-out GEMM (scores / attnV partials), with split-K support
// ---------------------------------------------------------------------------
__global__ __launch_bounds__(256, 2)
void gemm_f32(const u16* __restrict__ Agh, const u16* __restrict__ Agl,
              const u16* __restrict__ Bgh, const u16* __restrict__ Bgl,
              float* __restrict__ Cf,
              int M, int N, int K, int splitk,
              long sA, long sB, long sC, float alpha)
{
    extern __shared__ char smem[];

    const int bzAll = blockIdx.z;
    const int bat   = bzAll / splitk;
    const int ksp   = bzAll - bat * splitk;
    const int Kpart = K / splitk;

    Agh += (size_t)bat * sA;  Agl += (size_t)bat * sA;
    Bgh += (size_t)bat * sB;  Bgl += (size_t)bat * sB;

    const int tid  = threadIdx.x;
    const int lane = tid & 31;
    const int wid  = tid >> 5;
    const int g    = lane >> 2;
    const int tg   = lane & 3;
    const int wm0  = (wid & 3) * 32;
    const int wn0  = (wid >> 2) * 64;
    const int row0 = blockIdx.y * 128;
    const int col0 = blockIdx.x * 128;

    float acc[2][8][4];
    gemm_main(smem, acc, Agh, Agl, Bgh, Bgl,
              row0, col0, K, ksp * Kpart, Kpart, tid);

    float* Cb = Cf + (size_t)bzAll * sC;
#pragma unroll
    for (int i = 0; i < 2; i++) {
        int r1 = row0 + wm0 + 16 * i + g;
        int r2 = r1 + 8;
#pragma unroll
        for (int j = 0; j < 8; j++) {
            int n = col0 + wn0 + 8 * j + 2 * tg;
            *reinterpret_cast<float2*>(Cb + (size_t)r1 * N + n) =
                make_float2(acc[i][j][0] * alpha, acc[i][j][1] * alpha);
            *reinterpret_cast<float2*>(Cb + (size_t)r2 * N + n) =
                make_float2(acc[i][j][2] * alpha, acc[i][j][3] * alpha);
        }
    }
}

// ---------------------------------------------------------------------------
// Fused Q/K/V projections in ONE launch: grid (DM/128, ROWS/128, 3)
// z in {0,1} -> split bf16 out (+bias); z==2 -> split bf16 transposed out
// ---------------------------------------------------------------------------
struct ProjArgs {
    const u16* Ah[3]; const u16* Al[3];
    const u16* Bh[3]; const u16* Bl[3];
    const float* bias[3];
    u16* Ch[3]; u16* Cl[3];
};

__global__ __launch_bounds__(256, 2)
void proj3(ProjArgs pa)
{
    extern __shared__ char smem[];
    const int z = blockIdx.z;

    const int tid  = threadIdx.x;
    const int lane = tid & 31;
    const int wid  = tid >> 5;
    const int g    = lane >> 2;
    const int tg   = lane & 3;
    const int wm0  = (wid & 3) * 32;
    const int wn0  = (wid >> 2) * 64;
    const int row0 = blockIdx.y * 128;
    const int col0 = blockIdx.x * 128;

    float acc[2][8][4];
    gemm_main(smem, acc, pa.Ah[z], pa.Al[z], pa.Bh[z], pa.Bl[z],
              row0, col0, DM, 0, DM, tid);

    const float* bias = pa.bias[z];
    u16* Ch = pa.Ch[z];
    u16* Cl = pa.Cl[z];
    const int N = DM;

#pragma unroll
    for (int i = 0; i < 2; i++) {
        int r1 = row0 + wm0 + 16 * i + g;
        int r2 = r1 + 8;
#pragma unroll
        for (int j = 0; j < 8; j++) {
            int n = col0 + wn0 + 8 * j + 2 * tg;
            float b0 = bias[n], b1 = bias[n + 1];
            float v00 = acc[i][j][0] + b0;
            float v01 = acc[i][j][1] + b1;
            float v10 = acc[i][j][2] + b0;
            float v11 = acc[i][j][3] + b1;

            if (z != 2) {
                u16 h0,l0,h1,l1;
                split_bf16(v00, h0, l0); split_bf16(v01, h1, l1);
                *reinterpret_cast<u32*>(Ch + (size_t)r1 * N + n) = pack2(h0, h1);
                *reinterpret_cast<u32*>(Cl + (size_t)r1 * N + n) = pack2(l0, l1);
                split_bf16(v10, h0, l0); split_bf16(v11, h1, l1);
                *reinterpret_cast<u32*>(Ch + (size_t)r2 * N + n) = pack2(h0, h1);
                *reinterpret_cast<u32*>(Cl + (size_t)r2 * N + n) = pack2(l0, l1);
            } else {
                int   rr[2] = { r1, r2 };
                float vv[2][2] = { { v00, v01 }, { v10, v11 } };
#pragma unroll
                for (int t = 0; t < 2; t++) {
                    int m  = rr[t];
                    int b  = m >> 12;          // /SEQ
                    int mm = m & (SEQ - 1);
#pragma unroll
                    for (int u = 0; u < 2; u++) {
                        u16 h, l;
                        split_bf16(vv[t][u], h, l);
                        size_t idx = ((size_t)(b * DM + n + u)) * SEQ + mm;
                        Ch[idx] = h;
                        Cl[idx] = l;
                    }
                }
            }
        }
    }
}

// ---------------------------------------------------------------------------
// Reduce SPLITK partials: out[b][r] = sum_ks part[b*SPLITK+ks][r]
// ---------------------------------------------------------------------------
__global__ __launch_bounds__(256)
void reduce_splitk(const float* __restrict__ part, float* __restrict__ out)
{
    const size_t SD = (size_t)SEQ * DM;
    size_t idx = ((size_t)blockIdx.x * 256 + threadIdx.x) * 4;
    int b = (int)(idx / SD);
    size_t r = idx - (size_t)b * SD;
    const float* pb = part + (size_t)b * SPLITK * SD + r;
    float4 s0 = *reinterpret_cast<const float4*>(pb);
    float4 s1 = *reinterpret_cast<const float4*>(pb + SD);
    float4 s2 = *reinterpret_cast<const float4*>(pb + 2*SD);
    float4 s3 = *reinterpret_cast<const float4*>(pb + 3*SD);
    float4 o;
    o.x = (s0.x + s1.x) + (s2.x + s3.x);
    o.y = (s0.y + s1.y) + (s2.y + s3.y);
    o.z = (s0.z + s1.z) + (s2.z + s3.z);
    o.w = (s0.w + s1.w) + (s2.w + s3.w);
    *reinterpret_cast<float4*>(out + idx) = o;
}

// ---------------------------------------------------------------------------
// Row softmax (vectorized): fp32 scores row -> split bf16 attention row
// ---------------------------------------------------------------------------
__global__ __launch_bounds__(256)
void softmax_split(const float* __restrict__ scores,
                   u16* __restrict__ ah, u16* __restrict__ al)
{
    const size_t roff = (size_t)blockIdx.x * SEQ;
    const float* p = scores + roff;
    const int tid = threadIdx.x;

    float v[16];
#pragma unroll
    for (int i = 0; i < 4; i++) {
        float4 f = *reinterpret_cast<const float4*>(p + i * 1024 + tid * 4);
        v[i*4+0] = f.x; v[i*4+1] = f.y; v[i*4+2] = f.z; v[i*4+3] = f.w;
    }

    float m = v[0];
#pragma unroll
    for (int i = 1; i < 16; i++) m = fmaxf(m, v[i]);

    __shared__ float red[32];
#pragma unroll
    for (int o = 16; o > 0; o >>= 1)
        m = fmaxf(m, __shfl_xor_sync(0xffffffffu, m, o));
    if ((tid & 31) == 0) red[tid >> 5] = m;
    __syncthreads();
    if (tid < 32) {
        float t = (tid < 8) ? red[tid] : -INFINITY;
#pragma unroll
        for (int o = 4; o > 0; o >>= 1)
            t = fmaxf(t, __shfl_xor_sync(0xffffffffu, t, o));
        if (tid == 0) red[0] = t;
    }
    __syncthreads();
    m = red[0];
    __syncthreads();

    float s = 0.0f;
#pragma unroll
    for (int i = 0; i < 16; i++) {
        v[i] = __expf(v[i] - m);
        s += v[i];
    }
#pragma unroll
    for (int o = 16; o > 0; o >>= 1)
        s += __shfl_xor_sync(0xffffffffu, s, o);
    if ((tid & 31) == 0) red[tid >> 5] = s;
    __syncthreads();
    if (tid < 32) {
        float t = (tid < 8) ? red[tid] : 0.0f;
#pragma unroll
        for (int o = 4; o > 0; o >>= 1)
            t += __shfl_xor_sync(0xffffffffu, t, o);
        if (tid == 0) red[0] = t;
    }
    __syncthreads();
    float inv = 1.0f / red[0];

#pragma unroll
    for (int i = 0; i < 4; i++) {
        u16 h[4], l[4];
#pragma unroll
        for (int j = 0; j < 4; j++)
            split_bf16(v[i*4+j] * inv, h[j], l[j]);
        *reinterpret_cast<uint2*>(ah + roff + i * 1024 + tid * 4) =
            make_uint2(pack2(h[0], h[1]), pack2(h[2], h[3]));
        *reinterpret_cast<uint2*>(al + roff + i * 1024 + tid * 4) =
            make_uint2(pack2(l[0], l[1]), pack2(l[2], l[3]));
    }
}

// ---------------------------------------------------------------------------
extern "C" void kernel_launch(void* const* d_in, const int* in_sizes, int n_in,
                              void* d_out, int out_size)
{
    const float* Q   = (const float*)d_in[0];
    const float* K   = (const float*)d_in[1];
    const float* V   = (const float*)d_in[2];
    const float* W_q = (const float*)d_in[3];
    const float* b_q = (const float*)d_in[4];
    const float* W_k = (const float*)d_in[5];
    const float* b_k = (const float*)d_in[6];
    const float* W_v = (const float*)d_in[7];
    const float* b_v = (const float*)d_in[8];
    float* out = (float*)d_out;

    u16 *Qh,*Ql,*Kh,*Kl,*Vh,*Vl, *Wqh,*Wql,*Wkh,*Wkl,*Wvh,*Wvl;
    u16 *qh,*ql,*kh,*kl,*vth,*vtl,*ah,*al;
    float *s, *part;
    cudaGetSymbolAddress((void**)&Qh, g_Qh);   cudaGetSymbolAddress((void**)&Ql, g_Ql);
    cudaGetSymbolAddress((void**)&Kh, g_Kh);   cudaGetSymbolAddress((void**)&Kl, g_Kl);
    cudaGetSymbolAddress((void**)&Vh, g_Vh);   cudaGetSymbolAddress((void**)&Vl, g_Vl);
    cudaGetSymbolAddress((void**)&Wqh, g_Wqh); cudaGetSymbolAddress((void**)&Wql, g_Wql);
    cudaGetSymbolAddress((void**)&Wkh, g_Wkh); cudaGetSymbolAddress((void**)&Wkl, g_Wkl);
    cudaGetSymbolAddress((void**)&Wvh, g_Wvh); cudaGetSymbolAddress((void**)&Wvl, g_Wvl);
    cudaGetSymbolAddress((void**)&qh, g_qh);   cudaGetSymbolAddress((void**)&ql, g_ql);
    cudaGetSymbolAddress((void**)&kh, g_kh);   cudaGetSymbolAddress((void**)&kl, g_kl);
    cudaGetSymbolAddress((void**)&vth, g_vth); cudaGetSymbolAddress((void**)&vtl, g_vtl);
    cudaGetSymbolAddress((void**)&ah, g_ah);   cudaGetSymbolAddress((void**)&al, g_al);
    cudaGetSymbolAddress((void**)&s, g_s);     cudaGetSymbolAddress((void**)&part, g_part);

    cudaFuncSetAttribute(gemm_f32, cudaFuncAttributeMaxDynamicSharedMemorySize, DYNSMEM);
    cudaFuncSetAttribute(proj3,    cudaFuncAttributeMaxDynamicSharedMemorySize, DYNSMEM);

    const float scale = 1.0f / sqrtf((float)DM);
    dim3 blk(256);

    const int n1 = ROWS * DM;
    const int n2 = DM * DM;
    split3_kernel<<<dim3(n1/1024, 3), blk>>>(Q, K, V,
        Qh, Ql, Kh, Kl, Vh, Vl, n1);
    split3_kernel<<<dim3(n2/1024, 3), blk>>>(W_q, W_k, W_v,
        Wqh, Wql, Wkh, Wkl, Wvh, Wvl, n2);

    // Fused projections (one launch, 768 CTAs)
    {
        ProjArgs pa;
        pa.Ah[0]=Qh; pa.Al[0]=Ql; pa.Bh[0]=Wqh; pa.Bl[0]=Wql; pa.bias[0]=b_q;
        pa.Ch[0]=qh; pa.Cl[0]=ql;
        pa.Ah[1]=Kh; pa.Al[1]=Kl; pa.Bh[1]=Wkh; pa.Bl[1]=Wkl; pa.bias[1]=b_k;
        pa.Ch[1]=kh; pa.Cl[1]=kl;
        pa.Ah[2]=Vh; pa.Al[2]=Vl; pa.Bh[2]=Wvh; pa.Bl[2]=Wvl; pa.bias[2]=b_v;
        pa.Ch[2]=vth; pa.Cl[2]=vtl;
        dim3 gp(DM/128, ROWS/128, 3);
        proj3<<<gp, blk, DYNSMEM>>>(pa);
    }

    // Scores (NT, per batch): s = scale * q @ k^T, M=N=4096, K=512
    {
        dim3 gs(SEQ/128, SEQ/128, BATCH);
        gemm_f32<<<gs, blk, DYNSMEM>>>(qh, ql, kh, kl,
            s, SEQ, SEQ, DM, 1,
            (long)SEQ*DM, (long)SEQ*DM, (long)SEQ*SEQ, scale);
    }

    // Softmax -> split bf16 attention
    softmax_split<<<ROWS, blk>>>(s, ah, al);

    // Output: out = attn @ v via vT, split-K=4 partials then reduce
    {
        dim3 go(DM/128, SEQ/128, BATCH * SPLITK);   // 1024 CTAs, K=1024 each
        gemm_f32<<<go, blk, DYNSMEM>>>(ah, al, vth, vtl,
            part, SEQ, DM, SEQ, SPLITK,
            (long)SEQ*SEQ, (long)DM*SEQ, (long)SEQ*DM, 1.0f);
        reduce_splitk<<<(ROWS*DM)/1024, blk>>>(part, out);
    }
}

// round 12
// speedup vs baseline: 1.1015x; 1.0002x over previous
#include <cuda_runtime.h>
#include <cuda_bf16.h>
#include <math.h>

#define BATCH 2
#define SEQ   4096
#define DM    512
#define ROWS  (BATCH*SEQ)   // 8192
#define SPLITK 4
#define L2E   1.4426950408889634f

typedef unsigned short u16;
typedef unsigned int   u32;

// ---------------------------------------------------------------------------
// Device scratch (allocation-free rule: __device__ globals)
// ---------------------------------------------------------------------------
__device__ u16 g_Qh[(size_t)ROWS*DM], g_Ql[(size_t)ROWS*DM];
__device__ u16 g_Kh[(size_t)ROWS*DM], g_Kl[(size_t)ROWS*DM];
__device__ u16 g_Vh[(size_t)ROWS*DM], g_Vl[(size_t)ROWS*DM];
__device__ u16 g_Wqh[DM*DM], g_Wql[DM*DM];
__device__ u16 g_Wkh[DM*DM], g_Wkl[DM*DM];
__device__ u16 g_Wvh[DM*DM], g_Wvl[DM*DM];
__device__ u16 g_qh[(size_t)ROWS*DM], g_ql[(size_t)ROWS*DM];
__device__ u16 g_kh[(size_t)ROWS*DM], g_kl[(size_t)ROWS*DM];
__device__ u16 g_vth[(size_t)BATCH*DM*SEQ], g_vtl[(size_t)BATCH*DM*SEQ];
__device__ float g_s[(size_t)BATCH*SEQ*SEQ];
__device__ u16 g_ah[(size_t)BATCH*SEQ*SEQ], g_al[(size_t)BATCH*SEQ*SEQ];
__device__ float g_part[(size_t)BATCH*SPLITK*SEQ*DM];   // attnV split-K partials

// ---------------------------------------------------------------------------
// bf16 helpers
// ---------------------------------------------------------------------------
__device__ __forceinline__ u16 f2bf(float x) {
    __nv_bfloat16 h = __float2bfloat16(x);
    return *reinterpret_cast<u16*>(&h);
}
__device__ __forceinline__ float bf2f(u16 u) {
    __nv_bfloat16 h = *reinterpret_cast<__nv_bfloat16*>(&u);
    return __bfloat162float(h);
}
__device__ __forceinline__ void split_bf16(float x, u16& hi, u16& lo) {
    hi = f2bf(x);
    lo = f2bf(x - bf2f(hi));
}
__device__ __forceinline__ unsigned pack2(u16 a, u16 b) {
    return (unsigned)a | ((unsigned)b << 16);
}

__device__ __forceinline__ void mma16816(float c[4],
                                         u32 a0, u32 a1, u32 a2, u32 a3,
                                         u32 b0, u32 b1)
{
    asm volatile(
        "mma.sync.aligned.m16n8k16.row.col.f32.bf16.bf16.f32 "
        "{%0,%1,%2,%3}, {%4,%5,%6,%7}, {%8,%9}, {%0,%1,%2,%3};\n"
        : "+f"(c[0]), "+f"(c[1]), "+f"(c[2]), "+f"(c[3])
        : "r"(a0), "r"(a1), "r"(a2), "r"(a3), "r"(b0), "r"(b1));
}

__device__ __forceinline__ void cp16(void* smem_dst, const void* gsrc) {
    u32 u = (u32)__cvta_generic_to_shared(smem_dst);
    asm volatile("cp.async.cg.shared.global [%0], [%1], 16;\n" :: "r"(u), "l"(gsrc));
}

__device__ __forceinline__ void ldsm4(u32& r0, u32& r1, u32& r2, u32& r3, u32 addr) {
    asm volatile("ldmatrix.sync.aligned.m8n8.x4.shared.b16 {%0,%1,%2,%3}, [%4];"
                 : "=r"(r0), "=r"(r1), "=r"(r2), "=r"(r3) : "r"(addr));
}

// ---------------------------------------------------------------------------
// Fused fp32 -> split bf16 for 3 equal-size arrays
// ---------------------------------------------------------------------------
__global__ __launch_bounds__(256)
void split3_kernel(const float* __restrict__ x0, const float* __restrict__ x1,
                   const float* __restrict__ x2,
                   u16* __restrict__ h0a, u16* __restrict__ l0a,
                   u16* __restrict__ h1a, u16* __restrict__ l1a,
                   u16* __restrict__ h2a, u16* __restrict__ l2a, int n)
{
    const float* x;
    u16 *hp, *lp;
    if (blockIdx.y == 0)      { x = x0; hp = h0a; lp = l0a; }
    else if (blockIdx.y == 1) { x = x1; hp = h1a; lp = l1a; }
    else                      { x = x2; hp = h2a; lp = l2a; }

    int i = (blockIdx.x * blockDim.x + threadIdx.x) * 4;
    if (i >= n) return;
    float4 f = *reinterpret_cast<const float4*>(x + i);
    u16 h0,l0,h1,l1,h2,l2,h3,l3;
    split_bf16(f.x, h0, l0);
    split_bf16(f.y, h1, l1);
    split_bf16(f.z, h2, l2);
    split_bf16(f.w, h3, l3);
    *reinterpret_cast<uint2*>(hp + i) = make_uint2(pack2(h0,h1), pack2(h2,h3));
    *reinterpret_cast<uint2*>(lp + i) = make_uint2(pack2(l0,l1), pack2(l2,l3));
}

// ---------------------------------------------------------------------------
// Shared mainloop: pipelined bf16 NT GEMM, 3-term hi/lo split, LDSM loads.
// Block 128x128x32(bf16), 256 thr = 8 warps (4M x 2N), warp tile 32x64.
// 2-stage cp.async ring (80KB smem) -> 2 CTAs/SM. Term-major MMA order.
// ---------------------------------------------------------------------------
#define SMP   40                   // padded row stride (bf16): 80B, LDSM-conflict-free
#define ROWB  (SMP*2)              // 80 bytes
#define ARR_BYTES   (128*ROWB)     // 10240
#define STAGE_BYTES (4*ARR_BYTES)  // 40960
#define NSTAGE 2
#define DYNSMEM (NSTAGE*STAGE_BYTES)   // 81920 -> 2 CTAs/SM

__device__ __forceinline__ void issue_stage(char* base,
    const u16* __restrict__ Agh, const u16* __restrict__ Agl,
    const u16* __restrict__ Bgh, const u16* __restrict__ Bgl,
    int row0, int col0, int Kstride, int k0, int tid)
{
#pragma unroll
    for (int e = 0; e < 2; e++) {
        int idx = tid + (e << 8);        // 0..511
        int r = idx >> 2;                // 0..127
        int c = (idx & 3) << 3;          // 0,8,16,24 (bf16 elems)
        size_t offA = (size_t)(row0 + r) * Kstride + k0 + c;
        size_t offB = (size_t)(col0 + r) * Kstride + k0 + c;
        int sm = r * ROWB + c * 2;
        cp16(base + sm,                 Agh + offA);
        cp16(base + ARR_BYTES   + sm,   Agl + offA);
        cp16(base + 2*ARR_BYTES + sm,   Bgh + offB);
        cp16(base + 3*ARR_BYTES + sm,   Bgl + offB);
    }
}

__device__ __forceinline__ void gemm_main(char* smem, float acc[2][8][4],
    const u16* __restrict__ Agh, const u16* __restrict__ Agl,
    const u16* __restrict__ Bgh, const u16* __restrict__ Bgl,
    int row0, int col0, int Kstride, int kbeg, int Kpart, int tid)
{
    const int lane = tid & 31;
    const int wid  = tid >> 5;          // 0..7
    const int wm0  = (wid & 3) * 32;    // 4 warps along M
    const int wn0  = (wid >> 2) * 64;   // 2 warps along N

    const u32 aLane = (u32)((wm0 + (lane & 15)) * ROWB + ((lane >> 4) << 4));
    const u32 bLane = (u32)((wn0 + ((lane >> 4) << 3) + (lane & 7)) * ROWB
                            + ((lane & 8) << 1));
    const u32 smem_base = (u32)__cvta_generic_to_shared(smem);

#pragma unroll
    for (int i = 0; i < 2; i++)
#pragma unroll
        for (int j = 0; j < 8; j++)
#pragma unroll
            for (int t = 0; t < 4; t++) acc[i][j][t] = 0.0f;

    const int NIT = Kpart >> 5;

#pragma unroll
    for (int s = 0; s < NSTAGE; s++) {
        issue_stage(smem + s * STAGE_BYTES, Agh, Agl, Bgh, Bgl,
                    row0, col0, Kstride, kbeg + (s << 5), tid);
        asm volatile("cp.async.commit_group;\n" ::: "memory");
    }

    for (int it = 0; it < NIT; it++) {
        asm volatile("cp.async.wait_group 1;\n" ::: "memory");
        __syncthreads();

        const u32 stg = smem_base + (u32)((it & 1) * STAGE_BYTES);

#pragma unroll
        for (int ks = 0; ks < 2; ks++) {
            const u32 ko = ks << 5;   // 16 bf16 = 32 bytes
            u32 ah[2][4], al[2][4];
#pragma unroll
            for (int i = 0; i < 2; i++) {
                u32 aoff = stg + aLane + (u32)(i * 16 * ROWB) + ko;
                ldsm4(ah[i][0], ah[i][1], ah[i][2], ah[i][3], aoff);
                ldsm4(al[i][0], al[i][1], al[i][2], al[i][3], aoff + ARR_BYTES);
            }
#pragma unroll
            for (int half = 0; half < 2; half++) {
                u32 bh[4][2], bl[4][2];
#pragma unroll
                for (int p = 0; p < 2; p++) {
                    u32 boff = stg + 2*ARR_BYTES + bLane
                             + (u32)((half * 2 + p) * 16 * ROWB) + ko;
                    ldsm4(bh[2*p][0], bh[2*p][1], bh[2*p+1][0], bh[2*p+1][1], boff);
                    ldsm4(bl[2*p][0], bl[2*p][1], bl[2*p+1][0], bl[2*p+1][1],
                          boff + ARR_BYTES);
                }
                // term-major: consecutive MMAs to same acc are 8 apart
#pragma unroll
                for (int i = 0; i < 2; i++)
#pragma unroll
                    for (int j = 0; j < 4; j++)
                        mma16816(acc[i][half*4 + j],
                                 ah[i][0], ah[i][1], ah[i][2], ah[i][3],
                                 bh[j][0], bh[j][1]);
#pragma unroll
                for (int i = 0; i < 2; i++)
#pragma unroll
                    for (int j = 0; j < 4; j++)
                        mma16816(acc[i][half*4 + j],
                                 ah[i][0], ah[i][1], ah[i][2], ah[i][3],
                                 bl[j][0], bl[j][1]);
#pragma unroll
                for (int i = 0; i < 2; i++)
#pragma unroll
                    for (int j = 0; j < 4; j++)
                        mma16816(acc[i][half*4 + j],
                                 al[i][0], al[i][1], al[i][2], al[i][3],
                                 bh[j][0], bh[j][1]);
            }
        }
        __syncthreads();

        if (it + NSTAGE < NIT)
            issue_stage(smem + (it & 1) * STAGE_BYTES, Agh, Agl, Bgh, Bgl,
                        row0, col0, Kstride, kbeg + ((it + NSTAGE) << 5), tid);
        asm volatile("cp.async.commit_group;\n" ::: "memory");
    }
}

// ---------------------------------------------------------------------------
// fp32-out GEMM (scores / attnV partials), with split-K support
// ---------------------------------------------------------------------------
__global__ __launch_bounds__(256, 2)
void gemm_f32(const u16* __restrict__ Agh, const u16* __restrict__ Agl,
              const u16* __restrict__ Bgh, const u16* __restrict__ Bgl,
              float* __restrict__ Cf,
              int M, int N, int K, int splitk,
              long sA, long sB, long sC, float alpha)
{
    extern __shared__ char smem[];

    const int bzAll = blockIdx.z;
    const int bat   = bzAll / splitk;
    const int ksp   = bzAll - bat * splitk;
    const int Kpart = K / splitk;

    Agh += (size_t)bat * sA;  Agl += (size_t)bat * sA;
    Bgh += (size_t)bat * sB;  Bgl += (size_t)bat * sB;

    const int tid  = threadIdx.x;
    const int lane = tid & 31;
    const int wid  = tid >> 5;
    const int g    = lane >> 2;
    const int tg   = lane & 3;
    const int wm0  = (wid & 3) * 32;
    const int wn0  = (wid >> 2) * 64;
    const int row0 = blockIdx.y * 128;
    const int col0 = blockIdx.x * 128;

    float acc[2][8][4];
    gemm_main(smem, acc, Agh, Agl, Bgh, Bgl,
              row0, col0, K, ksp * Kpart, Kpart, tid);

    float* Cb = Cf + (size_t)bzAll * sC;
#pragma unroll
    for (int i = 0; i < 2; i++) {
        int r1 = row0 + wm0 + 16 * i + g;
        int r2 = r1 + 8;
#pragma unroll
        for (int j = 0; j < 8; j++) {
            int n = col0 + wn0 + 8 * j + 2 * tg;
            *reinterpret_cast<float2*>(Cb + (size_t)r1 * N + n) =
                make_float2(acc[i][j][0] * alpha, acc[i][j][1] * alpha);
            *reinterpret_cast<float2*>(Cb + (size_t)r2 * N + n) =
                make_float2(acc[i][j][2] * alpha, acc[i][j][3] * alpha);
        }
    }
}

// ---------------------------------------------------------------------------
// Fused Q/K/V projections in ONE launch: grid (DM/128, ROWS/128, 3)
// ---------------------------------------------------------------------------
struct ProjArgs {
    const u16* Ah[3]; const u16* Al[3];
    const u16* Bh[3]; const u16* Bl[3];
    const float* bias[3];
    u16* Ch[3]; u16* Cl[3];
};

__global__ __launch_bounds__(256, 2)
void proj3(ProjArgs pa)
{
    extern __shared__ char smem[];
    const int z = blockIdx.z;

    const int tid  = threadIdx.x;
    const int lane = tid & 31;
    const int wid  = tid >> 5;
    const int g    = lane >> 2;
    const int tg   = lane & 3;
    const int wm0  = (wid & 3) * 32;
    const int wn0  = (wid >> 2) * 64;
    const int row0 = blockIdx.y * 128;
    const int col0 = blockIdx.x * 128;

    float acc[2][8][4];
    gemm_main(smem, acc, pa.Ah[z], pa.Al[z], pa.Bh[z], pa.Bl[z],
              row0, col0, DM, 0, DM, tid);

    const float* bias = pa.bias[z];
    u16* Ch = pa.Ch[z];
    u16* Cl = pa.Cl[z];
    const int N = DM;

#pragma unroll
    for (int i = 0; i < 2; i++) {
        int r1 = row0 + wm0 + 16 * i + g;
        int r2 = r1 + 8;
#pragma unroll
        for (int j = 0; j < 8; j++) {
            int n = col0 + wn0 + 8 * j + 2 * tg;
            float b0 = bias[n], b1 = bias[n + 1];
            float v00 = acc[i][j][0] + b0;
            float v01 = acc[i][j][1] + b1;
            float v10 = acc[i][j][2] + b0;
            float v11 = acc[i][j][3] + b1;

            if (z != 2) {
                u16 h0,l0,h1,l1;
                split_bf16(v00, h0, l0); split_bf16(v01, h1, l1);
                *reinterpret_cast<u32*>(Ch + (size_t)r1 * N + n) = pack2(h0, h1);
                *reinterpret_cast<u32*>(Cl + (size_t)r1 * N + n) = pack2(l0, l1);
                split_bf16(v10, h0, l0); split_bf16(v11, h1, l1);
                *reinterpret_cast<u32*>(Ch + (size_t)r2 * N + n) = pack2(h0, h1);
                *reinterpret_cast<u32*>(Cl + (size_t)r2 * N + n) = pack2(l0, l1);
            } else {
                int   rr[2] = { r1, r2 };
                float vv[2][2] = { { v00, v01 }, { v10, v11 } };
#pragma unroll
                for (int t = 0; t < 2; t++) {
                    int m  = rr[t];
                    int b  = m >> 12;          // /SEQ
                    int mm = m & (SEQ - 1);
#pragma unroll
                    for (int u = 0; u < 2; u++) {
                        u16 h, l;
                        split_bf16(vv[t][u], h, l);
                        size_t idx = ((size_t)(b * DM + n + u)) * SEQ + mm;
                        Ch[idx] = h;
                        Cl[idx] = l;
                    }
                }
            }
        }
    }
}

// ---------------------------------------------------------------------------
// Reduce SPLITK partials: out[b][r] = sum_ks part[b*SPLITK+ks][r]
// ---------------------------------------------------------------------------
__global__ __launch_bounds__(256)
void reduce_splitk(const float* __restrict__ part, float* __restrict__ out)
{
    const size_t SD = (size_t)SEQ * DM;
    size_t idx = ((size_t)blockIdx.x * 256 + threadIdx.x) * 4;
    int b = (int)(idx / SD);
    size_t r = idx - (size_t)b * SD;
    const float* pb = part + (size_t)b * SPLITK * SD + r;
    float4 s0 = *reinterpret_cast<const float4*>(pb);
    float4 s1 = *reinterpret_cast<const float4*>(pb + SD);
    float4 s2 = *reinterpret_cast<const float4*>(pb + 2*SD);
    float4 s3 = *reinterpret_cast<const float4*>(pb + 3*SD);
    float4 o;
    o.x = (s0.x + s1.x) + (s2.x + s3.x);
    o.y = (s0.y + s1.y) + (s2.y + s3.y);
    o.z = (s0.z + s1.z) + (s2.z + s3.z);
    o.w = (s0.w + s1.w) + (s2.w + s3.w);
    *reinterpret_cast<float4*>(out + idx) = o;
}

// ---------------------------------------------------------------------------
// ONLINE row softmax: single fused (max,sum) reduction, exp2-based.
// fp32 scores row -> split bf16 attention row. 256 thr, 16 elems/thread.
// ---------------------------------------------------------------------------
__global__ __launch_bounds__(256)
void softmax_split(const float* __restrict__ scores,
                   u16* __restrict__ ah, u16* __restrict__ al)
{
    const size_t roff = (size_t)blockIdx.x * SEQ;
    const float* p = scores + roff;
    const int tid  = threadIdx.x;
    const int lane = tid & 31;
    const int wrp  = tid >> 5;

    float v[16];
#pragma unroll
    for (int i = 0; i < 4; i++) {
        float4 f = *reinterpret_cast<const float4*>(p + i * 1024 + tid * 4);
        v[i*4+0] = f.x; v[i*4+1] = f.y; v[i*4+2] = f.z; v[i*4+3] = f.w;
    }

    // Thread-local max, then local exp2 sums (store e_j in v[])
    float m = v[0];
#pragma unroll
    for (int i = 1; i < 16; i++) m = fmaxf(m, v[i]);
    const float mloc = m;

    float s = 0.0f;
#pragma unroll
    for (int i = 0; i < 16; i++) {
        v[i] = exp2f((v[i] - mloc) * L2E);
        s += v[i];
    }

    // Fused (m, s) warp reduction: m'=max, s' = s1*2^((m1-m')L2E) + s2*...
#pragma unroll
    for (int o = 16; o > 0; o >>= 1) {
        float mo = __shfl_xor_sync(0xffffffffu, m, o);
        float so = __shfl_xor_sync(0xffffffffu, s, o);
        float mn = fmaxf(m, mo);
        s = s * exp2f((m - mn) * L2E) + so * exp2f((mo - mn) * L2E);
        m = mn;
    }

    __shared__ float redM[8], redS[8], fin[2];
    if (lane == 0) { redM[wrp] = m; redS[wrp] = s; }
    __syncthreads();
    if (tid < 32) {
        float mm = (tid < 8) ? redM[tid] : -INFINITY;
        float ss = (tid < 8) ? redS[tid] : 0.0f;
#pragma unroll
        for (int o = 4; o > 0; o >>= 1) {
            float mo = __shfl_xor_sync(0xffffffffu, mm, o);
            float so = __shfl_xor_sync(0xffffffffu, ss, o);
            float mn = fmaxf(mm, mo);
            ss = ss * exp2f((mm - mn) * L2E) + so * exp2f((mo - mn) * L2E);
            mm = mn;
        }
        if (tid == 0) { fin[0] = mm; fin[1] = 1.0f / ss; }
    }
    __syncthreads();

    // p_j = e_j * 2^((mloc - m_tot)*L2E) / s_tot
    const float scalef = exp2f((mloc - fin[0]) * L2E) * fin[1];

#pragma unroll
    for (int i = 0; i < 4; i++) {
        u16 h[4], l[4];
#pragma unroll
        for (int j = 0; j < 4; j++)
            split_bf16(v[i*4+j] * scalef, h[j], l[j]);
        *reinterpret_cast<uint2*>(ah + roff + i * 1024 + tid * 4) =
            make_uint2(pack2(h[0], h[1]), pack2(h[2], h[3]));
        *reinterpret_cast<uint2*>(al + roff + i * 1024 + tid * 4) =
            make_uint2(pack2(l[0], l[1]), pack2(l[2], l[3]));
    }
}

// ---------------------------------------------------------------------------
extern "C" void kernel_launch(void* const* d_in, const int* in_sizes, int n_in,
                              void* d_out, int out_size)
{
    const float* Q   = (const float*)d_in[0];
    const float* K   = (const float*)d_in[1];
    const float* V   = (const float*)d_in[2];
    const float* W_q = (const float*)d_in[3];
    const float* b_q = (const float*)d_in[4];
    const float* W_k = (const float*)d_in[5];
    const float* b_k = (const float*)d_in[6];
    const float* W_v = (const float*)d_in[7];
    const float* b_v = (const float*)d_in[8];
    float* out = (float*)d_out;

    u16 *Qh,*Ql,*Kh,*Kl,*Vh,*Vl, *Wqh,*Wql,*Wkh,*Wkl,*Wvh,*Wvl;
    u16 *qh,*ql,*kh,*kl,*vth,*vtl,*ah,*al;
    float *s, *part;
    cudaGetSymbolAddress((void**)&Qh, g_Qh);   cudaGetSymbolAddress((void**)&Ql, g_Ql);
    cudaGetSymbolAddress((void**)&Kh, g_Kh);   cudaGetSymbolAddress((void**)&Kl, g_Kl);
    cudaGetSymbolAddress((void**)&Vh, g_Vh);   cudaGetSymbolAddress((void**)&Vl, g_Vl);
    cudaGetSymbolAddress((void**)&Wqh, g_Wqh); cudaGetSymbolAddress((void**)&Wql, g_Wql);
    cudaGetSymbolAddress((void**)&Wkh, g_Wkh); cudaGetSymbolAddress((void**)&Wkl, g_Wkl);
    cudaGetSymbolAddress((void**)&Wvh, g_Wvh); cudaGetSymbolAddress((void**)&Wvl, g_Wvl);
    cudaGetSymbolAddress((void**)&qh, g_qh);   cudaGetSymbolAddress((void**)&ql, g_ql);
    cudaGetSymbolAddress((void**)&kh, g_kh);   cudaGetSymbolAddress((void**)&kl, g_kl);
    cudaGetSymbolAddress((void**)&vth, g_vth); cudaGetSymbolAddress((void**)&vtl, g_vtl);
    cudaGetSymbolAddress((void**)&ah, g_ah);   cudaGetSymbolAddress((void**)&al, g_al);
    cudaGetSymbolAddress((void**)&s, g_s);     cudaGetSymbolAddress((void**)&part, g_part);

    cudaFuncSetAttribute(gemm_f32, cudaFuncAttributeMaxDynamicSharedMemorySize, DYNSMEM);
    cudaFuncSetAttribute(proj3,    cudaFuncAttributeMaxDynamicSharedMemorySize, DYNSMEM);

    const float scale = 1.0f / sqrtf((float)DM);
    dim3 blk(256);

    const int n1 = ROWS * DM;
    const int n2 = DM * DM;
    split3_kernel<<<dim3(n1/1024, 3), blk>>>(Q, K, V,
        Qh, Ql, Kh, Kl, Vh, Vl, n1);
    split3_kernel<<<dim3(n2/1024, 3), blk>>>(W_q, W_k, W_v,
        Wqh, Wql, Wkh, Wkl, Wvh, Wvl, n2);

    // Fused projections (one launch, 768 CTAs)
    {
        ProjArgs pa;
        pa.Ah[0]=Qh; pa.Al[0]=Ql; pa.Bh[0]=Wqh; pa.Bl[0]=Wql; pa.bias[0]=b_q;
        pa.Ch[0]=qh; pa.Cl[0]=ql;
        pa.Ah[1]=Kh; pa.Al[1]=Kl; pa.Bh[1]=Wkh; pa.Bl[1]=Wkl; pa.bias[1]=b_k;
        pa.Ch[1]=kh; pa.Cl[1]=kl;
        pa.Ah[2]=Vh; pa.Al[2]=Vl; pa.Bh[2]=Wvh; pa.Bl[2]=Wvl; pa.bias[2]=b_v;
        pa.Ch[2]=vth; pa.Cl[2]=vtl;
        dim3 gp(DM/128, ROWS/128, 3);
        proj3<<<gp, blk, DYNSMEM>>>(pa);
    }

    // Scores (NT, per batch): s = scale * q @ k^T, M=N=4096, K=512
    {
        dim3 gs(SEQ/128, SEQ/128, BATCH);
        gemm_f32<<<gs, blk, DYNSMEM>>>(qh, ql, kh, kl,
            s, SEQ, SEQ, DM, 1,
            (long)SEQ*DM, (long)SEQ*DM, (long)SEQ*SEQ, scale);
    }

    // Online softmax -> split bf16 attention
    softmax_split<<<ROWS, blk>>>(s, ah, al);

    // Output: out = attn @ v via vT, split-K=4 partials then reduce
    {
        dim3 go(DM/128, SEQ/128, BATCH * SPLITK);   // 1024 CTAs, K=1024 each
        gemm_f32<<<go, blk, DYNSMEM>>>(ah, al, vth, vtl,
            part, SEQ, DM, SEQ, SPLITK,
            (long)SEQ*SEQ, (long)DM*SEQ, (long)SEQ*DM, 1.0f);
        reduce_splitk<<<(ROWS*DM)/1024, blk>>>(part, out);
    }
}

// round 13
// speedup vs baseline: 1.2279x; 1.1148x over previous
#include <cuda_runtime.h>
#include <cuda_fp16.h>
#include <math.h>

#define BATCH 2
#define SEQ   4096
#define DM    512
#define ROWS  (BATCH*SEQ)   // 8192
#define SPLITK 4
#define L2E   1.4426950408889634f

typedef unsigned short u16;
typedef unsigned int   u32;

// ---------------------------------------------------------------------------
// Device scratch (allocation-free rule: __device__ globals)
// ---------------------------------------------------------------------------
__device__ u16 g_Qh[(size_t)ROWS*DM], g_Ql[(size_t)ROWS*DM];
__device__ u16 g_Kh[(size_t)ROWS*DM], g_Kl[(size_t)ROWS*DM];
__device__ u16 g_Vh[(size_t)ROWS*DM], g_Vl[(size_t)ROWS*DM];
__device__ u16 g_Wqh[DM*DM], g_Wql[DM*DM];
__device__ u16 g_Wkh[DM*DM], g_Wkl[DM*DM];
__device__ u16 g_Wvh[DM*DM], g_Wvl[DM*DM];
__device__ u16 g_qh[(size_t)ROWS*DM], g_ql[(size_t)ROWS*DM];
__device__ u16 g_kh[(size_t)ROWS*DM], g_kl[(size_t)ROWS*DM];
__device__ u16 g_vth[(size_t)BATCH*DM*SEQ];          // V^T, single fp16
__device__ float g_s[(size_t)BATCH*SEQ*SEQ];
__device__ u16 g_ah[(size_t)BATCH*SEQ*SEQ], g_al[(size_t)BATCH*SEQ*SEQ];
__device__ float g_part[(size_t)BATCH*SPLITK*SEQ*DM];   // attnV split-K partials

// ---------------------------------------------------------------------------
// fp16 helpers
// ---------------------------------------------------------------------------
__device__ __forceinline__ u16 f2h(float x) {
    return __half_as_ushort(__float2half_rn(x));
}
__device__ __forceinline__ float h2f(u16 u) {
    return __half2float(__ushort_as_half(u));
}
__device__ __forceinline__ void split_f16(float x, u16& hi, u16& lo) {
    hi = f2h(x);
    lo = f2h(x - h2f(hi));
}
__device__ __forceinline__ unsigned pack2(u16 a, u16 b) {
    return (unsigned)a | ((unsigned)b << 16);
}

__device__ __forceinline__ void mma16816(float c[4],
                                         u32 a0, u32 a1, u32 a2, u32 a3,
                                         u32 b0, u32 b1)
{
    asm volatile(
        "mma.sync.aligned.m16n8k16.row.col.f32.f16.f16.f32 "
        "{%0,%1,%2,%3}, {%4,%5,%6,%7}, {%8,%9}, {%0,%1,%2,%3};\n"
        : "+f"(c[0]), "+f"(c[1]), "+f"(c[2]), "+f"(c[3])
        : "r"(a0), "r"(a1), "r"(a2), "r"(a3), "r"(b0), "r"(b1));
}

__device__ __forceinline__ void cp16(void* smem_dst, const void* gsrc) {
    u32 u = (u32)__cvta_generic_to_shared(smem_dst);
    asm volatile("cp.async.cg.shared.global [%0], [%1], 16;\n" :: "r"(u), "l"(gsrc));
}

__device__ __forceinline__ void ldsm4(u32& r0, u32& r1, u32& r2, u32& r3, u32 addr) {
    asm volatile("ldmatrix.sync.aligned.m8n8.x4.shared.b16 {%0,%1,%2,%3}, [%4];"
                 : "=r"(r0), "=r"(r1), "=r"(r2), "=r"(r3) : "r"(addr));
}

// ---------------------------------------------------------------------------
// Fused fp32 -> split fp16 for 3 equal-size arrays
// ---------------------------------------------------------------------------
__global__ __launch_bounds__(256)
void split3_kernel(const float* __restrict__ x0, const float* __restrict__ x1,
                   const float* __restrict__ x2,
                   u16* __restrict__ h0a, u16* __restrict__ l0a,
                   u16* __restrict__ h1a, u16* __restrict__ l1a,
                   u16* __restrict__ h2a, u16* __restrict__ l2a, int n)
{
    const float* x;
    u16 *hp, *lp;
    if (blockIdx.y == 0)      { x = x0; hp = h0a; lp = l0a; }
    else if (blockIdx.y == 1) { x = x1; hp = h1a; lp = l1a; }
    else                      { x = x2; hp = h2a; lp = l2a; }

    int i = (blockIdx.x * blockDim.x + threadIdx.x) * 4;
    if (i >= n) return;
    float4 f = *reinterpret_cast<const float4*>(x + i);
    u16 h0,l0,h1,l1,h2,l2,h3,l3;
    split_f16(f.x, h0, l0);
    split_f16(f.y, h1, l1);
    split_f16(f.z, h2, l2);
    split_f16(f.w, h3, l3);
    *reinterpret_cast<uint2*>(hp + i) = make_uint2(pack2(h0,h1), pack2(h2,h3));
    *reinterpret_cast<uint2*>(lp + i) = make_uint2(pack2(l0,l1), pack2(l2,l3));
}

// ---------------------------------------------------------------------------
// Shared 3-term mainloop (projections / scores)
// Block 128x128x32(f16), 256 thr = 8 warps (4M x 2N), warp tile 32x64.
// 2-stage cp.async ring (80KB smem) -> 2 CTAs/SM. Term-major MMA order.
// ---------------------------------------------------------------------------
#define SMP   40
#define ROWB  (SMP*2)              // 80 bytes
#define ARR_BYTES   (128*ROWB)     // 10240
#define STAGE_BYTES (4*ARR_BYTES)  // 40960
#define NSTAGE 2
#define DYNSMEM (NSTAGE*STAGE_BYTES)   // 81920 -> 2 CTAs/SM

__device__ __forceinline__ void issue_stage(char* base,
    const u16* __restrict__ Agh, const u16* __restrict__ Agl,
    const u16* __restrict__ Bgh, const u16* __restrict__ Bgl,
    int row0, int col0, int Kstride, int k0, int tid)
{
#pragma unroll
    for (int e = 0; e < 2; e++) {
        int idx = tid + (e << 8);        // 0..511
        int r = idx >> 2;                // 0..127
        int c = (idx & 3) << 3;          // 0,8,16,24
        size_t offA = (size_t)(row0 + r) * Kstride + k0 + c;
        size_t offB = (size_t)(col0 + r) * Kstride + k0 + c;
        int sm = r * ROWB + c * 2;
        cp16(base + sm,                 Agh + offA);
        cp16(base + ARR_BYTES   + sm,   Agl + offA);
        cp16(base + 2*ARR_BYTES + sm,   Bgh + offB);
        cp16(base + 3*ARR_BYTES + sm,   Bgl + offB);
    }
}

__device__ __forceinline__ void gemm_main(char* smem, float acc[2][8][4],
    const u16* __restrict__ Agh, const u16* __restrict__ Agl,
    const u16* __restrict__ Bgh, const u16* __restrict__ Bgl,
    int row0, int col0, int Kstride, int kbeg, int Kpart, int tid)
{
    const int lane = tid & 31;
    const int wid  = tid >> 5;
    const int wm0  = (wid & 3) * 32;
    const int wn0  = (wid >> 2) * 64;

    const u32 aLane = (u32)((wm0 + (lane & 15)) * ROWB + ((lane >> 4) << 4));
    const u32 bLane = (u32)((wn0 + ((lane >> 4) << 3) + (lane & 7)) * ROWB
                            + ((lane & 8) << 1));
    const u32 smem_base = (u32)__cvta_generic_to_shared(smem);

#pragma unroll
    for (int i = 0; i < 2; i++)
#pragma unroll
        for (int j = 0; j < 8; j++)
#pragma unroll
            for (int t = 0; t < 4; t++) acc[i][j][t] = 0.0f;

    const int NIT = Kpart >> 5;

#pragma unroll
    for (int s = 0; s < NSTAGE; s++) {
        issue_stage(smem + s * STAGE_BYTES, Agh, Agl, Bgh, Bgl,
                    row0, col0, Kstride, kbeg + (s << 5), tid);
        asm volatile("cp.async.commit_group;\n" ::: "memory");
    }

    for (int it = 0; it < NIT; it++) {
        asm volatile("cp.async.wait_group 1;\n" ::: "memory");
        __syncthreads();

        const u32 stg = smem_base + (u32)((it & 1) * STAGE_BYTES);

#pragma unroll
        for (int ks = 0; ks < 2; ks++) {
            const u32 ko = ks << 5;
            u32 ah[2][4], al[2][4];
#pragma unroll
            for (int i = 0; i < 2; i++) {
                u32 aoff = stg + aLane + (u32)(i * 16 * ROWB) + ko;
                ldsm4(ah[i][0], ah[i][1], ah[i][2], ah[i][3], aoff);
                ldsm4(al[i][0], al[i][1], al[i][2], al[i][3], aoff + ARR_BYTES);
            }
#pragma unroll
            for (int half = 0; half < 2; half++) {
                u32 bh[4][2], bl[4][2];
#pragma unroll
                for (int p = 0; p < 2; p++) {
                    u32 boff = stg + 2*ARR_BYTES + bLane
                             + (u32)((half * 2 + p) * 16 * ROWB) + ko;
                    ldsm4(bh[2*p][0], bh[2*p][1], bh[2*p+1][0], bh[2*p+1][1], boff);
                    ldsm4(bl[2*p][0], bl[2*p][1], bl[2*p+1][0], bl[2*p+1][1],
                          boff + ARR_BYTES);
                }
#pragma unroll
                for (int i = 0; i < 2; i++)
#pragma unroll
                    for (int j = 0; j < 4; j++)
                        mma16816(acc[i][half*4 + j],
                                 ah[i][0], ah[i][1], ah[i][2], ah[i][3],
                                 bh[j][0], bh[j][1]);
#pragma unroll
                for (int i = 0; i < 2; i++)
#pragma unroll
                    for (int j = 0; j < 4; j++)
                        mma16816(acc[i][half*4 + j],
                                 ah[i][0], ah[i][1], ah[i][2], ah[i][3],
                                 bl[j][0], bl[j][1]);
#pragma unroll
                for (int i = 0; i < 2; i++)
#pragma unroll
                    for (int j = 0; j < 4; j++)
                        mma16816(acc[i][half*4 + j],
                                 al[i][0], al[i][1], al[i][2], al[i][3],
                                 bh[j][0], bh[j][1]);
            }
        }
        __syncthreads();

        if (it + NSTAGE < NIT)
            issue_stage(smem + (it & 1) * STAGE_BYTES, Agh, Agl, Bgh, Bgl,
                        row0, col0, Kstride, kbeg + ((it + NSTAGE) << 5), tid);
        asm volatile("cp.async.commit_group;\n" ::: "memory");
    }
}

// ---------------------------------------------------------------------------
// Scores GEMM: 3-term, fp32 out
// ---------------------------------------------------------------------------
__global__ __launch_bounds__(256, 2)
void gemm_scores(const u16* __restrict__ Agh, const u16* __restrict__ Agl,
                 const u16* __restrict__ Bgh, const u16* __restrict__ Bgl,
                 float* __restrict__ Cf,
                 int M, int N, int K,
                 long sA, long sB, long sC, float alpha)
{
    extern __shared__ char smem[];

    const int bz = blockIdx.z;
    Agh += (size_t)bz * sA;  Agl += (size_t)bz * sA;
    Bgh += (size_t)bz * sB;  Bgl += (size_t)bz * sB;

    const int tid  = threadIdx.x;
    const int lane = tid & 31;
    const int wid  = tid >> 5;
    const int g    = lane >> 2;
    const int tg   = lane & 3;
    const int wm0  = (wid & 3) * 32;
    const int wn0  = (wid >> 2) * 64;
    const int row0 = blockIdx.y * 128;
    const int col0 = blockIdx.x * 128;

    float acc[2][8][4];
    gemm_main(smem, acc, Agh, Agl, Bgh, Bgl, row0, col0, K, 0, K, tid);

    float* Cb = Cf + (size_t)bz * sC;
#pragma unroll
    for (int i = 0; i < 2; i++) {
        int r1 = row0 + wm0 + 16 * i + g;
        int r2 = r1 + 8;
#pragma unroll
        for (int j = 0; j < 8; j++) {
            int n = col0 + wn0 + 8 * j + 2 * tg;
            *reinterpret_cast<float2*>(Cb + (size_t)r1 * N + n) =
                make_float2(acc[i][j][0] * alpha, acc[i][j][1] * alpha);
            *reinterpret_cast<float2*>(Cb + (size_t)r2 * N + n) =
                make_float2(acc[i][j][2] * alpha, acc[i][j][3] * alpha);
        }
    }
}

// ---------------------------------------------------------------------------
// Fused Q/K/V projections (3-term): grid (DM/128, ROWS/128, 3)
// z in {0,1} -> split fp16 out (+bias); z==2 -> SINGLE fp16 transposed out
// ---------------------------------------------------------------------------
struct ProjArgs {
    const u16* Ah[3]; const u16* Al[3];
    const u16* Bh[3]; const u16* Bl[3];
    const float* bias[3];
    u16* Ch[3]; u16* Cl[3];
};

__global__ __launch_bounds__(256, 2)
void proj3(ProjArgs pa)
{
    extern __shared__ char smem[];
    const int z = blockIdx.z;

    const int tid  = threadIdx.x;
    const int lane = tid & 31;
    const int wid  = tid >> 5;
    const int g    = lane >> 2;
    const int tg   = lane & 3;
    const int wm0  = (wid & 3) * 32;
    const int wn0  = (wid >> 2) * 64;
    const int row0 = blockIdx.y * 128;
    const int col0 = blockIdx.x * 128;

    float acc[2][8][4];
    gemm_main(smem, acc, pa.Ah[z], pa.Al[z], pa.Bh[z], pa.Bl[z],
              row0, col0, DM, 0, DM, tid);

    const float* bias = pa.bias[z];
    u16* Ch = pa.Ch[z];
    u16* Cl = pa.Cl[z];
    const int N = DM;

#pragma unroll
    for (int i = 0; i < 2; i++) {
        int r1 = row0 + wm0 + 16 * i + g;
        int r2 = r1 + 8;
#pragma unroll
        for (int j = 0; j < 8; j++) {
            int n = col0 + wn0 + 8 * j + 2 * tg;
            float b0 = bias[n], b1 = bias[n + 1];
            float v00 = acc[i][j][0] + b0;
            float v01 = acc[i][j][1] + b1;
            float v10 = acc[i][j][2] + b0;
            float v11 = acc[i][j][3] + b1;

            if (z != 2) {
                u16 h0,l0,h1,l1;
                split_f16(v00, h0, l0); split_f16(v01, h1, l1);
                *reinterpret_cast<u32*>(Ch + (size_t)r1 * N + n) = pack2(h0, h1);
                *reinterpret_cast<u32*>(Cl + (size_t)r1 * N + n) = pack2(l0, l1);
                split_f16(v10, h0, l0); split_f16(v11, h1, l1);
                *reinterpret_cast<u32*>(Ch + (size_t)r2 * N + n) = pack2(h0, h1);
                *reinterpret_cast<u32*>(Cl + (size_t)r2 * N + n) = pack2(l0, l1);
            } else {
                // single fp16, transposed per-batch [b][n][m]
                int   rr[2] = { r1, r2 };
                float vv[2][2] = { { v00, v01 }, { v10, v11 } };
#pragma unroll
                for (int t = 0; t < 2; t++) {
                    int m  = rr[t];
                    int b  = m >> 12;
                    int mm = m & (SEQ - 1);
#pragma unroll
                    for (int u = 0; u < 2; u++) {
                        size_t idx = ((size_t)(b * DM + n + u)) * SEQ + mm;
                        Ch[idx] = f2h(vv[t][u]);
                    }
                }
            }
        }
    }
}

// ---------------------------------------------------------------------------
// attnV GEMM: 2-term (A split fp16 x B single fp16), split-K, fp32 partials
// Stage = Ah, Al, Bh (3 arrays, 30KB); 2 stages = 60KB -> 2 CTAs/SM
// ---------------------------------------------------------------------------
#define AV_STAGE (3*ARR_BYTES)     // 30720
#define DYNSMEM_AV (2*AV_STAGE)    // 61440

__device__ __forceinline__ void issue_stage_av(char* base,
    const u16* __restrict__ Agh, const u16* __restrict__ Agl,
    const u16* __restrict__ Bgh,
    int row0, int col0, int Kstride, int k0, int tid)
{
#pragma unroll
    for (int e = 0; e < 2; e++) {
        int idx = tid + (e << 8);
        int r = idx >> 2;
        int c = (idx & 3) << 3;
        size_t offA = (size_t)(row0 + r) * Kstride + k0 + c;
        size_t offB = (size_t)(col0 + r) * Kstride + k0 + c;
        int sm = r * ROWB + c * 2;
        cp16(base + sm,               Agh + offA);
        cp16(base + ARR_BYTES + sm,   Agl + offA);
        cp16(base + 2*ARR_BYTES + sm, Bgh + offB);
    }
}

__global__ __launch_bounds__(256, 2)
void gemm_av(const u16* __restrict__ Agh, const u16* __restrict__ Agl,
             const u16* __restrict__ Bgh,
             float* __restrict__ Cf,
             int M, int N, int K, int splitk,
             long sA, long sB, long sC)
{
    extern __shared__ char smem[];

    const int bzAll = blockIdx.z;
    const int bat   = bzAll / splitk;
    const int ksp   = bzAll - bat * splitk;
    const int Kpart = K / splitk;
    const int kbeg  = ksp * Kpart;

    Agh += (size_t)bat * sA;  Agl += (size_t)bat * sA;
    Bgh += (size_t)bat * sB;

    const int tid  = threadIdx.x;
    const int lane = tid & 31;
    const int wid  = tid >> 5;
    const int g    = lane >> 2;
    const int tg   = lane & 3;
    const int wm0  = (wid & 3) * 32;
    const int wn0  = (wid >> 2) * 64;
    const int row0 = blockIdx.y * 128;
    const int col0 = blockIdx.x * 128;

    const u32 aLane = (u32)((wm0 + (lane & 15)) * ROWB + ((lane >> 4) << 4));
    const u32 bLane = (u32)((wn0 + ((lane >> 4) << 3) + (lane & 7)) * ROWB
                            + ((lane & 8) << 1));
    const u32 smem_base = (u32)__cvta_generic_to_shared(smem);

    float acc[2][8][4];
#pragma unroll
    for (int i = 0; i < 2; i++)
#pragma unroll
        for (int j = 0; j < 8; j++)
#pragma unroll
            for (int t = 0; t < 4; t++) acc[i][j][t] = 0.0f;

    const int NIT = Kpart >> 5;

#pragma unroll
    for (int s = 0; s < 2; s++) {
        issue_stage_av(smem + s * AV_STAGE, Agh, Agl, Bgh,
                       row0, col0, K, kbeg + (s << 5), tid);
        asm volatile("cp.async.commit_group;\n" ::: "memory");
    }

    for (int it = 0; it < NIT; it++) {
        asm volatile("cp.async.wait_group 1;\n" ::: "memory");
        __syncthreads();

        const u32 stg = smem_base + (u32)((it & 1) * AV_STAGE);

#pragma unroll
        for (int ks = 0; ks < 2; ks++) {
            const u32 ko = ks << 5;
            u32 ah[2][4], al[2][4];
#pragma unroll
            for (int i = 0; i < 2; i++) {
                u32 aoff = stg + aLane + (u32)(i * 16 * ROWB) + ko;
                ldsm4(ah[i][0], ah[i][1], ah[i][2], ah[i][3], aoff);
                ldsm4(al[i][0], al[i][1], al[i][2], al[i][3], aoff + ARR_BYTES);
            }
#pragma unroll
            for (int half = 0; half < 2; half++) {
                u32 bh[4][2];
#pragma unroll
                for (int p = 0; p < 2; p++) {
                    u32 boff = stg + 2*ARR_BYTES + bLane
                             + (u32)((half * 2 + p) * 16 * ROWB) + ko;
                    ldsm4(bh[2*p][0], bh[2*p][1], bh[2*p+1][0], bh[2*p+1][1], boff);
                }
#pragma unroll
                for (int i = 0; i < 2; i++)
#pragma unroll
                    for (int j = 0; j < 4; j++)
                        mma16816(acc[i][half*4 + j],
                                 ah[i][0], ah[i][1], ah[i][2], ah[i][3],
                                 bh[j][0], bh[j][1]);
#pragma unroll
                for (int i = 0; i < 2; i++)
#pragma unroll
                    for (int j = 0; j < 4; j++)
                        mma16816(acc[i][half*4 + j],
                                 al[i][0], al[i][1], al[i][2], al[i][3],
                                 bh[j][0], bh[j][1]);
            }
        }
        __syncthreads();

        if (it + 2 < NIT)
            issue_stage_av(smem + (it & 1) * AV_STAGE, Agh, Agl, Bgh,
                           row0, col0, K, kbeg + ((it + 2) << 5), tid);
        asm volatile("cp.async.commit_group;\n" ::: "memory");
    }

    float* Cb = Cf + (size_t)bzAll * sC;
#pragma unroll
    for (int i = 0; i < 2; i++) {
        int r1 = row0 + wm0 + 16 * i + g;
        int r2 = r1 + 8;
#pragma unroll
        for (int j = 0; j < 8; j++) {
            int n = col0 + wn0 + 8 * j + 2 * tg;
            *reinterpret_cast<float2*>(Cb + (size_t)r1 * N + n) =
                make_float2(acc[i][j][0], acc[i][j][1]);
            *reinterpret_cast<float2*>(Cb + (size_t)r2 * N + n) =
                make_float2(acc[i][j][2], acc[i][j][3]);
        }
    }
}

// ---------------------------------------------------------------------------
// Reduce SPLITK partials
// ---------------------------------------------------------------------------
__global__ __launch_bounds__(256)
void reduce_splitk(const float* __restrict__ part, float* __restrict__ out)
{
    const size_t SD = (size_t)SEQ * DM;
    size_t idx = ((size_t)blockIdx.x * 256 + threadIdx.x) * 4;
    int b = (int)(idx / SD);
    size_t r = idx - (size_t)b * SD;
    const float* pb = part + (size_t)b * SPLITK * SD + r;
    float4 s0 = *reinterpret_cast<const float4*>(pb);
    float4 s1 = *reinterpret_cast<const float4*>(pb + SD);
    float4 s2 = *reinterpret_cast<const float4*>(pb + 2*SD);
    float4 s3 = *reinterpret_cast<const float4*>(pb + 3*SD);
    float4 o;
    o.x = (s0.x + s1.x) + (s2.x + s3.x);
    o.y = (s0.y + s1.y) + (s2.y + s3.y);
    o.z = (s0.z + s1.z) + (s2.z + s3.z);
    o.w = (s0.w + s1.w) + (s2.w + s3.w);
    *reinterpret_cast<float4*>(out + idx) = o;
}

// ---------------------------------------------------------------------------
// ONLINE row softmax -> split fp16 attention row
// ---------------------------------------------------------------------------
__global__ __launch_bounds__(256)
void softmax_split(const float* __restrict__ scores,
                   u16* __restrict__ ah, u16* __restrict__ al)
{
    const size_t roff = (size_t)blockIdx.x * SEQ;
    const float* p = scores + roff;
    const int tid  = threadIdx.x;
    const int lane = tid & 31;
    const int wrp  = tid >> 5;

    float v[16];
#pragma unroll
    for (int i = 0; i < 4; i++) {
        float4 f = *reinterpret_cast<const float4*>(p + i * 1024 + tid * 4);
        v[i*4+0] = f.x; v[i*4+1] = f.y; v[i*4+2] = f.z; v[i*4+3] = f.w;
    }

    float m = v[0];
#pragma unroll
    for (int i = 1; i < 16; i++) m = fmaxf(m, v[i]);
    const float mloc = m;

    float s = 0.0f;
#pragma unroll
    for (int i = 0; i < 16; i++) {
        v[i] = exp2f((v[i] - mloc) * L2E);
        s += v[i];
    }

#pragma unroll
    for (int o = 16; o > 0; o >>= 1) {
        float mo = __shfl_xor_sync(0xffffffffu, m, o);
        float so = __shfl_xor_sync(0xffffffffu, s, o);
        float mn = fmaxf(m, mo);
        s = s * exp2f((m - mn) * L2E) + so * exp2f((mo - mn) * L2E);
        m = mn;
    }

    __shared__ float redM[8], redS[8], fin[2];
    if (lane == 0) { redM[wrp] = m; redS[wrp] = s; }
    __syncthreads();
    if (tid < 32) {
        float mm = (tid < 8) ? redM[tid] : -INFINITY;
        float ss = (tid < 8) ? redS[tid] : 0.0f;
#pragma unroll
        for (int o = 4; o > 0; o >>= 1) {
            float mo = __shfl_xor_sync(0xffffffffu, mm, o);
            float so = __shfl_xor_sync(0xffffffffu, ss, o);
            float mn = fmaxf(mm, mo);
            ss = ss * exp2f((mm - mn) * L2E) + so * exp2f((mo - mn) * L2E);
            mm = mn;
        }
        if (tid == 0) { fin[0] = mm; fin[1] = 1.0f / ss; }
    }
    __syncthreads();

    const float scalef = exp2f((mloc - fin[0]) * L2E) * fin[1];

#pragma unroll
    for (int i = 0; i < 4; i++) {
        u16 h[4], l[4];
#pragma unroll
        for (int j = 0; j < 4; j++)
            split_f16(v[i*4+j] * scalef, h[j], l[j]);
        *reinterpret_cast<uint2*>(ah + roff + i * 1024 + tid * 4) =
            make_uint2(pack2(h[0], h[1]), pack2(h[2], h[3]));
        *reinterpret_cast<uint2*>(al + roff + i * 1024 + tid * 4) =
            make_uint2(pack2(l[0], l[1]), pack2(l[2], l[3]));
    }
}

// ---------------------------------------------------------------------------
extern "C" void kernel_launch(void* const* d_in, const int* in_sizes, int n_in,
                              void* d_out, int out_size)
{
    const float* Q   = (const float*)d_in[0];
    const float* K   = (const float*)d_in[1];
    const float* V   = (const float*)d_in[2];
    const float* W_q = (const float*)d_in[3];
    const float* b_q = (const float*)d_in[4];
    const float* W_k = (const float*)d_in[5];
    const float* b_k = (const float*)d_in[6];
    const float* W_v = (const float*)d_in[7];
    const float* b_v = (const float*)d_in[8];
    float* out = (float*)d_out;

    u16 *Qh,*Ql,*Kh,*Kl,*Vh,*Vl, *Wqh,*Wql,*Wkh,*Wkl,*Wvh,*Wvl;
    u16 *qh,*ql,*kh,*kl,*vth,*ah,*al;
    float *s, *part;
    cudaGetSymbolAddress((void**)&Qh, g_Qh);   cudaGetSymbolAddress((void**)&Ql, g_Ql);
    cudaGetSymbolAddress((void**)&Kh, g_Kh);   cudaGetSymbolAddress((void**)&Kl, g_Kl);
    cudaGetSymbolAddress((void**)&Vh, g_Vh);   cudaGetSymbolAddress((void**)&Vl, g_Vl);
    cudaGetSymbolAddress((void**)&Wqh, g_Wqh); cudaGetSymbolAddress((void**)&Wql, g_Wql);
    cudaGetSymbolAddress((void**)&Wkh, g_Wkh); cudaGetSymbolAddress((void**)&Wkl, g_Wkl);
    cudaGetSymbolAddress((void**)&Wvh, g_Wvh); cudaGetSymbolAddress((void**)&Wvl, g_Wvl);
    cudaGetSymbolAddress((void**)&qh, g_qh);   cudaGetSymbolAddress((void**)&ql, g_ql);
    cudaGetSymbolAddress((void**)&kh, g_kh);   cudaGetSymbolAddress((void**)&kl, g_kl);
    cudaGetSymbolAddress((void**)&vth, g_vth);
    cudaGetSymbolAddress((void**)&ah, g_ah);   cudaGetSymbolAddress((void**)&al, g_al);
    cudaGetSymbolAddress((void**)&s, g_s);     cudaGetSymbolAddress((void**)&part, g_part);

    cudaFuncSetAttribute(gemm_scores, cudaFuncAttributeMaxDynamicSharedMemorySize, DYNSMEM);
    cudaFuncSetAttribute(proj3,       cudaFuncAttributeMaxDynamicSharedMemorySize, DYNSMEM);
    cudaFuncSetAttribute(gemm_av,     cudaFuncAttributeMaxDynamicSharedMemorySize, DYNSMEM_AV);

    const float scale = 1.0f / sqrtf((float)DM);
    dim3 blk(256);

    const int n1 = ROWS * DM;
    const int n2 = DM * DM;
    split3_kernel<<<dim3(n1/1024, 3), blk>>>(Q, K, V,
        Qh, Ql, Kh, Kl, Vh, Vl, n1);
    split3_kernel<<<dim3(n2/1024, 3), blk>>>(W_q, W_k, W_v,
        Wqh, Wql, Wkh, Wkl, Wvh, Wvl, n2);

    // Fused projections (one launch, 768 CTAs)
    {
        ProjArgs pa;
        pa.Ah[0]=Qh; pa.Al[0]=Ql; pa.Bh[0]=Wqh; pa.Bl[0]=Wql; pa.bias[0]=b_q;
        pa.Ch[0]=qh; pa.Cl[0]=ql;
        pa.Ah[1]=Kh; pa.Al[1]=Kl; pa.Bh[1]=Wkh; pa.Bl[1]=Wkl; pa.bias[1]=b_k;
        pa.Ch[1]=kh; pa.Cl[1]=kl;
        pa.Ah[2]=Vh; pa.Al[2]=Vl; pa.Bh[2]=Wvh; pa.Bl[2]=Wvl; pa.bias[2]=b_v;
        pa.Ch[2]=vth; pa.Cl[2]=vth;   // z==2 writes Ch only
        dim3 gp(DM/128, ROWS/128, 3);
        proj3<<<gp, blk, DYNSMEM>>>(pa);
    }

    // Scores (NT, per batch, 3-term): s = scale * q @ k^T
    {
        dim3 gs(SEQ/128, SEQ/128, BATCH);
        gemm_scores<<<gs, blk, DYNSMEM>>>(qh, ql, kh, kl,
            s, SEQ, SEQ, DM,
            (long)SEQ*DM, (long)SEQ*DM, (long)SEQ*SEQ, scale);
    }

    // Online softmax -> split fp16 attention
    softmax_split<<<ROWS, blk>>>(s, ah, al);

    // Output: 2-term attn @ v via vT, split-K=4 partials then reduce
    {
        dim3 go(DM/128, SEQ/128, BATCH * SPLITK);
        gemm_av<<<go, blk, DYNSMEM_AV>>>(ah, al, vth,
            part, SEQ, DM, SEQ, SPLITK,
            (long)SEQ*SEQ, (long)DM*SEQ, (long)SEQ*DM);
        reduce_splitk<<<(ROWS*DM)/1024, blk>>>(part, out);
    }
}

// round 14
// speedup vs baseline: 1.4281x; 1.1630x over previous
#include <cuda_runtime.h>
#include <cuda_fp16.h>
#include <math.h>

#define BATCH 2
#define SEQ   4096
#define DM    512
#define ROWS  (BATCH*SEQ)   // 8192
#define SPLITK 4
#define L2E   1.4426950408889634f

typedef unsigned short u16;
typedef unsigned int   u32;

// ---------------------------------------------------------------------------
// Device scratch (allocation-free rule: __device__ globals)
// ---------------------------------------------------------------------------
__device__ u16 g_Qh[(size_t)ROWS*DM], g_Ql[(size_t)ROWS*DM];
__device__ u16 g_Kh[(size_t)ROWS*DM], g_Kl[(size_t)ROWS*DM];
__device__ u16 g_Vh[(size_t)ROWS*DM], g_Vl[(size_t)ROWS*DM];
__device__ u16 g_Wqh[DM*DM], g_Wql[DM*DM];
__device__ u16 g_Wkh[DM*DM], g_Wkl[DM*DM];
__device__ u16 g_Wvh[DM*DM], g_Wvl[DM*DM];
__device__ u16 g_qh[(size_t)ROWS*DM], g_ql[(size_t)ROWS*DM];
__device__ u16 g_kh[(size_t)ROWS*DM];                // k single fp16
__device__ u16 g_vth[(size_t)BATCH*DM*SEQ];          // V^T single fp16
__device__ float g_s[(size_t)BATCH*SEQ*SEQ];
__device__ u16 g_ah[(size_t)BATCH*SEQ*SEQ], g_al[(size_t)BATCH*SEQ*SEQ];
__device__ float g_part[(size_t)BATCH*SPLITK*SEQ*DM];   // attnV split-K partials

// ---------------------------------------------------------------------------
// fp16 helpers
// ---------------------------------------------------------------------------
__device__ __forceinline__ u16 f2h(float x) {
    return __half_as_ushort(__float2half_rn(x));
}
__device__ __forceinline__ float h2f(u16 u) {
    return __half2float(__ushort_as_half(u));
}
__device__ __forceinline__ void split_f16(float x, u16& hi, u16& lo) {
    hi = f2h(x);
    lo = f2h(x - h2f(hi));
}
__device__ __forceinline__ unsigned pack2(u16 a, u16 b) {
    return (unsigned)a | ((unsigned)b << 16);
}

__device__ __forceinline__ void mma16816(float c[4],
                                         u32 a0, u32 a1, u32 a2, u32 a3,
                                         u32 b0, u32 b1)
{
    asm volatile(
        "mma.sync.aligned.m16n8k16.row.col.f32.f16.f16.f32 "
        "{%0,%1,%2,%3}, {%4,%5,%6,%7}, {%8,%9}, {%0,%1,%2,%3};\n"
        : "+f"(c[0]), "+f"(c[1]), "+f"(c[2]), "+f"(c[3])
        : "r"(a0), "r"(a1), "r"(a2), "r"(a3), "r"(b0), "r"(b1));
}

__device__ __forceinline__ void cp16(void* smem_dst, const void* gsrc) {
    u32 u = (u32)__cvta_generic_to_shared(smem_dst);
    asm volatile("cp.async.cg.shared.global [%0], [%1], 16;\n" :: "r"(u), "l"(gsrc));
}

__device__ __forceinline__ void ldsm4(u32& r0, u32& r1, u32& r2, u32& r3, u32 addr) {
    asm volatile("ldmatrix.sync.aligned.m8n8.x4.shared.b16 {%0,%1,%2,%3}, [%4];"
                 : "=r"(r0), "=r"(r1), "=r"(r2), "=r"(r3) : "r"(addr));
}

// ---------------------------------------------------------------------------
// Fused fp32 -> split fp16 for 3 equal-size arrays
// ---------------------------------------------------------------------------
__global__ __launch_bounds__(256)
void split3_kernel(const float* __restrict__ x0, const float* __restrict__ x1,
                   const float* __restrict__ x2,
                   u16* __restrict__ h0a, u16* __restrict__ l0a,
                   u16* __restrict__ h1a, u16* __restrict__ l1a,
                   u16* __restrict__ h2a, u16* __restrict__ l2a, int n)
{
    const float* x;
    u16 *hp, *lp;
    if (blockIdx.y == 0)      { x = x0; hp = h0a; lp = l0a; }
    else if (blockIdx.y == 1) { x = x1; hp = h1a; lp = l1a; }
    else                      { x = x2; hp = h2a; lp = l2a; }

    int i = (blockIdx.x * blockDim.x + threadIdx.x) * 4;
    if (i >= n) return;
    float4 f = *reinterpret_cast<const float4*>(x + i);
    u16 h0,l0,h1,l1,h2,l2,h3,l3;
    split_f16(f.x, h0, l0);
    split_f16(f.y, h1, l1);
    split_f16(f.z, h2, l2);
    split_f16(f.w, h3, l3);
    *reinterpret_cast<uint2*>(hp + i) = make_uint2(pack2(h0,h1), pack2(h2,h3));
    *reinterpret_cast<uint2*>(lp + i) = make_uint2(pack2(l0,l1), pack2(l2,l3));
}

// ---------------------------------------------------------------------------
// Common tiling constants
// ---------------------------------------------------------------------------
#define SMP   40
#define ROWB  (SMP*2)              // 80 bytes
#define ARR_BYTES   (128*ROWB)     // 10240
#define STAGE_BYTES (4*ARR_BYTES)  // 40960 (3-term stage: Ah,Al,Bh,Bl)
#define NSTAGE 2
#define DYNSMEM (NSTAGE*STAGE_BYTES)   // 81920 -> 2 CTAs/SM

// ---------------------------------------------------------------------------
// 3-term mainloop (projections only): A split x B split
// ---------------------------------------------------------------------------
__device__ __forceinline__ void issue_stage(char* base,
    const u16* __restrict__ Agh, const u16* __restrict__ Agl,
    const u16* __restrict__ Bgh, const u16* __restrict__ Bgl,
    int row0, int col0, int Kstride, int k0, int tid)
{
#pragma unroll
    for (int e = 0; e < 2; e++) {
        int idx = tid + (e << 8);
        int r = idx >> 2;
        int c = (idx & 3) << 3;
        size_t offA = (size_t)(row0 + r) * Kstride + k0 + c;
        size_t offB = (size_t)(col0 + r) * Kstride + k0 + c;
        int sm = r * ROWB + c * 2;
        cp16(base + sm,                 Agh + offA);
        cp16(base + ARR_BYTES   + sm,   Agl + offA);
        cp16(base + 2*ARR_BYTES + sm,   Bgh + offB);
        cp16(base + 3*ARR_BYTES + sm,   Bgl + offB);
    }
}

__device__ __forceinline__ void gemm_main(char* smem, float acc[2][8][4],
    const u16* __restrict__ Agh, const u16* __restrict__ Agl,
    const u16* __restrict__ Bgh, const u16* __restrict__ Bgl,
    int row0, int col0, int Kstride, int kbeg, int Kpart, int tid)
{
    const int lane = tid & 31;
    const int wid  = tid >> 5;
    const int wm0  = (wid & 3) * 32;
    const int wn0  = (wid >> 2) * 64;

    const u32 aLane = (u32)((wm0 + (lane & 15)) * ROWB + ((lane >> 4) << 4));
    const u32 bLane = (u32)((wn0 + ((lane >> 4) << 3) + (lane & 7)) * ROWB
                            + ((lane & 8) << 1));
    const u32 smem_base = (u32)__cvta_generic_to_shared(smem);

#pragma unroll
    for (int i = 0; i < 2; i++)
#pragma unroll
        for (int j = 0; j < 8; j++)
#pragma unroll
            for (int t = 0; t < 4; t++) acc[i][j][t] = 0.0f;

    const int NIT = Kpart >> 5;

#pragma unroll
    for (int s = 0; s < NSTAGE; s++) {
        issue_stage(smem + s * STAGE_BYTES, Agh, Agl, Bgh, Bgl,
                    row0, col0, Kstride, kbeg + (s << 5), tid);
        asm volatile("cp.async.commit_group;\n" ::: "memory");
    }

    for (int it = 0; it < NIT; it++) {
        asm volatile("cp.async.wait_group 1;\n" ::: "memory");
        __syncthreads();

        const u32 stg = smem_base + (u32)((it & 1) * STAGE_BYTES);

#pragma unroll
        for (int ks = 0; ks < 2; ks++) {
            const u32 ko = ks << 5;
            u32 ah[2][4], al[2][4];
#pragma unroll
            for (int i = 0; i < 2; i++) {
                u32 aoff = stg + aLane + (u32)(i * 16 * ROWB) + ko;
                ldsm4(ah[i][0], ah[i][1], ah[i][2], ah[i][3], aoff);
                ldsm4(al[i][0], al[i][1], al[i][2], al[i][3], aoff + ARR_BYTES);
            }
#pragma unroll
            for (int half = 0; half < 2; half++) {
                u32 bh[4][2], bl[4][2];
#pragma unroll
                for (int p = 0; p < 2; p++) {
                    u32 boff = stg + 2*ARR_BYTES + bLane
                             + (u32)((half * 2 + p) * 16 * ROWB) + ko;
                    ldsm4(bh[2*p][0], bh[2*p][1], bh[2*p+1][0], bh[2*p+1][1], boff);
                    ldsm4(bl[2*p][0], bl[2*p][1], bl[2*p+1][0], bl[2*p+1][1],
                          boff + ARR_BYTES);
                }
#pragma unroll
                for (int i = 0; i < 2; i++)
#pragma unroll
                    for (int j = 0; j < 4; j++)
                        mma16816(acc[i][half*4 + j],
                                 ah[i][0], ah[i][1], ah[i][2], ah[i][3],
                                 bh[j][0], bh[j][1]);
#pragma unroll
                for (int i = 0; i < 2; i++)
#pragma unroll
                    for (int j = 0; j < 4; j++)
                        mma16816(acc[i][half*4 + j],
                                 ah[i][0], ah[i][1], ah[i][2], ah[i][3],
                                 bl[j][0], bl[j][1]);
#pragma unroll
                for (int i = 0; i < 2; i++)
#pragma unroll
                    for (int j = 0; j < 4; j++)
                        mma16816(acc[i][half*4 + j],
                                 al[i][0], al[i][1], al[i][2], al[i][3],
                                 bh[j][0], bh[j][1]);
            }
        }
        __syncthreads();

        if (it + NSTAGE < NIT)
            issue_stage(smem + (it & 1) * STAGE_BYTES, Agh, Agl, Bgh, Bgl,
                        row0, col0, Kstride, kbeg + ((it + NSTAGE) << 5), tid);
        asm volatile("cp.async.commit_group;\n" ::: "memory");
    }
}

// ---------------------------------------------------------------------------
// Fused Q/K/V projections (3-term): grid (DM/128, ROWS/128, 3)
// z==0 -> split fp16 out; z==1 -> single fp16 out; z==2 -> single fp16 ^T out
// ---------------------------------------------------------------------------
struct ProjArgs {
    const u16* Ah[3]; const u16* Al[3];
    const u16* Bh[3]; const u16* Bl[3];
    const float* bias[3];
    u16* Ch[3]; u16* Cl[3];
};

__global__ __launch_bounds__(256, 2)
void proj3(ProjArgs pa)
{
    extern __shared__ char smem[];
    const int z = blockIdx.z;

    const int tid  = threadIdx.x;
    const int lane = tid & 31;
    const int wid  = tid >> 5;
    const int g    = lane >> 2;
    const int tg   = lane & 3;
    const int wm0  = (wid & 3) * 32;
    const int wn0  = (wid >> 2) * 64;
    const int row0 = blockIdx.y * 128;
    const int col0 = blockIdx.x * 128;

    float acc[2][8][4];
    gemm_main(smem, acc, pa.Ah[z], pa.Al[z], pa.Bh[z], pa.Bl[z],
              row0, col0, DM, 0, DM, tid);

    const float* bias = pa.bias[z];
    u16* Ch = pa.Ch[z];
    u16* Cl = pa.Cl[z];
    const int N = DM;

#pragma unroll
    for (int i = 0; i < 2; i++) {
        int r1 = row0 + wm0 + 16 * i + g;
        int r2 = r1 + 8;
#pragma unroll
        for (int j = 0; j < 8; j++) {
            int n = col0 + wn0 + 8 * j + 2 * tg;
            float b0 = bias[n], b1 = bias[n + 1];
            float v00 = acc[i][j][0] + b0;
            float v01 = acc[i][j][1] + b1;
            float v10 = acc[i][j][2] + b0;
            float v11 = acc[i][j][3] + b1;

            if (z == 0) {
                u16 h0,l0,h1,l1;
                split_f16(v00, h0, l0); split_f16(v01, h1, l1);
                *reinterpret_cast<u32*>(Ch + (size_t)r1 * N + n) = pack2(h0, h1);
                *reinterpret_cast<u32*>(Cl + (size_t)r1 * N + n) = pack2(l0, l1);
                split_f16(v10, h0, l0); split_f16(v11, h1, l1);
                *reinterpret_cast<u32*>(Ch + (size_t)r2 * N + n) = pack2(h0, h1);
                *reinterpret_cast<u32*>(Cl + (size_t)r2 * N + n) = pack2(l0, l1);
            } else if (z == 1) {
                *reinterpret_cast<u32*>(Ch + (size_t)r1 * N + n) =
                    pack2(f2h(v00), f2h(v01));
                *reinterpret_cast<u32*>(Ch + (size_t)r2 * N + n) =
                    pack2(f2h(v10), f2h(v11));
            } else {
                // single fp16, transposed per-batch [b][n][m]
                int   rr[2] = { r1, r2 };
                float vv[2][2] = { { v00, v01 }, { v10, v11 } };
#pragma unroll
                for (int t = 0; t < 2; t++) {
                    int m  = rr[t];
                    int b  = m >> 12;
                    int mm = m & (SEQ - 1);
#pragma unroll
                    for (int u = 0; u < 2; u++) {
                        size_t idx = ((size_t)(b * DM + n + u)) * SEQ + mm;
                        Ch[idx] = f2h(vv[t][u]);
                    }
                }
            }
        }
    }
}

// ---------------------------------------------------------------------------
// 2-term GEMM (A split fp16 x B single fp16), split-K, fp32 out with alpha.
// Used for BOTH scores (splitk=1, alpha=scale) and attnV (splitk=4, alpha=1).
// Stage = Ah, Al, Bh (3 arrays, 30KB); 2 stages = 60KB -> 2 CTAs/SM
// ---------------------------------------------------------------------------
#define T2_STAGE (3*ARR_BYTES)     // 30720
#define DYNSMEM_T2 (2*T2_STAGE)    // 61440

__device__ __forceinline__ void issue_stage_2t(char* base,
    const u16* __restrict__ Agh, const u16* __restrict__ Agl,
    const u16* __restrict__ Bgh,
    int row0, int col0, int Kstride, int k0, int tid)
{
#pragma unroll
    for (int e = 0; e < 2; e++) {
        int idx = tid + (e << 8);
        int r = idx >> 2;
        int c = (idx & 3) << 3;
        size_t offA = (size_t)(row0 + r) * Kstride + k0 + c;
        size_t offB = (size_t)(col0 + r) * Kstride + k0 + c;
        int sm = r * ROWB + c * 2;
        cp16(base + sm,               Agh + offA);
        cp16(base + ARR_BYTES + sm,   Agl + offA);
        cp16(base + 2*ARR_BYTES + sm, Bgh + offB);
    }
}

__global__ __launch_bounds__(256, 2)
void gemm_2t(const u16* __restrict__ Agh, const u16* __restrict__ Agl,
             const u16* __restrict__ Bgh,
             float* __restrict__ Cf,
             int M, int N, int K, int splitk,
             long sA, long sB, long sC, float alpha)
{
    extern __shared__ char smem[];

    const int bzAll = blockIdx.z;
    const int bat   = bzAll / splitk;
    const int ksp   = bzAll - bat * splitk;
    const int Kpart = K / splitk;
    const int kbeg  = ksp * Kpart;

    Agh += (size_t)bat * sA;  Agl += (size_t)bat * sA;
    Bgh += (size_t)bat * sB;

    const int tid  = threadIdx.x;
    const int lane = tid & 31;
    const int wid  = tid >> 5;
    const int g    = lane >> 2;
    const int tg   = lane & 3;
    const int wm0  = (wid & 3) * 32;
    const int wn0  = (wid >> 2) * 64;
    const int row0 = blockIdx.y * 128;
    const int col0 = blockIdx.x * 128;

    const u32 aLane = (u32)((wm0 + (lane & 15)) * ROWB + ((lane >> 4) << 4));
    const u32 bLane = (u32)((wn0 + ((lane >> 4) << 3) + (lane & 7)) * ROWB
                            + ((lane & 8) << 1));
    const u32 smem_base = (u32)__cvta_generic_to_shared(smem);

    float acc[2][8][4];
#pragma unroll
    for (int i = 0; i < 2; i++)
#pragma unroll
        for (int j = 0; j < 8; j++)
#pragma unroll
            for (int t = 0; t < 4; t++) acc[i][j][t] = 0.0f;

    const int NIT = Kpart >> 5;

#pragma unroll
    for (int s = 0; s < 2; s++) {
        issue_stage_2t(smem + s * T2_STAGE, Agh, Agl, Bgh,
                       row0, col0, K, kbeg + (s << 5), tid);
        asm volatile("cp.async.commit_group;\n" ::: "memory");
    }

    for (int it = 0; it < NIT; it++) {
        asm volatile("cp.async.wait_group 1;\n" ::: "memory");
        __syncthreads();

        const u32 stg = smem_base + (u32)((it & 1) * T2_STAGE);

#pragma unroll
        for (int ks = 0; ks < 2; ks++) {
            const u32 ko = ks << 5;
            u32 ah[2][4], al[2][4];
#pragma unroll
            for (int i = 0; i < 2; i++) {
                u32 aoff = stg + aLane + (u32)(i * 16 * ROWB) + ko;
                ldsm4(ah[i][0], ah[i][1], ah[i][2], ah[i][3], aoff);
                ldsm4(al[i][0], al[i][1], al[i][2], al[i][3], aoff + ARR_BYTES);
            }
#pragma unroll
            for (int half = 0; half < 2; half++) {
                u32 bh[4][2];
#pragma unroll
                for (int p = 0; p < 2; p++) {
                    u32 boff = stg + 2*ARR_BYTES + bLane
                             + (u32)((half * 2 + p) * 16 * ROWB) + ko;
                    ldsm4(bh[2*p][0], bh[2*p][1], bh[2*p+1][0], bh[2*p+1][1], boff);
                }
#pragma unroll
                for (int i = 0; i < 2; i++)
#pragma unroll
                    for (int j = 0; j < 4; j++)
                        mma16816(acc[i][half*4 + j],
                                 ah[i][0], ah[i][1], ah[i][2], ah[i][3],
                                 bh[j][0], bh[j][1]);
#pragma unroll
                for (int i = 0; i < 2; i++)
#pragma unroll
                    for (int j = 0; j < 4; j++)
                        mma16816(acc[i][half*4 + j],
                                 al[i][0], al[i][1], al[i][2], al[i][3],
                                 bh[j][0], bh[j][1]);
            }
        }
        __syncthreads();

        if (it + 2 < NIT)
            issue_stage_2t(smem + (it & 1) * T2_STAGE, Agh, Agl, Bgh,
                           row0, col0, K, kbeg + ((it + 2) << 5), tid);
        asm volatile("cp.async.commit_group;\n" ::: "memory");
    }

    float* Cb = Cf + (size_t)bzAll * sC;
#pragma unroll
    for (int i = 0; i < 2; i++) {
        int r1 = row0 + wm0 + 16 * i + g;
        int r2 = r1 + 8;
#pragma unroll
        for (int j = 0; j < 8; j++) {
            int n = col0 + wn0 + 8 * j + 2 * tg;
            *reinterpret_cast<float2*>(Cb + (size_t)r1 * N + n) =
                make_float2(acc[i][j][0] * alpha, acc[i][j][1] * alpha);
            *reinterpret_cast<float2*>(Cb + (size_t)r2 * N + n) =
                make_float2(acc[i][j][2] * alpha, acc[i][j][3] * alpha);
        }
    }
}

// ---------------------------------------------------------------------------
// Reduce SPLITK partials
// ---------------------------------------------------------------------------
__global__ __launch_bounds__(256)
void reduce_splitk(const float* __restrict__ part, float* __restrict__ out)
{
    const size_t SD = (size_t)SEQ * DM;
    size_t idx = ((size_t)blockIdx.x * 256 + threadIdx.x) * 4;
    int b = (int)(idx / SD);
    size_t r = idx - (size_t)b * SD;
    const float* pb = part + (size_t)b * SPLITK * SD + r;
    float4 s0 = *reinterpret_cast<const float4*>(pb);
    float4 s1 = *reinterpret_cast<const float4*>(pb + SD);
    float4 s2 = *reinterpret_cast<const float4*>(pb + 2*SD);
    float4 s3 = *reinterpret_cast<const float4*>(pb + 3*SD);
    float4 o;
    o.x = (s0.x + s1.x) + (s2.x + s3.x);
    o.y = (s0.y + s1.y) + (s2.y + s3.y);
    o.z = (s0.z + s1.z) + (s2.z + s3.z);
    o.w = (s0.w + s1.w) + (s2.w + s3.w);
    *reinterpret_cast<float4*>(out + idx) = o;
}

// ---------------------------------------------------------------------------
// ONLINE row softmax -> split fp16 attention row
// ---------------------------------------------------------------------------
__global__ __launch_bounds__(256)
void softmax_split(const float* __restrict__ scores,
                   u16* __restrict__ ah, u16* __restrict__ al)
{
    const size_t roff = (size_t)blockIdx.x * SEQ;
    const float* p = scores + roff;
    const int tid  = threadIdx.x;
    const int lane = tid & 31;
    const int wrp  = tid >> 5;

    float v[16];
#pragma unroll
    for (int i = 0; i < 4; i++) {
        float4 f = *reinterpret_cast<const float4*>(p + i * 1024 + tid * 4);
        v[i*4+0] = f.x; v[i*4+1] = f.y; v[i*4+2] = f.z; v[i*4+3] = f.w;
    }

    float m = v[0];
#pragma unroll
    for (int i = 1; i < 16; i++) m = fmaxf(m, v[i]);
    const float mloc = m;

    float s = 0.0f;
#pragma unroll
    for (int i = 0; i < 16; i++) {
        v[i] = exp2f((v[i] - mloc) * L2E);
        s += v[i];
    }

#pragma unroll
    for (int o = 16; o > 0; o >>= 1) {
        float mo = __shfl_xor_sync(0xffffffffu, m, o);
        float so = __shfl_xor_sync(0xffffffffu, s, o);
        float mn = fmaxf(m, mo);
        s = s * exp2f((m - mn) * L2E) + so * exp2f((mo - mn) * L2E);
        m = mn;
    }

    __shared__ float redM[8], redS[8], fin[2];
    if (lane == 0) { redM[wrp] = m; redS[wrp] = s; }
    __syncthreads();
    if (tid < 32) {
        float mm = (tid < 8) ? redM[tid] : -INFINITY;
        float ss = (tid < 8) ? redS[tid] : 0.0f;
#pragma unroll
        for (int o = 4; o > 0; o >>= 1) {
            float mo = __shfl_xor_sync(0xffffffffu, mm, o);
            float so = __shfl_xor_sync(0xffffffffu, ss, o);
            float mn = fmaxf(mm, mo);
            ss = ss * exp2f((mm - mn) * L2E) + so * exp2f((mo - mn) * L2E);
            mm = mn;
        }
        if (tid == 0) { fin[0] = mm; fin[1] = 1.0f / ss; }
    }
    __syncthreads();

    const float scalef = exp2f((mloc - fin[0]) * L2E) * fin[1];

#pragma unroll
    for (int i = 0; i < 4; i++) {
        u16 h[4], l[4];
#pragma unroll
        for (int j = 0; j < 4; j++)
            split_f16(v[i*4+j] * scalef, h[j], l[j]);
        *reinterpret_cast<uint2*>(ah + roff + i * 1024 + tid * 4) =
            make_uint2(pack2(h[0], h[1]), pack2(h[2], h[3]));
        *reinterpret_cast<uint2*>(al + roff + i * 1024 + tid * 4) =
            make_uint2(pack2(l[0], l[1]), pack2(l[2], l[3]));
    }
}

// ---------------------------------------------------------------------------
extern "C" void kernel_launch(void* const* d_in, const int* in_sizes, int n_in,
                              void* d_out, int out_size)
{
    const float* Q   = (const float*)d_in[0];
    const float* K   = (const float*)d_in[1];
    const float* V   = (const float*)d_in[2];
    const float* W_q = (const float*)d_in[3];
    const float* b_q = (const float*)d_in[4];
    const float* W_k = (const float*)d_in[5];
    const float* b_k = (const float*)d_in[6];
    const float* W_v = (const float*)d_in[7];
    const float* b_v = (const float*)d_in[8];
    float* out = (float*)d_out;

    u16 *Qh,*Ql,*Kh,*Kl,*Vh,*Vl, *Wqh,*Wql,*Wkh,*Wkl,*Wvh,*Wvl;
    u16 *qh,*ql,*kh,*vth,*ah,*al;
    float *s, *part;
    cudaGetSymbolAddress((void**)&Qh, g_Qh);   cudaGetSymbolAddress((void**)&Ql, g_Ql);
    cudaGetSymbolAddress((void**)&Kh, g_Kh);   cudaGetSymbolAddress((void**)&Kl, g_Kl);
    cudaGetSymbolAddress((void**)&Vh, g_Vh);   cudaGetSymbolAddress((void**)&Vl, g_Vl);
    cudaGetSymbolAddress((void**)&Wqh, g_Wqh); cudaGetSymbolAddress((void**)&Wql, g_Wql);
    cudaGetSymbolAddress((void**)&Wkh, g_Wkh); cudaGetSymbolAddress((void**)&Wkl, g_Wkl);
    cudaGetSymbolAddress((void**)&Wvh, g_Wvh); cudaGetSymbolAddress((void**)&Wvl, g_Wvl);
    cudaGetSymbolAddress((void**)&qh, g_qh);   cudaGetSymbolAddress((void**)&ql, g_ql);
    cudaGetSymbolAddress((void**)&kh, g_kh);
    cudaGetSymbolAddress((void**)&vth, g_vth);
    cudaGetSymbolAddress((void**)&ah, g_ah);   cudaGetSymbolAddress((void**)&al, g_al);
    cudaGetSymbolAddress((void**)&s, g_s);     cudaGetSymbolAddress((void**)&part, g_part);

    cudaFuncSetAttribute(proj3,   cudaFuncAttributeMaxDynamicSharedMemorySize, DYNSMEM);
    cudaFuncSetAttribute(gemm_2t, cudaFuncAttributeMaxDynamicSharedMemorySize, DYNSMEM_T2);

    const float scale = 1.0f / sqrtf((float)DM);
    dim3 blk(256);

    const int n1 = ROWS * DM;
    const int n2 = DM * DM;
    split3_kernel<<<dim3(n1/1024, 3), blk>>>(Q, K, V,
        Qh, Ql, Kh, Kl, Vh, Vl, n1);
    split3_kernel<<<dim3(n2/1024, 3), blk>>>(W_q, W_k, W_v,
        Wqh, Wql, Wkh, Wkl, Wvh, Wvl, n2);

    // Fused projections (one launch, 768 CTAs):
    // q -> split (qh,ql); k -> single (kh); v -> single transposed (vth)
    {
        ProjArgs pa;
        pa.Ah[0]=Qh; pa.Al[0]=Ql; pa.Bh[0]=Wqh; pa.Bl[0]=Wql; pa.bias[0]=b_q;
        pa.Ch[0]=qh; pa.Cl[0]=ql;
        pa.Ah[1]=Kh; pa.Al[1]=Kl; pa.Bh[1]=Wkh; pa.Bl[1]=Wkl; pa.bias[1]=b_k;
        pa.Ch[1]=kh; pa.Cl[1]=kh;
        pa.Ah[2]=Vh; pa.Al[2]=Vl; pa.Bh[2]=Wvh; pa.Bl[2]=Wvl; pa.bias[2]=b_v;
        pa.Ch[2]=vth; pa.Cl[2]=vth;
        dim3 gp(DM/128, ROWS/128, 3);
        proj3<<<gp, blk, DYNSMEM>>>(pa);
    }

    // Scores (2-term, NT, per batch): s = scale * (qh+ql) @ kh^T
    {
        dim3 gs(SEQ/128, SEQ/128, BATCH);
        gemm_2t<<<gs, blk, DYNSMEM_T2>>>(qh, ql, kh,
            s, SEQ, SEQ, DM, 1,
            (long)SEQ*DM, (long)SEQ*DM, (long)SEQ*SEQ, scale);
    }

    // Online softmax -> split fp16 attention
    softmax_split<<<ROWS, blk>>>(s, ah, al);

    // Output: 2-term attn @ v via vT, split-K=4 partials then reduce
    {
        dim3 go(DM/128, SEQ/128, BATCH * SPLITK);
        gemm_2t<<<go, blk, DYNSMEM_T2>>>(ah, al, vth,
            part, SEQ, DM, SEQ, SPLITK,
            (long)SEQ*SEQ, (long)DM*SEQ, (long)SEQ*DM, 1.0f);
        reduce_splitk<<<(ROWS*DM)/1024, blk>>>(part, out);
    }
}

// round 15
// speedup vs baseline: 1.5201x; 1.0644x over previous
#include <cuda_runtime.h>
#include <cuda_fp16.h>
#include <math.h>

#define BATCH 2
#define SEQ   4096
#define DM    512
#define ROWS  (BATCH*SEQ)   // 8192
#define SPLITK 4
#define L2E   1.4426950408889634f

typedef unsigned short u16;
typedef unsigned int   u32;

// ---------------------------------------------------------------------------
// Device scratch (allocation-free rule: __device__ globals)
// ---------------------------------------------------------------------------
__device__ u16 g_Xq[(size_t)ROWS*DM], g_Xk[(size_t)ROWS*DM], g_Xv[(size_t)ROWS*DM];
__device__ u16 g_Wqh[DM*DM], g_Wql[DM*DM];
__device__ u16 g_Wkh[DM*DM], g_Wkl[DM*DM];
__device__ u16 g_Wvh[DM*DM], g_Wvl[DM*DM];
__device__ u16 g_qh[(size_t)ROWS*DM], g_ql[(size_t)ROWS*DM];
__device__ u16 g_kh[(size_t)ROWS*DM];                // k single fp16
__device__ u16 g_vth[(size_t)BATCH*DM*SEQ];          // V^T single fp16
__device__ float g_s[(size_t)BATCH*SEQ*SEQ];
__device__ u16 g_ah[(size_t)BATCH*SEQ*SEQ], g_al[(size_t)BATCH*SEQ*SEQ];
__device__ float g_part[(size_t)BATCH*SPLITK*SEQ*DM];   // attnV split-K partials

// ---------------------------------------------------------------------------
// fp16 helpers
// ---------------------------------------------------------------------------
__device__ __forceinline__ u16 f2h(float x) {
    return __half_as_ushort(__float2half_rn(x));
}
__device__ __forceinline__ float h2f(u16 u) {
    return __half2float(__ushort_as_half(u));
}
__device__ __forceinline__ void split_f16(float x, u16& hi, u16& lo) {
    hi = f2h(x);
    lo = f2h(x - h2f(hi));
}
__device__ __forceinline__ unsigned pack2(u16 a, u16 b) {
    return (unsigned)a | ((unsigned)b << 16);
}

__device__ __forceinline__ void mma16816(float c[4],
                                         u32 a0, u32 a1, u32 a2, u32 a3,
                                         u32 b0, u32 b1)
{
    asm volatile(
        "mma.sync.aligned.m16n8k16.row.col.f32.f16.f16.f32 "
        "{%0,%1,%2,%3}, {%4,%5,%6,%7}, {%8,%9}, {%0,%1,%2,%3};\n"
        : "+f"(c[0]), "+f"(c[1]), "+f"(c[2]), "+f"(c[3])
        : "r"(a0), "r"(a1), "r"(a2), "r"(a3), "r"(b0), "r"(b1));
}

__device__ __forceinline__ void cp16(void* smem_dst, const void* gsrc) {
    u32 u = (u32)__cvta_generic_to_shared(smem_dst);
    asm volatile("cp.async.cg.shared.global [%0], [%1], 16;\n" :: "r"(u), "l"(gsrc));
}

__device__ __forceinline__ void ldsm4(u32& r0, u32& r1, u32& r2, u32& r3, u32 addr) {
    asm volatile("ldmatrix.sync.aligned.m8n8.x4.shared.b16 {%0,%1,%2,%3}, [%4];"
                 : "=r"(r0), "=r"(r1), "=r"(r2), "=r"(r3) : "r"(addr));
}

// ---------------------------------------------------------------------------
// Fused fp32 -> SINGLE fp16 for 3 equal-size arrays (inputs)
// ---------------------------------------------------------------------------
__global__ __launch_bounds__(256)
void conv3_kernel(const float* __restrict__ x0, const float* __restrict__ x1,
                  const float* __restrict__ x2,
                  u16* __restrict__ o0, u16* __restrict__ o1,
                  u16* __restrict__ o2, int n)
{
    const float* x;
    u16* op;
    if (blockIdx.y == 0)      { x = x0; op = o0; }
    else if (blockIdx.y == 1) { x = x1; op = o1; }
    else                      { x = x2; op = o2; }

    int i = (blockIdx.x * blockDim.x + threadIdx.x) * 4;
    if (i >= n) return;
    float4 f = *reinterpret_cast<const float4*>(x + i);
    *reinterpret_cast<uint2*>(op + i) =
        make_uint2(pack2(f2h(f.x), f2h(f.y)), pack2(f2h(f.z), f2h(f.w)));
}

// ---------------------------------------------------------------------------
// Fused fp32 -> split fp16 for 3 equal-size arrays (weights)
// ---------------------------------------------------------------------------
__global__ __launch_bounds__(256)
void split3_kernel(const float* __restrict__ x0, const float* __restrict__ x1,
                   const float* __restrict__ x2,
                   u16* __restrict__ h0a, u16* __restrict__ l0a,
                   u16* __restrict__ h1a, u16* __restrict__ l1a,
                   u16* __restrict__ h2a, u16* __restrict__ l2a, int n)
{
    const float* x;
    u16 *hp, *lp;
    if (blockIdx.y == 0)      { x = x0; hp = h0a; lp = l0a; }
    else if (blockIdx.y == 1) { x = x1; hp = h1a; lp = l1a; }
    else                      { x = x2; hp = h2a; lp = l2a; }

    int i = (blockIdx.x * blockDim.x + threadIdx.x) * 4;
    if (i >= n) return;
    float4 f = *reinterpret_cast<const float4*>(x + i);
    u16 h0,l0,h1,l1,h2,l2,h3,l3;
    split_f16(f.x, h0, l0);
    split_f16(f.y, h1, l1);
    split_f16(f.z, h2, l2);
    split_f16(f.w, h3, l3);
    *reinterpret_cast<uint2*>(hp + i) = make_uint2(pack2(h0,h1), pack2(h2,h3));
    *reinterpret_cast<uint2*>(lp + i) = make_uint2(pack2(l0,l1), pack2(l2,l3));
}

// ---------------------------------------------------------------------------
// Common tiling constants
// ---------------------------------------------------------------------------
#define SMP   40
#define ROWB  (SMP*2)              // 80 bytes
#define ARR_BYTES   (128*ROWB)     // 10240
#define T2_STAGE (3*ARR_BYTES)     // 30720 (2-term stage: 3 arrays)
#define DYNSMEM_T2 (2*T2_STAGE)    // 61440 -> 2 CTAs/SM

// ---------------------------------------------------------------------------
// Projections (2-term: X single x W split): grid (DM/128, ROWS/128, 3)
// Stage = [Xh][Wh][Wl]
// z==0 -> split fp16 out; z==1 -> single fp16 out; z==2 -> single fp16 ^T out
// ---------------------------------------------------------------------------
struct ProjArgs {
    const u16* X[3];
    const u16* Bh[3]; const u16* Bl[3];
    const float* bias[3];
    u16* Ch[3]; u16* Cl[3];
};

__device__ __forceinline__ void issue_stage_p(char* base,
    const u16* __restrict__ Xg,
    const u16* __restrict__ Bgh, const u16* __restrict__ Bgl,
    int row0, int col0, int Kstride, int k0, int tid)
{
#pragma unroll
    for (int e = 0; e < 2; e++) {
        int idx = tid + (e << 8);
        int r = idx >> 2;
        int c = (idx & 3) << 3;
        size_t offA = (size_t)(row0 + r) * Kstride + k0 + c;
        size_t offB = (size_t)(col0 + r) * Kstride + k0 + c;
        int sm = r * ROWB + c * 2;
        cp16(base + sm,               Xg + offA);
        cp16(base + ARR_BYTES + sm,   Bgh + offB);
        cp16(base + 2*ARR_BYTES + sm, Bgl + offB);
    }
}

__global__ __launch_bounds__(256, 2)
void proj3(ProjArgs pa)
{
    extern __shared__ char smem[];
    const int z = blockIdx.z;

    const int tid  = threadIdx.x;
    const int lane = tid & 31;
    const int wid  = tid >> 5;
    const int g    = lane >> 2;
    const int tg   = lane & 3;
    const int wm0  = (wid & 3) * 32;
    const int wn0  = (wid >> 2) * 64;
    const int row0 = blockIdx.y * 128;
    const int col0 = blockIdx.x * 128;

    const u16* Xg  = pa.X[z];
    const u16* Bgh = pa.Bh[z];
    const u16* Bgl = pa.Bl[z];

    const u32 aLane = (u32)((wm0 + (lane & 15)) * ROWB + ((lane >> 4) << 4));
    const u32 bLane = (u32)((wn0 + ((lane >> 4) << 3) + (lane & 7)) * ROWB
                            + ((lane & 8) << 1));
    const u32 smem_base = (u32)__cvta_generic_to_shared(smem);

    float acc[2][8][4];
#pragma unroll
    for (int i = 0; i < 2; i++)
#pragma unroll
        for (int j = 0; j < 8; j++)
#pragma unroll
            for (int t = 0; t < 4; t++) acc[i][j][t] = 0.0f;

    const int NIT = DM >> 5;

#pragma unroll
    for (int s = 0; s < 2; s++) {
        issue_stage_p(smem + s * T2_STAGE, Xg, Bgh, Bgl,
                      row0, col0, DM, s << 5, tid);
        asm volatile("cp.async.commit_group;\n" ::: "memory");
    }

    for (int it = 0; it < NIT; it++) {
        asm volatile("cp.async.wait_group 1;\n" ::: "memory");
        __syncthreads();

        const u32 stg = smem_base + (u32)((it & 1) * T2_STAGE);

#pragma unroll
        for (int ks = 0; ks < 2; ks++) {
            const u32 ko = ks << 5;
            u32 ah[2][4];
#pragma unroll
            for (int i = 0; i < 2; i++) {
                u32 aoff = stg + aLane + (u32)(i * 16 * ROWB) + ko;
                ldsm4(ah[i][0], ah[i][1], ah[i][2], ah[i][3], aoff);
            }
#pragma unroll
            for (int half = 0; half < 2; half++) {
                u32 bh[4][2], bl[4][2];
#pragma unroll
                for (int p = 0; p < 2; p++) {
                    u32 boff = stg + ARR_BYTES + bLane
                             + (u32)((half * 2 + p) * 16 * ROWB) + ko;
                    ldsm4(bh[2*p][0], bh[2*p][1], bh[2*p+1][0], bh[2*p+1][1], boff);
                    ldsm4(bl[2*p][0], bl[2*p][1], bl[2*p+1][0], bl[2*p+1][1],
                          boff + ARR_BYTES);
                }
#pragma unroll
                for (int i = 0; i < 2; i++)
#pragma unroll
                    for (int j = 0; j < 4; j++)
                        mma16816(acc[i][half*4 + j],
                                 ah[i][0], ah[i][1], ah[i][2], ah[i][3],
                                 bh[j][0], bh[j][1]);
#pragma unroll
                for (int i = 0; i < 2; i++)
#pragma unroll
                    for (int j = 0; j < 4; j++)
                        mma16816(acc[i][half*4 + j],
                                 ah[i][0], ah[i][1], ah[i][2], ah[i][3],
                                 bl[j][0], bl[j][1]);
            }
        }
        __syncthreads();

        if (it + 2 < NIT)
            issue_stage_p(smem + (it & 1) * T2_STAGE, Xg, Bgh, Bgl,
                          row0, col0, DM, (it + 2) << 5, tid);
        asm volatile("cp.async.commit_group;\n" ::: "memory");
    }

    const float* bias = pa.bias[z];
    u16* Ch = pa.Ch[z];
    u16* Cl = pa.Cl[z];
    const int N = DM;

#pragma unroll
    for (int i = 0; i < 2; i++) {
        int r1 = row0 + wm0 + 16 * i + g;
        int r2 = r1 + 8;
#pragma unroll
        for (int j = 0; j < 8; j++) {
            int n = col0 + wn0 + 8 * j + 2 * tg;
            float b0 = bias[n], b1 = bias[n + 1];
            float v00 = acc[i][j][0] + b0;
            float v01 = acc[i][j][1] + b1;
            float v10 = acc[i][j][2] + b0;
            float v11 = acc[i][j][3] + b1;

            if (z == 0) {
                u16 h0,l0,h1,l1;
                split_f16(v00, h0, l0); split_f16(v01, h1, l1);
                *reinterpret_cast<u32*>(Ch + (size_t)r1 * N + n) = pack2(h0, h1);
                *reinterpret_cast<u32*>(Cl + (size_t)r1 * N + n) = pack2(l0, l1);
                split_f16(v10, h0, l0); split_f16(v11, h1, l1);
                *reinterpret_cast<u32*>(Ch + (size_t)r2 * N + n) = pack2(h0, h1);
                *reinterpret_cast<u32*>(Cl + (size_t)r2 * N + n) = pack2(l0, l1);
            } else if (z == 1) {
                *reinterpret_cast<u32*>(Ch + (size_t)r1 * N + n) =
                    pack2(f2h(v00), f2h(v01));
                *reinterpret_cast<u32*>(Ch + (size_t)r2 * N + n) =
                    pack2(f2h(v10), f2h(v11));
            } else {
                int   rr[2] = { r1, r2 };
                float vv[2][2] = { { v00, v01 }, { v10, v11 } };
#pragma unroll
                for (int t = 0; t < 2; t++) {
                    int m  = rr[t];
                    int b  = m >> 12;
                    int mm = m & (SEQ - 1);
#pragma unroll
                    for (int u = 0; u < 2; u++) {
                        size_t idx = ((size_t)(b * DM + n + u)) * SEQ + mm;
                        Ch[idx] = f2h(vv[t][u]);
                    }
                }
            }
        }
    }
}

// ---------------------------------------------------------------------------
// 2-term GEMM (A split fp16 x B single fp16), split-K, fp32 out with alpha.
// Used for BOTH scores (splitk=1, alpha=scale) and attnV (splitk=4, alpha=1).
// ---------------------------------------------------------------------------
__device__ __forceinline__ void issue_stage_2t(char* base,
    const u16* __restrict__ Agh, const u16* __restrict__ Agl,
    const u16* __restrict__ Bgh,
    int row0, int col0, int Kstride, int k0, int tid)
{
#pragma unroll
    for (int e = 0; e < 2; e++) {
        int idx = tid + (e << 8);
        int r = idx >> 2;
        int c = (idx & 3) << 3;
        size_t offA = (size_t)(row0 + r) * Kstride + k0 + c;
        size_t offB = (size_t)(col0 + r) * Kstride + k0 + c;
        int sm = r * ROWB + c * 2;
        cp16(base + sm,               Agh + offA);
        cp16(base + ARR_BYTES + sm,   Agl + offA);
        cp16(base + 2*ARR_BYTES + sm, Bgh + offB);
    }
}

__global__ __launch_bounds__(256, 2)
void gemm_2t(const u16* __restrict__ Agh, const u16* __restrict__ Agl,
             const u16* __restrict__ Bgh,
             float* __restrict__ Cf,
             int M, int N, int K, int splitk,
             long sA, long sB, long sC, float alpha)
{
    extern __shared__ char smem[];

    const int bzAll = blockIdx.z;
    const int bat   = bzAll / splitk;
    const int ksp   = bzAll - bat * splitk;
    const int Kpart = K / splitk;
    const int kbeg  = ksp * Kpart;

    Agh += (size_t)bat * sA;  Agl += (size_t)bat * sA;
    Bgh += (size_t)bat * sB;

    const int tid  = threadIdx.x;
    const int lane = tid & 31;
    const int wid  = tid >> 5;
    const int g    = lane >> 2;
    const int tg   = lane & 3;
    const int wm0  = (wid & 3) * 32;
    const int wn0  = (wid >> 2) * 64;
    const int row0 = blockIdx.y * 128;
    const int col0 = blockIdx.x * 128;

    const u32 aLane = (u32)((wm0 + (lane & 15)) * ROWB + ((lane >> 4) << 4));
    const u32 bLane = (u32)((wn0 + ((lane >> 4) << 3) + (lane & 7)) * ROWB
                            + ((lane & 8) << 1));
    const u32 smem_base = (u32)__cvta_generic_to_shared(smem);

    float acc[2][8][4];
#pragma unroll
    for (int i = 0; i < 2; i++)
#pragma unroll
        for (int j = 0; j < 8; j++)
#pragma unroll
            for (int t = 0; t < 4; t++) acc[i][j][t] = 0.0f;

    const int NIT = Kpart >> 5;

#pragma unroll
    for (int s = 0; s < 2; s++) {
        issue_stage_2t(smem + s * T2_STAGE, Agh, Agl, Bgh,
                       row0, col0, K, kbeg + (s << 5), tid);
        asm volatile("cp.async.commit_group;\n" ::: "memory");
    }

    for (int it = 0; it < NIT; it++) {
        asm volatile("cp.async.wait_group 1;\n" ::: "memory");
        __syncthreads();

        const u32 stg = smem_base + (u32)((it & 1) * T2_STAGE);

#pragma unroll
        for (int ks = 0; ks < 2; ks++) {
            const u32 ko = ks << 5;
            u32 ah[2][4], al[2][4];
#pragma unroll
            for (int i = 0; i < 2; i++) {
                u32 aoff = stg + aLane + (u32)(i * 16 * ROWB) + ko;
                ldsm4(ah[i][0], ah[i][1], ah[i][2], ah[i][3], aoff);
                ldsm4(al[i][0], al[i][1], al[i][2], al[i][3], aoff + ARR_BYTES);
            }
#pragma unroll
            for (int half = 0; half < 2; half++) {
                u32 bh[4][2];
#pragma unroll
                for (int p = 0; p < 2; p++) {
                    u32 boff = stg + 2*ARR_BYTES + bLane
                             + (u32)((half * 2 + p) * 16 * ROWB) + ko;
                    ldsm4(bh[2*p][0], bh[2*p][1], bh[2*p+1][0], bh[2*p+1][1], boff);
                }
#pragma unroll
                for (int i = 0; i < 2; i++)
#pragma unroll
                    for (int j = 0; j < 4; j++)
                        mma16816(acc[i][half*4 + j],
                                 ah[i][0], ah[i][1], ah[i][2], ah[i][3],
                                 bh[j][0], bh[j][1]);
#pragma unroll
                for (int i = 0; i < 2; i++)
#pragma unroll
                    for (int j = 0; j < 4; j++)
                        mma16816(acc[i][half*4 + j],
                                 al[i][0], al[i][1], al[i][2], al[i][3],
                                 bh[j][0], bh[j][1]);
            }
        }
        __syncthreads();

        if (it + 2 < NIT)
            issue_stage_2t(smem + (it & 1) * T2_STAGE, Agh, Agl, Bgh,
                           row0, col0, K, kbeg + ((it + 2) << 5), tid);
        asm volatile("cp.async.commit_group;\n" ::: "memory");
    }

    float* Cb = Cf + (size_t)bzAll * sC;
#pragma unroll
    for (int i = 0; i < 2; i++) {
        int r1 = row0 + wm0 + 16 * i + g;
        int r2 = r1 + 8;
#pragma unroll
        for (int j = 0; j < 8; j++) {
            int n = col0 + wn0 + 8 * j + 2 * tg;
            *reinterpret_cast<float2*>(Cb + (size_t)r1 * N + n) =
                make_float2(acc[i][j][0] * alpha, acc[i][j][1] * alpha);
            *reinterpret_cast<float2*>(Cb + (size_t)r2 * N + n) =
                make_float2(acc[i][j][2] * alpha, acc[i][j][3] * alpha);
        }
    }
}

// ---------------------------------------------------------------------------
// Reduce SPLITK partials
// ---------------------------------------------------------------------------
__global__ __launch_bounds__(256)
void reduce_splitk(const float* __restrict__ part, float* __restrict__ out)
{
    const size_t SD = (size_t)SEQ * DM;
    size_t idx = ((size_t)blockIdx.x * 256 + threadIdx.x) * 4;
    int b = (int)(idx / SD);
    size_t r = idx - (size_t)b * SD;
    const float* pb = part + (size_t)b * SPLITK * SD + r;
    float4 s0 = *reinterpret_cast<const float4*>(pb);
    float4 s1 = *reinterpret_cast<const float4*>(pb + SD);
    float4 s2 = *reinterpret_cast<const float4*>(pb + 2*SD);
    float4 s3 = *reinterpret_cast<const float4*>(pb + 3*SD);
    float4 o;
    o.x = (s0.x + s1.x) + (s2.x + s3.x);
    o.y = (s0.y + s1.y) + (s2.y + s3.y);
    o.z = (s0.z + s1.z) + (s2.z + s3.z);
    o.w = (s0.w + s1.w) + (s2.w + s3.w);
    *reinterpret_cast<float4*>(out + idx) = o;
}

// ---------------------------------------------------------------------------
// ONLINE row softmax -> split fp16 attention row
// ---------------------------------------------------------------------------
__global__ __launch_bounds__(256)
void softmax_split(const float* __restrict__ scores,
                   u16* __restrict__ ah, u16* __restrict__ al)
{
    const size_t roff = (size_t)blockIdx.x * SEQ;
    const float* p = scores + roff;
    const int tid  = threadIdx.x;
    const int lane = tid & 31;
    const int wrp  = tid >> 5;

    float v[16];
#pragma unroll
    for (int i = 0; i < 4; i++) {
        float4 f = *reinterpret_cast<const float4*>(p + i * 1024 + tid * 4);
        v[i*4+0] = f.x; v[i*4+1] = f.y; v[i*4+2] = f.z; v[i*4+3] = f.w;
    }

    float m = v[0];
#pragma unroll
    for (int i = 1; i < 16; i++) m = fmaxf(m, v[i]);
    const float mloc = m;

    float s = 0.0f;
#pragma unroll
    for (int i = 0; i < 16; i++) {
        v[i] = exp2f((v[i] - mloc) * L2E);
        s += v[i];
    }

#pragma unroll
    for (int o = 16; o > 0; o >>= 1) {
        float mo = __shfl_xor_sync(0xffffffffu, m, o);
        float so = __shfl_xor_sync(0xffffffffu, s, o);
        float mn = fmaxf(m, mo);
        s = s * exp2f((m - mn) * L2E) + so * exp2f((mo - mn) * L2E);
        m = mn;
    }

    __shared__ float redM[8], redS[8], fin[2];
    if (lane == 0) { redM[wrp] = m; redS[wrp] = s; }
    __syncthreads();
    if (tid < 32) {
        float mm = (tid < 8) ? redM[tid] : -INFINITY;
        float ss = (tid < 8) ? redS[tid] : 0.0f;
#pragma unroll
        for (int o = 4; o > 0; o >>= 1) {
            float mo = __shfl_xor_sync(0xffffffffu, mm, o);
            float so = __shfl_xor_sync(0xffffffffu, ss, o);
            float mn = fmaxf(mm, mo);
            ss = ss * exp2f((mm - mn) * L2E) + so * exp2f((mo - mn) * L2E);
            mm = mn;
        }
        if (tid == 0) { fin[0] = mm; fin[1] = 1.0f / ss; }
    }
    __syncthreads();

    const float scalef = exp2f((mloc - fin[0]) * L2E) * fin[1];

#pragma unroll
    for (int i = 0; i < 4; i++) {
        u16 h[4], l[4];
#pragma unroll
        for (int j = 0; j < 4; j++)
            split_f16(v[i*4+j] * scalef, h[j], l[j]);
        *reinterpret_cast<uint2*>(ah + roff + i * 1024 + tid * 4) =
            make_uint2(pack2(h[0], h[1]), pack2(h[2], h[3]));
        *reinterpret_cast<uint2*>(al + roff + i * 1024 + tid * 4) =
            make_uint2(pack2(l[0], l[1]), pack2(l[2], l[3]));
    }
}

// ---------------------------------------------------------------------------
extern "C" void kernel_launch(void* const* d_in, const int* in_sizes, int n_in,
                              void* d_out, int out_size)
{
    const float* Q   = (const float*)d_in[0];
    const float* K   = (const float*)d_in[1];
    const float* V   = (const float*)d_in[2];
    const float* W_q = (const float*)d_in[3];
    const float* b_q = (const float*)d_in[4];
    const float* W_k = (const float*)d_in[5];
    const float* b_k = (const float*)d_in[6];
    const float* W_v = (const float*)d_in[7];
    const float* b_v = (const float*)d_in[8];
    float* out = (float*)d_out;

    u16 *Xq,*Xk,*Xv, *Wqh,*Wql,*Wkh,*Wkl,*Wvh,*Wvl;
    u16 *qh,*ql,*kh,*vth,*ah,*al;
    float *s, *part;
    cudaGetSymbolAddress((void**)&Xq, g_Xq);
    cudaGetSymbolAddress((void**)&Xk, g_Xk);
    cudaGetSymbolAddress((void**)&Xv, g_Xv);
    cudaGetSymbolAddress((void**)&Wqh, g_Wqh); cudaGetSymbolAddress((void**)&Wql, g_Wql);
    cudaGetSymbolAddress((void**)&Wkh, g_Wkh); cudaGetSymbolAddress((void**)&Wkl, g_Wkl);
    cudaGetSymbolAddress((void**)&Wvh, g_Wvh); cudaGetSymbolAddress((void**)&Wvl, g_Wvl);
    cudaGetSymbolAddress((void**)&qh, g_qh);   cudaGetSymbolAddress((void**)&ql, g_ql);
    cudaGetSymbolAddress((void**)&kh, g_kh);
    cudaGetSymbolAddress((void**)&vth, g_vth);
    cudaGetSymbolAddress((void**)&ah, g_ah);   cudaGetSymbolAddress((void**)&al, g_al);
    cudaGetSymbolAddress((void**)&s, g_s);     cudaGetSymbolAddress((void**)&part, g_part);

    cudaFuncSetAttribute(proj3,   cudaFuncAttributeMaxDynamicSharedMemorySize, DYNSMEM_T2);
    cudaFuncSetAttribute(gemm_2t, cudaFuncAttributeMaxDynamicSharedMemorySize, DYNSMEM_T2);

    const float scale = 1.0f / sqrtf((float)DM);
    dim3 blk(256);

    const int n1 = ROWS * DM;
    const int n2 = DM * DM;
    conv3_kernel<<<dim3(n1/1024, 3), blk>>>(Q, K, V, Xq, Xk, Xv, n1);
    split3_kernel<<<dim3(n2/1024, 3), blk>>>(W_q, W_k, W_v,
        Wqh, Wql, Wkh, Wkl, Wvh, Wvl, n2);

    // Fused 2-term projections (one launch, 768 CTAs):
    // q -> split (qh,ql); k -> single (kh); v -> single transposed (vth)
    {
        ProjArgs pa;
        pa.X[0]=Xq; pa.Bh[0]=Wqh; pa.Bl[0]=Wql; pa.bias[0]=b_q;
        pa.Ch[0]=qh; pa.Cl[0]=ql;
        pa.X[1]=Xk; pa.Bh[1]=Wkh; pa.Bl[1]=Wkl; pa.bias[1]=b_k;
        pa.Ch[1]=kh; pa.Cl[1]=kh;
        pa.X[2]=Xv; pa.Bh[2]=Wvh; pa.Bl[2]=Wvl; pa.bias[2]=b_v;
        pa.Ch[2]=vth; pa.Cl[2]=vth;
        dim3 gp(DM/128, ROWS/128, 3);
        proj3<<<gp, blk, DYNSMEM_T2>>>(pa);
    }

    // Scores (2-term, NT, per batch): s = scale * (qh+ql) @ kh^T
    {
        dim3 gs(SEQ/128, SEQ/128, BATCH);
        gemm_2t<<<gs, blk, DYNSMEM_T2>>>(qh, ql, kh,
            s, SEQ, SEQ, DM, 1,
            (long)SEQ*DM, (long)SEQ*DM, (long)SEQ*SEQ, scale);
    }

    // Online softmax -> split fp16 attention
    softmax_split<<<ROWS, blk>>>(s, ah, al);

    // Output: 2-term attn @ v via vT, split-K=4 partials then reduce
    {
        dim3 go(DM/128, SEQ/128, BATCH * SPLITK);
        gemm_2t<<<go, blk, DYNSMEM_T2>>>(ah, al, vth,
            part, SEQ, DM, SEQ, SPLITK,
            (long)SEQ*SEQ, (long)DM*SEQ, (long)SEQ*DM, 1.0f);
        reduce_splitk<<<(ROWS*DM)/1024, blk>>>(part, out);
    }
}

// round 16
// speedup vs baseline: 2.1237x; 1.3971x over previous
#include <cuda_runtime.h>
#include <cuda_fp16.h>
#include <math.h>

#define BATCH 2
#define SEQ   4096
#define DM    512
#define ROWS  (BATCH*SEQ)   // 8192
#define SPLITK 4
#define L2E   1.4426950408889634f

typedef unsigned short u16;
typedef unsigned int   u32;

// ---------------------------------------------------------------------------
// Device scratch (allocation-free rule: __device__ globals)
// ---------------------------------------------------------------------------
__device__ u16 g_Xq[(size_t)ROWS*DM], g_Xk[(size_t)ROWS*DM], g_Xv[(size_t)ROWS*DM];
__device__ u16 g_Wqh[DM*DM], g_Wql[DM*DM];
__device__ u16 g_Wkh[DM*DM], g_Wkl[DM*DM];
__device__ u16 g_Wvh[DM*DM], g_Wvl[DM*DM];
__device__ u16 g_qh[(size_t)ROWS*DM];                // q single fp16
__device__ u16 g_kh[(size_t)ROWS*DM];                // k single fp16
__device__ u16 g_vth[(size_t)BATCH*DM*SEQ];          // V^T single fp16
__device__ float g_s[(size_t)BATCH*SEQ*SEQ];
__device__ u16 g_ah[(size_t)BATCH*SEQ*SEQ];          // attn single fp16
__device__ float g_part[(size_t)BATCH*SPLITK*SEQ*DM];   // attnV split-K partials

// ---------------------------------------------------------------------------
// fp16 helpers
// ---------------------------------------------------------------------------
__device__ __forceinline__ u16 f2h(float x) {
    return __half_as_ushort(__float2half_rn(x));
}
__device__ __forceinline__ float h2f(u16 u) {
    return __half2float(__ushort_as_half(u));
}
__device__ __forceinline__ void split_f16(float x, u16& hi, u16& lo) {
    hi = f2h(x);
    lo = f2h(x - h2f(hi));
}
__device__ __forceinline__ unsigned pack2(u16 a, u16 b) {
    return (unsigned)a | ((unsigned)b << 16);
}

__device__ __forceinline__ void mma16816(float c[4],
                                         u32 a0, u32 a1, u32 a2, u32 a3,
                                         u32 b0, u32 b1)
{
    asm volatile(
        "mma.sync.aligned.m16n8k16.row.col.f32.f16.f16.f32 "
        "{%0,%1,%2,%3}, {%4,%5,%6,%7}, {%8,%9}, {%0,%1,%2,%3};\n"
        : "+f"(c[0]), "+f"(c[1]), "+f"(c[2]), "+f"(c[3])
        : "r"(a0), "r"(a1), "r"(a2), "r"(a3), "r"(b0), "r"(b1));
}

__device__ __forceinline__ void cp16(void* smem_dst, const void* gsrc) {
    u32 u = (u32)__cvta_generic_to_shared(smem_dst);
    asm volatile("cp.async.cg.shared.global [%0], [%1], 16;\n" :: "r"(u), "l"(gsrc));
}

__device__ __forceinline__ void ldsm4(u32& r0, u32& r1, u32& r2, u32& r3, u32 addr) {
    asm volatile("ldmatrix.sync.aligned.m8n8.x4.shared.b16 {%0,%1,%2,%3}, [%4];"
                 : "=r"(r0), "=r"(r1), "=r"(r2), "=r"(r3) : "r"(addr));
}

// ---------------------------------------------------------------------------
// Fused fp32 -> SINGLE fp16 for 3 equal-size arrays (inputs)
// ---------------------------------------------------------------------------
__global__ __launch_bounds__(256)
void conv3_kernel(const float* __restrict__ x0, const float* __restrict__ x1,
                  const float* __restrict__ x2,
                  u16* __restrict__ o0, u16* __restrict__ o1,
                  u16* __restrict__ o2, int n)
{
    const float* x;
    u16* op;
    if (blockIdx.y == 0)      { x = x0; op = o0; }
    else if (blockIdx.y == 1) { x = x1; op = o1; }
    else                      { x = x2; op = o2; }

    int i = (blockIdx.x * blockDim.x + threadIdx.x) * 4;
    if (i >= n) return;
    float4 f = *reinterpret_cast<const float4*>(x + i);
    *reinterpret_cast<uint2*>(op + i) =
        make_uint2(pack2(f2h(f.x), f2h(f.y)), pack2(f2h(f.z), f2h(f.w)));
}

// ---------------------------------------------------------------------------
// Fused fp32 -> split fp16 for 3 equal-size arrays (weights)
// ---------------------------------------------------------------------------
__global__ __launch_bounds__(256)
void split3_kernel(const float* __restrict__ x0, const float* __restrict__ x1,
                   const float* __restrict__ x2,
                   u16* __restrict__ h0a, u16* __restrict__ l0a,
                   u16* __restrict__ h1a, u16* __restrict__ l1a,
                   u16* __restrict__ h2a, u16* __restrict__ l2a, int n)
{
    const float* x;
    u16 *hp, *lp;
    if (blockIdx.y == 0)      { x = x0; hp = h0a; lp = l0a; }
    else if (blockIdx.y == 1) { x = x1; hp = h1a; lp = l1a; }
    else                      { x = x2; hp = h2a; lp = l2a; }

    int i = (blockIdx.x * blockDim.x + threadIdx.x) * 4;
    if (i >= n) return;
    float4 f = *reinterpret_cast<const float4*>(x + i);
    u16 h0,l0,h1,l1,h2,l2,h3,l3;
    split_f16(f.x, h0, l0);
    split_f16(f.y, h1, l1);
    split_f16(f.z, h2, l2);
    split_f16(f.w, h3, l3);
    *reinterpret_cast<uint2*>(hp + i) = make_uint2(pack2(h0,h1), pack2(h2,h3));
    *reinterpret_cast<uint2*>(lp + i) = make_uint2(pack2(l0,l1), pack2(l2,l3));
}

// ---------------------------------------------------------------------------
// Common tiling constants
// ---------------------------------------------------------------------------
#define SMP   40
#define ROWB  (SMP*2)              // 80 bytes
#define ARR_BYTES   (128*ROWB)     // 10240
#define T2_STAGE (3*ARR_BYTES)     // 30720 (2-term stage: 3 arrays)
#define DYNSMEM_T2 (2*T2_STAGE)    // 61440 -> 2 CTAs/SM
#define T1_STAGE (2*ARR_BYTES)     // 20480 (1-term stage: 2 arrays)
#define NST1     3
#define DYNSMEM_T1 (NST1*T1_STAGE) // 61440 -> 2 CTAs/SM

// ---------------------------------------------------------------------------
// Projections (2-term: X single x W split): grid (DM/128, ROWS/128, 3)
// Stage = [Xh][Wh][Wl]
// z in {0,1} -> single fp16 out (+bias); z==2 -> single fp16 transposed out
// ---------------------------------------------------------------------------
struct ProjArgs {
    const u16* X[3];
    const u16* Bh[3]; const u16* Bl[3];
    const float* bias[3];
    u16* Ch[3];
};

__device__ __forceinline__ void issue_stage_p(char* base,
    const u16* __restrict__ Xg,
    const u16* __restrict__ Bgh, const u16* __restrict__ Bgl,
    int row0, int col0, int Kstride, int k0, int tid)
{
#pragma unroll
    for (int e = 0; e < 2; e++) {
        int idx = tid + (e << 8);
        int r = idx >> 2;
        int c = (idx & 3) << 3;
        size_t offA = (size_t)(row0 + r) * Kstride + k0 + c;
        size_t offB = (size_t)(col0 + r) * Kstride + k0 + c;
        int sm = r * ROWB + c * 2;
        cp16(base + sm,               Xg + offA);
        cp16(base + ARR_BYTES + sm,   Bgh + offB);
        cp16(base + 2*ARR_BYTES + sm, Bgl + offB);
    }
}

__global__ __launch_bounds__(256, 2)
void proj3(ProjArgs pa)
{
    extern __shared__ char smem[];
    const int z = blockIdx.z;

    const int tid  = threadIdx.x;
    const int lane = tid & 31;
    const int wid  = tid >> 5;
    const int g    = lane >> 2;
    const int tg   = lane & 3;
    const int wm0  = (wid & 3) * 32;
    const int wn0  = (wid >> 2) * 64;
    const int row0 = blockIdx.y * 128;
    const int col0 = blockIdx.x * 128;

    const u16* Xg  = pa.X[z];
    const u16* Bgh = pa.Bh[z];
    const u16* Bgl = pa.Bl[z];

    const u32 aLane = (u32)((wm0 + (lane & 15)) * ROWB + ((lane >> 4) << 4));
    const u32 bLane = (u32)((wn0 + ((lane >> 4) << 3) + (lane & 7)) * ROWB
                            + ((lane & 8) << 1));
    const u32 smem_base = (u32)__cvta_generic_to_shared(smem);

    float acc[2][8][4];
#pragma unroll
    for (int i = 0; i < 2; i++)
#pragma unroll
        for (int j = 0; j < 8; j++)
#pragma unroll
            for (int t = 0; t < 4; t++) acc[i][j][t] = 0.0f;

    const int NIT = DM >> 5;

#pragma unroll
    for (int s = 0; s < 2; s++) {
        issue_stage_p(smem + s * T2_STAGE, Xg, Bgh, Bgl,
                      row0, col0, DM, s << 5, tid);
        asm volatile("cp.async.commit_group;\n" ::: "memory");
    }

    for (int it = 0; it < NIT; it++) {
        asm volatile("cp.async.wait_group 1;\n" ::: "memory");
        __syncthreads();

        const u32 stg = smem_base + (u32)((it & 1) * T2_STAGE);

#pragma unroll
        for (int ks = 0; ks < 2; ks++) {
            const u32 ko = ks << 5;
            u32 ah[2][4];
#pragma unroll
            for (int i = 0; i < 2; i++) {
                u32 aoff = stg + aLane + (u32)(i * 16 * ROWB) + ko;
                ldsm4(ah[i][0], ah[i][1], ah[i][2], ah[i][3], aoff);
            }
#pragma unroll
            for (int half = 0; half < 2; half++) {
                u32 bh[4][2], bl[4][2];
#pragma unroll
                for (int p = 0; p < 2; p++) {
                    u32 boff = stg + ARR_BYTES + bLane
                             + (u32)((half * 2 + p) * 16 * ROWB) + ko;
                    ldsm4(bh[2*p][0], bh[2*p][1], bh[2*p+1][0], bh[2*p+1][1], boff);
                    ldsm4(bl[2*p][0], bl[2*p][1], bl[2*p+1][0], bl[2*p+1][1],
                          boff + ARR_BYTES);
                }
#pragma unroll
                for (int i = 0; i < 2; i++)
#pragma unroll
                    for (int j = 0; j < 4; j++)
                        mma16816(acc[i][half*4 + j],
                                 ah[i][0], ah[i][1], ah[i][2], ah[i][3],
                                 bh[j][0], bh[j][1]);
#pragma unroll
                for (int i = 0; i < 2; i++)
#pragma unroll
                    for (int j = 0; j < 4; j++)
                        mma16816(acc[i][half*4 + j],
                                 ah[i][0], ah[i][1], ah[i][2], ah[i][3],
                                 bl[j][0], bl[j][1]);
            }
        }
        __syncthreads();

        if (it + 2 < NIT)
            issue_stage_p(smem + (it & 1) * T2_STAGE, Xg, Bgh, Bgl,
                          row0, col0, DM, (it + 2) << 5, tid);
        asm volatile("cp.async.commit_group;\n" ::: "memory");
    }

    const float* bias = pa.bias[z];
    u16* Ch = pa.Ch[z];
    const int N = DM;

#pragma unroll
    for (int i = 0; i < 2; i++) {
        int r1 = row0 + wm0 + 16 * i + g;
        int r2 = r1 + 8;
#pragma unroll
        for (int j = 0; j < 8; j++) {
            int n = col0 + wn0 + 8 * j + 2 * tg;
            float b0 = bias[n], b1 = bias[n + 1];
            float v00 = acc[i][j][0] + b0;
            float v01 = acc[i][j][1] + b1;
            float v10 = acc[i][j][2] + b0;
            float v11 = acc[i][j][3] + b1;

            if (z != 2) {
                *reinterpret_cast<u32*>(Ch + (size_t)r1 * N + n) =
                    pack2(f2h(v00), f2h(v01));
                *reinterpret_cast<u32*>(Ch + (size_t)r2 * N + n) =
                    pack2(f2h(v10), f2h(v11));
            } else {
                int   rr[2] = { r1, r2 };
                float vv[2][2] = { { v00, v01 }, { v10, v11 } };
#pragma unroll
                for (int t = 0; t < 2; t++) {
                    int m  = rr[t];
                    int b  = m >> 12;
                    int mm = m & (SEQ - 1);
#pragma unroll
                    for (int u = 0; u < 2; u++) {
                        size_t idx = ((size_t)(b * DM + n + u)) * SEQ + mm;
                        Ch[idx] = f2h(vv[t][u]);
                    }
                }
            }
        }
    }
}

// ---------------------------------------------------------------------------
// 1-term GEMM (A single fp16 x B single fp16), split-K, fp32 out with alpha.
// Used for BOTH scores (splitk=1, alpha=scale) and attnV (splitk=4, alpha=1).
// Stage = [A][B] (2 arrays, 20KB); 3-stage ring = 60KB -> 2 CTAs/SM
// ---------------------------------------------------------------------------
__device__ __forceinline__ void issue_stage_1t(char* base,
    const u16* __restrict__ Ag, const u16* __restrict__ Bg,
    int row0, int col0, int Kstride, int k0, int tid)
{
#pragma unroll
    for (int e = 0; e < 2; e++) {
        int idx = tid + (e << 8);
        int r = idx >> 2;
        int c = (idx & 3) << 3;
        size_t offA = (size_t)(row0 + r) * Kstride + k0 + c;
        size_t offB = (size_t)(col0 + r) * Kstride + k0 + c;
        int sm = r * ROWB + c * 2;
        cp16(base + sm,             Ag + offA);
        cp16(base + ARR_BYTES + sm, Bg + offB);
    }
}

__global__ __launch_bounds__(256, 2)
void gemm_1t(const u16* __restrict__ Ag, const u16* __restrict__ Bg,
             float* __restrict__ Cf,
             int M, int N, int K, int splitk,
             long sA, long sB, long sC, float alpha)
{
    extern __shared__ char smem[];

    const int bzAll = blockIdx.z;
    const int bat   = bzAll / splitk;
    const int ksp   = bzAll - bat * splitk;
    const int Kpart = K / splitk;
    const int kbeg  = ksp * Kpart;

    Ag += (size_t)bat * sA;
    Bg += (size_t)bat * sB;

    const int tid  = threadIdx.x;
    const int lane = tid & 31;
    const int wid  = tid >> 5;
    const int g    = lane >> 2;
    const int tg   = lane & 3;
    const int wm0  = (wid & 3) * 32;
    const int wn0  = (wid >> 2) * 64;
    const int row0 = blockIdx.y * 128;
    const int col0 = blockIdx.x * 128;

    const u32 aLane = (u32)((wm0 + (lane & 15)) * ROWB + ((lane >> 4) << 4));
    const u32 bLane = (u32)((wn0 + ((lane >> 4) << 3) + (lane & 7)) * ROWB
                            + ((lane & 8) << 1));
    const u32 smem_base = (u32)__cvta_generic_to_shared(smem);

    float acc[2][8][4];
#pragma unroll
    for (int i = 0; i < 2; i++)
#pragma unroll
        for (int j = 0; j < 8; j++)
#pragma unroll
            for (int t = 0; t < 4; t++) acc[i][j][t] = 0.0f;

    const int NIT = Kpart >> 5;

#pragma unroll
    for (int s = 0; s < NST1; s++) {
        if (s < NIT)
            issue_stage_1t(smem + s * T1_STAGE, Ag, Bg,
                           row0, col0, K, kbeg + (s << 5), tid);
        asm volatile("cp.async.commit_group;\n" ::: "memory");
    }

    for (int it = 0; it < NIT; it++) {
        asm volatile("cp.async.wait_group %0;\n" :: "n"(NST1 - 1) : "memory");
        __syncthreads();

        const u32 stg = smem_base + (u32)((it % NST1) * T1_STAGE);

#pragma unroll
        for (int ks = 0; ks < 2; ks++) {
            const u32 ko = ks << 5;
            u32 ah[2][4];
#pragma unroll
            for (int i = 0; i < 2; i++) {
                u32 aoff = stg + aLane + (u32)(i * 16 * ROWB) + ko;
                ldsm4(ah[i][0], ah[i][1], ah[i][2], ah[i][3], aoff);
            }
#pragma unroll
            for (int half = 0; half < 2; half++) {
                u32 bh[4][2];
#pragma unroll
                for (int p = 0; p < 2; p++) {
                    u32 boff = stg + ARR_BYTES + bLane
                             + (u32)((half * 2 + p) * 16 * ROWB) + ko;
                    ldsm4(bh[2*p][0], bh[2*p][1], bh[2*p+1][0], bh[2*p+1][1], boff);
                }
#pragma unroll
                for (int i = 0; i < 2; i++)
#pragma unroll
                    for (int j = 0; j < 4; j++)
                        mma16816(acc[i][half*4 + j],
                                 ah[i][0], ah[i][1], ah[i][2], ah[i][3],
                                 bh[j][0], bh[j][1]);
            }
        }
        __syncthreads();

        if (it + NST1 < NIT)
            issue_stage_1t(smem + (it % NST1) * T1_STAGE, Ag, Bg,
                           row0, col0, K, kbeg + ((it + NST1) << 5), tid);
        asm volatile("cp.async.commit_group;\n" ::: "memory");
    }

    float* Cb = Cf + (size_t)bzAll * sC;
#pragma unroll
    for (int i = 0; i < 2; i++) {
        int r1 = row0 + wm0 + 16 * i + g;
        int r2 = r1 + 8;
#pragma unroll
        for (int j = 0; j < 8; j++) {
            int n = col0 + wn0 + 8 * j + 2 * tg;
            *reinterpret_cast<float2*>(Cb + (size_t)r1 * N + n) =
                make_float2(acc[i][j][0] * alpha, acc[i][j][1] * alpha);
            *reinterpret_cast<float2*>(Cb + (size_t)r2 * N + n) =
                make_float2(acc[i][j][2] * alpha, acc[i][j][3] * alpha);
        }
    }
}

// ---------------------------------------------------------------------------
// Reduce SPLITK partials
// ---------------------------------------------------------------------------
__global__ __launch_bounds__(256)
void reduce_splitk(const float* __restrict__ part, float* __restrict__ out)
{
    const size_t SD = (size_t)SEQ * DM;
    size_t idx = ((size_t)blockIdx.x * 256 + threadIdx.x) * 4;
    int b = (int)(idx / SD);
    size_t r = idx - (size_t)b * SD;
    const float* pb = part + (size_t)b * SPLITK * SD + r;
    float4 s0 = *reinterpret_cast<const float4*>(pb);
    float4 s1 = *reinterpret_cast<const float4*>(pb + SD);
    float4 s2 = *reinterpret_cast<const float4*>(pb + 2*SD);
    float4 s3 = *reinterpret_cast<const float4*>(pb + 3*SD);
    float4 o;
    o.x = (s0.x + s1.x) + (s2.x + s3.x);
    o.y = (s0.y + s1.y) + (s2.y + s3.y);
    o.z = (s0.z + s1.z) + (s2.z + s3.z);
    o.w = (s0.w + s1.w) + (s2.w + s3.w);
    *reinterpret_cast<float4*>(out + idx) = o;
}

// ---------------------------------------------------------------------------
// ONLINE row softmax -> SINGLE fp16 attention row
// ---------------------------------------------------------------------------
__global__ __launch_bounds__(256)
void softmax_1h(const float* __restrict__ scores, u16* __restrict__ ah)
{
    const size_t roff = (size_t)blockIdx.x * SEQ;
    const float* p = scores + roff;
    const int tid  = threadIdx.x;
    const int lane = tid & 31;
    const int wrp  = tid >> 5;

    float v[16];
#pragma unroll
    for (int i = 0; i < 4; i++) {
        float4 f = *reinterpret_cast<const float4*>(p + i * 1024 + tid * 4);
        v[i*4+0] = f.x; v[i*4+1] = f.y; v[i*4+2] = f.z; v[i*4+3] = f.w;
    }

    float m = v[0];
#pragma unroll
    for (int i = 1; i < 16; i++) m = fmaxf(m, v[i]);
    const float mloc = m;

    float s = 0.0f;
#pragma unroll
    for (int i = 0; i < 16; i++) {
        v[i] = exp2f((v[i] - mloc) * L2E);
        s += v[i];
    }

#pragma unroll
    for (int o = 16; o > 0; o >>= 1) {
        float mo = __shfl_xor_sync(0xffffffffu, m, o);
        float so = __shfl_xor_sync(0xffffffffu, s, o);
        float mn = fmaxf(m, mo);
        s = s * exp2f((m - mn) * L2E) + so * exp2f((mo - mn) * L2E);
        m = mn;
    }

    __shared__ float redM[8], redS[8], fin[2];
    if (lane == 0) { redM[wrp] = m; redS[wrp] = s; }
    __syncthreads();
    if (tid < 32) {
        float mm = (tid < 8) ? redM[tid] : -INFINITY;
        float ss = (tid < 8) ? redS[tid] : 0.0f;
#pragma unroll
        for (int o = 4; o > 0; o >>= 1) {
            float mo = __shfl_xor_sync(0xffffffffu, mm, o);
            float so = __shfl_xor_sync(0xffffffffu, ss, o);
            float mn = fmaxf(mm, mo);
            ss = ss * exp2f((mm - mn) * L2E) + so * exp2f((mo - mn) * L2E);
            mm = mn;
        }
        if (tid == 0) { fin[0] = mm; fin[1] = 1.0f / ss; }
    }
    __syncthreads();

    const float scalef = exp2f((mloc - fin[0]) * L2E) * fin[1];

#pragma unroll
    for (int i = 0; i < 4; i++) {
        u16 h0 = f2h(v[i*4+0] * scalef);
        u16 h1 = f2h(v[i*4+1] * scalef);
        u16 h2 = f2h(v[i*4+2] * scalef);
        u16 h3 = f2h(v[i*4+3] * scalef);
        *reinterpret_cast<uint2*>(ah + roff + i * 1024 + tid * 4) =
            make_uint2(pack2(h0, h1), pack2(h2, h3));
    }
}

// ---------------------------------------------------------------------------
extern "C" void kernel_launch(void* const* d_in, const int* in_sizes, int n_in,
                              void* d_out, int out_size)
{
    const float* Q   = (const float*)d_in[0];
    const float* K   = (const float*)d_in[1];
    const float* V   = (const float*)d_in[2];
    const float* W_q = (const float*)d_in[3];
    const float* b_q = (const float*)d_in[4];
    const float* W_k = (const float*)d_in[5];
    const float* b_k = (const float*)d_in[6];
    const float* W_v = (const float*)d_in[7];
    const float* b_v = (const float*)d_in[8];
    float* out = (float*)d_out;

    u16 *Xq,*Xk,*Xv, *Wqh,*Wql,*Wkh,*Wkl,*Wvh,*Wvl;
    u16 *qh,*kh,*vth,*ah;
    float *s, *part;
    cudaGetSymbolAddress((void**)&Xq, g_Xq);
    cudaGetSymbolAddress((void**)&Xk, g_Xk);
    cudaGetSymbolAddress((void**)&Xv, g_Xv);
    cudaGetSymbolAddress((void**)&Wqh, g_Wqh); cudaGetSymbolAddress((void**)&Wql, g_Wql);
    cudaGetSymbolAddress((void**)&Wkh, g_Wkh); cudaGetSymbolAddress((void**)&Wkl, g_Wkl);
    cudaGetSymbolAddress((void**)&Wvh, g_Wvh); cudaGetSymbolAddress((void**)&Wvl, g_Wvl);
    cudaGetSymbolAddress((void**)&qh, g_qh);
    cudaGetSymbolAddress((void**)&kh, g_kh);
    cudaGetSymbolAddress((void**)&vth, g_vth);
    cudaGetSymbolAddress((void**)&ah, g_ah);
    cudaGetSymbolAddress((void**)&s, g_s);     cudaGetSymbolAddress((void**)&part, g_part);

    cudaFuncSetAttribute(proj3,   cudaFuncAttributeMaxDynamicSharedMemorySize, DYNSMEM_T2);
    cudaFuncSetAttribute(gemm_1t, cudaFuncAttributeMaxDynamicSharedMemorySize, DYNSMEM_T1);

    const float scale = 1.0f / sqrtf((float)DM);
    dim3 blk(256);

    const int n1 = ROWS * DM;
    const int n2 = DM * DM;
    conv3_kernel<<<dim3(n1/1024, 3), blk>>>(Q, K, V, Xq, Xk, Xv, n1);
    split3_kernel<<<dim3(n2/1024, 3), blk>>>(W_q, W_k, W_v,
        Wqh, Wql, Wkh, Wkl, Wvh, Wvl, n2);

    // Fused 2-term projections (one launch, 768 CTAs): all outputs single fp16
    {
        ProjArgs pa;
        pa.X[0]=Xq; pa.Bh[0]=Wqh; pa.Bl[0]=Wql; pa.bias[0]=b_q; pa.Ch[0]=qh;
        pa.X[1]=Xk; pa.Bh[1]=Wkh; pa.Bl[1]=Wkl; pa.bias[1]=b_k; pa.Ch[1]=kh;
        pa.X[2]=Xv; pa.Bh[2]=Wvh; pa.Bl[2]=Wvl; pa.bias[2]=b_v; pa.Ch[2]=vth;
        dim3 gp(DM/128, ROWS/128, 3);
        proj3<<<gp, blk, DYNSMEM_T2>>>(pa);
    }

    // Scores (1-term, NT, per batch): s = scale * qh @ kh^T
    {
        dim3 gs(SEQ/128, SEQ/128, BATCH);
        gemm_1t<<<gs, blk, DYNSMEM_T1>>>(qh, kh,
            s, SEQ, SEQ, DM, 1,
            (long)SEQ*DM, (long)SEQ*DM, (long)SEQ*SEQ, scale);
    }

    // Online softmax -> single fp16 attention
    softmax_1h<<<ROWS, blk>>>(s, ah);

    // Output: 1-term attn @ v via vT, split-K=4 partials then reduce
    {
        dim3 go(DM/128, SEQ/128, BATCH * SPLITK);
        gemm_1t<<<go, blk, DYNSMEM_T1>>>(ah, vth,
            part, SEQ, DM, SEQ, SPLITK,
            (long)SEQ*SEQ, (long)DM*SEQ, (long)SEQ*DM, 1.0f);
        reduce_splitk<<<(ROWS*DM)/1024, blk>>>(part, out);
    }
}

// round 17
// speedup vs baseline: 2.3137x; 1.0895x over previous
#include <cuda_runtime.h>
#include <cuda_fp16.h>
#include <math.h>

#define BATCH 2
#define SEQ   4096
#define DM    512
#define ROWS  (BATCH*SEQ)   // 8192
#define SPLITK 4
#define L2E   1.4426950408889634f

typedef unsigned short u16;
typedef unsigned int   u32;

// ---------------------------------------------------------------------------
// Device scratch (allocation-free rule: __device__ globals)
// ---------------------------------------------------------------------------
__device__ u16 g_Xq[(size_t)ROWS*DM], g_Xk[(size_t)ROWS*DM], g_Xv[(size_t)ROWS*DM];
__device__ u16 g_Wq[DM*DM], g_Wk[DM*DM], g_Wv[DM*DM];
__device__ u16 g_qh[(size_t)ROWS*DM];                // q single fp16
__device__ u16 g_kh[(size_t)ROWS*DM];                // k single fp16
__device__ u16 g_vth[(size_t)BATCH*DM*SEQ];          // V^T single fp16
__device__ float g_s[(size_t)BATCH*SEQ*SEQ];
__device__ u16 g_ah[(size_t)BATCH*SEQ*SEQ];          // attn single fp16
__device__ float g_part[(size_t)BATCH*SPLITK*SEQ*DM];   // attnV split-K partials

// ---------------------------------------------------------------------------
// fp16 helpers
// ---------------------------------------------------------------------------
__device__ __forceinline__ u16 f2h(float x) {
    return __half_as_ushort(__float2half_rn(x));
}
__device__ __forceinline__ unsigned pack2(u16 a, u16 b) {
    return (unsigned)a | ((unsigned)b << 16);
}

__device__ __forceinline__ void mma16816(float c[4],
                                         u32 a0, u32 a1, u32 a2, u32 a3,
                                         u32 b0, u32 b1)
{
    asm volatile(
        "mma.sync.aligned.m16n8k16.row.col.f32.f16.f16.f32 "
        "{%0,%1,%2,%3}, {%4,%5,%6,%7}, {%8,%9}, {%0,%1,%2,%3};\n"
        : "+f"(c[0]), "+f"(c[1]), "+f"(c[2]), "+f"(c[3])
        : "r"(a0), "r"(a1), "r"(a2), "r"(a3), "r"(b0), "r"(b1));
}

__device__ __forceinline__ void cp16(void* smem_dst, const void* gsrc) {
    u32 u = (u32)__cvta_generic_to_shared(smem_dst);
    asm volatile("cp.async.cg.shared.global [%0], [%1], 16;\n" :: "r"(u), "l"(gsrc));
}

__device__ __forceinline__ void ldsm4(u32& r0, u32& r1, u32& r2, u32& r3, u32 addr) {
    asm volatile("ldmatrix.sync.aligned.m8n8.x4.shared.b16 {%0,%1,%2,%3}, [%4];"
                 : "=r"(r0), "=r"(r1), "=r"(r2), "=r"(r3) : "r"(addr));
}

// ---------------------------------------------------------------------------
// Fused fp32 -> SINGLE fp16 for 3 equal-size arrays
// ---------------------------------------------------------------------------
__global__ __launch_bounds__(256)
void conv3_kernel(const float* __restrict__ x0, const float* __restrict__ x1,
                  const float* __restrict__ x2,
                  u16* __restrict__ o0, u16* __restrict__ o1,
                  u16* __restrict__ o2, int n)
{
    const float* x;
    u16* op;
    if (blockIdx.y == 0)      { x = x0; op = o0; }
    else if (blockIdx.y == 1) { x = x1; op = o1; }
    else                      { x = x2; op = o2; }

    int i = (blockIdx.x * blockDim.x + threadIdx.x) * 4;
    if (i >= n) return;
    float4 f = *reinterpret_cast<const float4*>(x + i);
    *reinterpret_cast<uint2*>(op + i) =
        make_uint2(pack2(f2h(f.x), f2h(f.y)), pack2(f2h(f.z), f2h(f.w)));
}

// ---------------------------------------------------------------------------
// Common tiling constants
// ---------------------------------------------------------------------------
#define SMP   40
#define ROWB  (SMP*2)              // 80 bytes
#define ARR_BYTES   (128*ROWB)     // 10240
#define T1_STAGE (2*ARR_BYTES)     // 20480 (1-term stage: 2 arrays)
#define NST1     3
#define DYNSMEM_T1 (NST1*T1_STAGE) // 61440 -> 2 CTAs/SM

// ---------------------------------------------------------------------------
// Shared 1-term mainloop core (A single fp16 x B single fp16, NT)
// Block 128x128x32, 256 thr = 8 warps (4M x 2N), warp tile 32x64.
// 3-stage cp.async ring. Leaves results in acc[2][8][4].
// ---------------------------------------------------------------------------
__device__ __forceinline__ void issue_stage_1t(char* base,
    const u16* __restrict__ Ag, const u16* __restrict__ Bg,
    int row0, int col0, int Kstride, int k0, int tid)
{
#pragma unroll
    for (int e = 0; e < 2; e++) {
        int idx = tid + (e << 8);
        int r = idx >> 2;
        int c = (idx & 3) << 3;
        size_t offA = (size_t)(row0 + r) * Kstride + k0 + c;
        size_t offB = (size_t)(col0 + r) * Kstride + k0 + c;
        int sm = r * ROWB + c * 2;
        cp16(base + sm,             Ag + offA);
        cp16(base + ARR_BYTES + sm, Bg + offB);
    }
}

__device__ __forceinline__ void gemm1t_main(char* smem, float acc[2][8][4],
    const u16* __restrict__ Ag, const u16* __restrict__ Bg,
    int row0, int col0, int Kstride, int kbeg, int Kpart, int tid)
{
    const int lane = tid & 31;
    const int wid  = tid >> 5;
    const int wm0  = (wid & 3) * 32;
    const int wn0  = (wid >> 2) * 64;

    const u32 aLane = (u32)((wm0 + (lane & 15)) * ROWB + ((lane >> 4) << 4));
    const u32 bLane = (u32)((wn0 + ((lane >> 4) << 3) + (lane & 7)) * ROWB
                            + ((lane & 8) << 1));
    const u32 smem_base = (u32)__cvta_generic_to_shared(smem);

#pragma unroll
    for (int i = 0; i < 2; i++)
#pragma unroll
        for (int j = 0; j < 8; j++)
#pragma unroll
            for (int t = 0; t < 4; t++) acc[i][j][t] = 0.0f;

    const int NIT = Kpart >> 5;

#pragma unroll
    for (int s = 0; s < NST1; s++) {
        if (s < NIT)
            issue_stage_1t(smem + s * T1_STAGE, Ag, Bg,
                           row0, col0, Kstride, kbeg + (s << 5), tid);
        asm volatile("cp.async.commit_group;\n" ::: "memory");
    }

    for (int it = 0; it < NIT; it++) {
        asm volatile("cp.async.wait_group %0;\n" :: "n"(NST1 - 1) : "memory");
        __syncthreads();

        const u32 stg = smem_base + (u32)((it % NST1) * T1_STAGE);

#pragma unroll
        for (int ks = 0; ks < 2; ks++) {
            const u32 ko = ks << 5;
            u32 ah[2][4];
#pragma unroll
            for (int i = 0; i < 2; i++) {
                u32 aoff = stg + aLane + (u32)(i * 16 * ROWB) + ko;
                ldsm4(ah[i][0], ah[i][1], ah[i][2], ah[i][3], aoff);
            }
#pragma unroll
            for (int half = 0; half < 2; half++) {
                u32 bh[4][2];
#pragma unroll
                for (int p = 0; p < 2; p++) {
                    u32 boff = stg + ARR_BYTES + bLane
                             + (u32)((half * 2 + p) * 16 * ROWB) + ko;
                    ldsm4(bh[2*p][0], bh[2*p][1], bh[2*p+1][0], bh[2*p+1][1], boff);
                }
#pragma unroll
                for (int i = 0; i < 2; i++)
#pragma unroll
                    for (int j = 0; j < 4; j++)
                        mma16816(acc[i][half*4 + j],
                                 ah[i][0], ah[i][1], ah[i][2], ah[i][3],
                                 bh[j][0], bh[j][1]);
            }
        }
        __syncthreads();

        if (it + NST1 < NIT)
            issue_stage_1t(smem + (it % NST1) * T1_STAGE, Ag, Bg,
                           row0, col0, Kstride, kbeg + ((it + NST1) << 5), tid);
        asm volatile("cp.async.commit_group;\n" ::: "memory");
    }
}

// ---------------------------------------------------------------------------
// Fused 1-term Q/K/V projections: grid (DM/128, ROWS/128, 3)
// z in {0,1} -> single fp16 out (+bias); z==2 -> single fp16 transposed out
// ---------------------------------------------------------------------------
struct ProjArgs {
    const u16* X[3];
    const u16* W[3];
    const float* bias[3];
    u16* Ch[3];
};

__global__ __launch_bounds__(256, 2)
void proj3(ProjArgs pa)
{
    extern __shared__ char smem[];
    const int z = blockIdx.z;

    const int tid  = threadIdx.x;
    const int lane = tid & 31;
    const int wid  = tid >> 5;
    const int g    = lane >> 2;
    const int tg   = lane & 3;
    const int wm0  = (wid & 3) * 32;
    const int wn0  = (wid >> 2) * 64;
    const int row0 = blockIdx.y * 128;
    const int col0 = blockIdx.x * 128;

    float acc[2][8][4];
    gemm1t_main(smem, acc, pa.X[z], pa.W[z], row0, col0, DM, 0, DM, tid);

    const float* bias = pa.bias[z];
    u16* Ch = pa.Ch[z];
    const int N = DM;

#pragma unroll
    for (int i = 0; i < 2; i++) {
        int r1 = row0 + wm0 + 16 * i + g;
        int r2 = r1 + 8;
#pragma unroll
        for (int j = 0; j < 8; j++) {
            int n = col0 + wn0 + 8 * j + 2 * tg;
            float b0 = bias[n], b1 = bias[n + 1];
            float v00 = acc[i][j][0] + b0;
            float v01 = acc[i][j][1] + b1;
            float v10 = acc[i][j][2] + b0;
            float v11 = acc[i][j][3] + b1;

            if (z != 2) {
                *reinterpret_cast<u32*>(Ch + (size_t)r1 * N + n) =
                    pack2(f2h(v00), f2h(v01));
                *reinterpret_cast<u32*>(Ch + (size_t)r2 * N + n) =
                    pack2(f2h(v10), f2h(v11));
            } else {
                int   rr[2] = { r1, r2 };
                float vv[2][2] = { { v00, v01 }, { v10, v11 } };
#pragma unroll
                for (int t = 0; t < 2; t++) {
                    int m  = rr[t];
                    int b  = m >> 12;
                    int mm = m & (SEQ - 1);
#pragma unroll
                    for (int u = 0; u < 2; u++) {
                        size_t idx = ((size_t)(b * DM + n + u)) * SEQ + mm;
                        Ch[idx] = f2h(vv[t][u]);
                    }
                }
            }
        }
    }
}

// ---------------------------------------------------------------------------
// 1-term GEMM, split-K, fp32 out with alpha (scores: splitk=1; attnV: splitk=4)
// ---------------------------------------------------------------------------
__global__ __launch_bounds__(256, 2)
void gemm_1t(const u16* __restrict__ Ag, const u16* __restrict__ Bg,
             float* __restrict__ Cf,
             int M, int N, int K, int splitk,
             long sA, long sB, long sC, float alpha)
{
    extern __shared__ char smem[];

    const int bzAll = blockIdx.z;
    const int bat   = bzAll / splitk;
    const int ksp   = bzAll - bat * splitk;
    const int Kpart = K / splitk;

    Ag += (size_t)bat * sA;
    Bg += (size_t)bat * sB;

    const int tid  = threadIdx.x;
    const int lane = tid & 31;
    const int wid  = tid >> 5;
    const int g    = lane >> 2;
    const int tg   = lane & 3;
    const int wm0  = (wid & 3) * 32;
    const int wn0  = (wid >> 2) * 64;
    const int row0 = blockIdx.y * 128;
    const int col0 = blockIdx.x * 128;

    float acc[2][8][4];
    gemm1t_main(smem, acc, Ag, Bg, row0, col0, K, ksp * Kpart, Kpart, tid);

    float* Cb = Cf + (size_t)bzAll * sC;
#pragma unroll
    for (int i = 0; i < 2; i++) {
        int r1 = row0 + wm0 + 16 * i + g;
        int r2 = r1 + 8;
#pragma unroll
        for (int j = 0; j < 8; j++) {
            int n = col0 + wn0 + 8 * j + 2 * tg;
            *reinterpret_cast<float2*>(Cb + (size_t)r1 * N + n) =
                make_float2(acc[i][j][0] * alpha, acc[i][j][1] * alpha);
            *reinterpret_cast<float2*>(Cb + (size_t)r2 * N + n) =
                make_float2(acc[i][j][2] * alpha, acc[i][j][3] * alpha);
        }
    }
}

// ---------------------------------------------------------------------------
// Reduce SPLITK partials
// ---------------------------------------------------------------------------
__global__ __launch_bounds__(256)
void reduce_splitk(const float* __restrict__ part, float* __restrict__ out)
{
    const size_t SD = (size_t)SEQ * DM;
    size_t idx = ((size_t)blockIdx.x * 256 + threadIdx.x) * 4;
    int b = (int)(idx / SD);
    size_t r = idx - (size_t)b * SD;
    const float* pb = part + (size_t)b * SPLITK * SD + r;
    float4 s0 = *reinterpret_cast<const float4*>(pb);
    float4 s1 = *reinterpret_cast<const float4*>(pb + SD);
    float4 s2 = *reinterpret_cast<const float4*>(pb + 2*SD);
    float4 s3 = *reinterpret_cast<const float4*>(pb + 3*SD);
    float4 o;
    o.x = (s0.x + s1.x) + (s2.x + s3.x);
    o.y = (s0.y + s1.y) + (s2.y + s3.y);
    o.z = (s0.z + s1.z) + (s2.z + s3.z);
    o.w = (s0.w + s1.w) + (s2.w + s3.w);
    *reinterpret_cast<float4*>(out + idx) = o;
}

// ---------------------------------------------------------------------------
// ONLINE row softmax -> SINGLE fp16 attention row
// ---------------------------------------------------------------------------
__global__ __launch_bounds__(256)
void softmax_1h(const float* __restrict__ scores, u16* __restrict__ ah)
{
    const size_t roff = (size_t)blockIdx.x * SEQ;
    const float* p = scores + roff;
    const int tid  = threadIdx.x;
    const int lane = tid & 31;
    const int wrp  = tid >> 5;

    float v[16];
#pragma unroll
    for (int i = 0; i < 4; i++) {
        float4 f = *reinterpret_cast<const float4*>(p + i * 1024 + tid * 4);
        v[i*4+0] = f.x; v[i*4+1] = f.y; v[i*4+2] = f.z; v[i*4+3] = f.w;
    }

    float m = v[0];
#pragma unroll
    for (int i = 1; i < 16; i++) m = fmaxf(m, v[i]);
    const float mloc = m;

    float s = 0.0f;
#pragma unroll
    for (int i = 0; i < 16; i++) {
        v[i] = exp2f((v[i] - mloc) * L2E);
        s += v[i];
    }

#pragma unroll
    for (int o = 16; o > 0; o >>= 1) {
        float mo = __shfl_xor_sync(0xffffffffu, m, o);
        float so = __shfl_xor_sync(0xffffffffu, s, o);
        float mn = fmaxf(m, mo);
        s = s * exp2f((m - mn) * L2E) + so * exp2f((mo - mn) * L2E);
        m = mn;
    }

    __shared__ float redM[8], redS[8], fin[2];
    if (lane == 0) { redM[wrp] = m; redS[wrp] = s; }
    __syncthreads();
    if (tid < 32) {
        float mm = (tid < 8) ? redM[tid] : -INFINITY;
        float ss = (tid < 8) ? redS[tid] : 0.0f;
#pragma unroll
        for (int o = 4; o > 0; o >>= 1) {
            float mo = __shfl_xor_sync(0xffffffffu, mm, o);
            float so = __shfl_xor_sync(0xffffffffu, ss, o);
            float mn = fmaxf(mm, mo);
            ss = ss * exp2f((mm - mn) * L2E) + so * exp2f((mo - mn) * L2E);
            mm = mn;
        }
        if (tid == 0) { fin[0] = mm; fin[1] = 1.0f / ss; }
    }
    __syncthreads();

    const float scalef = exp2f((mloc - fin[0]) * L2E) * fin[1];

#pragma unroll
    for (int i = 0; i < 4; i++) {
        u16 h0 = f2h(v[i*4+0] * scalef);
        u16 h1 = f2h(v[i*4+1] * scalef);
        u16 h2 = f2h(v[i*4+2] * scalef);
        u16 h3 = f2h(v[i*4+3] * scalef);
        *reinterpret_cast<uint2*>(ah + roff + i * 1024 + tid * 4) =
            make_uint2(pack2(h0, h1), pack2(h2, h3));
    }
}

// ---------------------------------------------------------------------------
extern "C" void kernel_launch(void* const* d_in, const int* in_sizes, int n_in,
                              void* d_out, int out_size)
{
    const float* Q   = (const float*)d_in[0];
    const float* K   = (const float*)d_in[1];
    const float* V   = (const float*)d_in[2];
    const float* W_q = (const float*)d_in[3];
    const float* b_q = (const float*)d_in[4];
    const float* W_k = (const float*)d_in[5];
    const float* b_k = (const float*)d_in[6];
    const float* W_v = (const float*)d_in[7];
    const float* b_v = (const float*)d_in[8];
    float* out = (float*)d_out;

    u16 *Xq,*Xk,*Xv, *Wq,*Wk,*Wv;
    u16 *qh,*kh,*vth,*ah;
    float *s, *part;
    cudaGetSymbolAddress((void**)&Xq, g_Xq);
    cudaGetSymbolAddress((void**)&Xk, g_Xk);
    cudaGetSymbolAddress((void**)&Xv, g_Xv);
    cudaGetSymbolAddress((void**)&Wq, g_Wq);
    cudaGetSymbolAddress((void**)&Wk, g_Wk);
    cudaGetSymbolAddress((void**)&Wv, g_Wv);
    cudaGetSymbolAddress((void**)&qh, g_qh);
    cudaGetSymbolAddress((void**)&kh, g_kh);
    cudaGetSymbolAddress((void**)&vth, g_vth);
    cudaGetSymbolAddress((void**)&ah, g_ah);
    cudaGetSymbolAddress((void**)&s, g_s);
    cudaGetSymbolAddress((void**)&part, g_part);

    cudaFuncSetAttribute(proj3,   cudaFuncAttributeMaxDynamicSharedMemorySize, DYNSMEM_T1);
    cudaFuncSetAttribute(gemm_1t, cudaFuncAttributeMaxDynamicSharedMemorySize, DYNSMEM_T1);

    const float scale = 1.0f / sqrtf((float)DM);
    dim3 blk(256);

    const int n1 = ROWS * DM;
    const int n2 = DM * DM;
    conv3_kernel<<<dim3(n1/1024, 3), blk>>>(Q, K, V, Xq, Xk, Xv, n1);
    conv3_kernel<<<dim3(n2/1024, 3), blk>>>(W_q, W_k, W_v, Wq, Wk, Wv, n2);

    // Fused 1-term projections (one launch, 768 CTAs): all outputs single fp16
    {
        ProjArgs pa;
        pa.X[0]=Xq; pa.W[0]=Wq; pa.bias[0]=b_q; pa.Ch[0]=qh;
        pa.X[1]=Xk; pa.W[1]=Wk; pa.bias[1]=b_k; pa.Ch[1]=kh;
        pa.X[2]=Xv; pa.W[2]=Wv; pa.bias[2]=b_v; pa.Ch[2]=vth;
        dim3 gp(DM/128, ROWS/128, 3);
        proj3<<<gp, blk, DYNSMEM_T1>>>(pa);
    }

    // Scores (1-term, NT, per batch): s = scale * qh @ kh^T
    {
        dim3 gs(SEQ/128, SEQ/128, BATCH);
        gemm_1t<<<gs, blk, DYNSMEM_T1>>>(qh, kh,
            s, SEQ, SEQ, DM, 1,
            (long)SEQ*DM, (long)SEQ*DM, (long)SEQ*SEQ, scale);
    }

    // Online softmax -> single fp16 attention
    softmax_1h<<<ROWS, blk>>>(s, ah);

    // Output: 1-term attn @ v via vT, split-K=4 partials then reduce
    {
        dim3 go(DM/128, SEQ/128, BATCH * SPLITK);
        gemm_1t<<<go, blk, DYNSMEM_T1>>>(ah, vth,
            part, SEQ, DM, SEQ, SPLITK,
            (long)SEQ*SEQ, (long)DM*SEQ, (long)SEQ*DM, 1.0f);
        reduce_splitk<<<(ROWS*DM)/1024, blk>>>(part, out);
    }
}